// round 4
// baseline (speedup 1.0000x reference)
#include <cuda_runtime.h>
#include <cuda_bf16.h>
#include <cstdint>

#define NB 8
#define SQ 2048
#define SK 2048
#define DH 512

#define KTILE 64
#define TILE_B (128 * KTILE * 2)   // 16384 bytes per bf16 operand tile
#define NBUF 3
#define SMEM_TILES 1024
#define SMEM_TOTAL (SMEM_TILES + NBUF * 4 * TILE_B)  // 197632 bytes

// tcgen05 is an arch-accelerated ('a') feature: only emit it in passes that
// target sm_103a/sm_100a (or arch/family-specific variants).
#if defined(__CUDA_ARCH_FEAT_SM103_ALL) || defined(__CUDA_ARCH_FEAT_SM100_ALL) || \
    defined(__CUDA_ARCH_FEAT_SM101_ALL) ||                                        \
    (defined(__CUDA_ARCH_SPECIFIC__) && (__CUDA_ARCH_SPECIFIC__ >= 1000)) ||      \
    (defined(__CUDA_ARCH_FAMILY_SPECIFIC__) && (__CUDA_ARCH_FAMILY_SPECIFIC__ >= 1000))
#define HAS_TCGEN05 1
#else
#define HAS_TCGEN05 0
#endif

// ------------------------- device scratch -------------------------
__device__ float g_ksq[NB * SK];
__device__ __align__(128) __nv_bfloat16 g_Vth[NB * DH * SK];
__device__ __align__(128) __nv_bfloat16 g_Vtl[NB * DH * SK];

// ------------------------- ptx helpers -------------------------
__device__ __forceinline__ uint32_t smem_u32(const void* p) {
    uint32_t a;
    asm("{ .reg .u64 t; cvta.to.shared.u64 t, %1; cvt.u32.u64 %0, t; }" : "=r"(a) : "l"(p));
    return a;
}
__device__ __forceinline__ uint32_t elect1() {
    uint32_t p;
    asm volatile("{\n\t.reg .pred p;\n\telect.sync _|p, 0xFFFFFFFF;\n\tselp.b32 %0,1,0,p;\n\t}" : "=r"(p));
    return p;
}
__device__ __forceinline__ void mbar_init(uint32_t addr, uint32_t cnt) {
    asm volatile("mbarrier.init.shared.b64 [%0], %1;" :: "r"(addr), "r"(cnt) : "memory");
}
__device__ __forceinline__ void mbar_wait(uint32_t mbar, uint32_t parity) {
    asm volatile(
        "{\n\t.reg .pred P;\n\t"
        "W_%=:\n\t"
        "mbarrier.try_wait.parity.acquire.cta.shared::cta.b64 P, [%0], %1, 0x989680;\n\t"
        "@P bra.uni D_%=;\n\t"
        "bra.uni W_%=;\n\t"
        "D_%=:\n\t}"
        :: "r"(mbar), "r"(parity) : "memory");
}
__device__ __forceinline__ void fence_async_shared() {
    asm volatile("fence.proxy.async.shared::cta;" ::: "memory");
}

#if HAS_TCGEN05
__device__ __forceinline__ void tmem_alloc(uint32_t smem_addr, uint32_t ncols) {
    asm volatile("tcgen05.alloc.cta_group::1.sync.aligned.shared::cta.b32 [%0], %1;"
                 :: "r"(smem_addr), "r"(ncols) : "memory");
}
__device__ __forceinline__ void tmem_dealloc(uint32_t tmem, uint32_t ncols) {
    asm volatile("tcgen05.dealloc.cta_group::1.sync.aligned.b32 %0, %1;" :: "r"(tmem), "r"(ncols));
}
__device__ __forceinline__ void tmem_relinquish() {
    asm volatile("tcgen05.relinquish_alloc_permit.cta_group::1.sync.aligned;");
}
__device__ __forceinline__ void mma_commit(uint32_t mbar) {
    asm volatile("tcgen05.commit.cta_group::1.mbarrier::arrive::one.shared::cluster.b64 [%0];"
                 :: "r"(mbar) : "memory");
}
__device__ __forceinline__ void tc_fence_after() {
    asm volatile("tcgen05.fence::after_thread_sync;" ::: "memory");
}
__device__ __forceinline__ void tc_wait_ld() {
    asm volatile("tcgen05.wait::ld.sync.aligned;" ::: "memory");
}
__device__ __forceinline__ uint64_t mk_desc(uint32_t addr) {
    // SW128, version=1 (Blackwell), SBO=64, LBO=1  (K-major, 128B rows)
    return (2ULL << 61) | (1ULL << 46) | (64ULL << 32) | (1ULL << 16) |
           ((uint64_t)(addr >> 4) & 0x3FFF);
}
__device__ __forceinline__ void mma_bf16_ss(uint32_t d, uint64_t da, uint64_t db,
                                            uint32_t idesc, uint32_t acc) {
    asm volatile(
        "{\n\t.reg .pred p;\n\t"
        "setp.ne.u32 p, %4, 0;\n\t"
        "tcgen05.mma.cta_group::1.kind::f16 [%0], %1, %2, %3, {%5, %5, %5, %5}, p;\n\t}"
        :: "r"(d), "l"(da), "l"(db), "r"(idesc), "r"(acc), "r"(0u) : "memory");
}
__device__ __forceinline__ void ldtm32(uint32_t* r, uint32_t a) {
    asm volatile(
        "tcgen05.ld.sync.aligned.32x32b.x32.b32 "
        "{%0,%1,%2,%3,%4,%5,%6,%7,%8,%9,%10,%11,%12,%13,%14,%15,"
        "%16,%17,%18,%19,%20,%21,%22,%23,%24,%25,%26,%27,%28,%29,%30,%31}, [%32];"
        : "=r"(r[0]), "=r"(r[1]), "=r"(r[2]), "=r"(r[3]), "=r"(r[4]), "=r"(r[5]), "=r"(r[6]), "=r"(r[7]),
          "=r"(r[8]), "=r"(r[9]), "=r"(r[10]), "=r"(r[11]), "=r"(r[12]), "=r"(r[13]), "=r"(r[14]), "=r"(r[15]),
          "=r"(r[16]), "=r"(r[17]), "=r"(r[18]), "=r"(r[19]), "=r"(r[20]), "=r"(r[21]), "=r"(r[22]), "=r"(r[23]),
          "=r"(r[24]), "=r"(r[25]), "=r"(r[26]), "=r"(r[27]), "=r"(r[28]), "=r"(r[29]), "=r"(r[30]), "=r"(r[31])
        : "r"(a));
}
#endif // HAS_TCGEN05

// idesc: F32 accum, BF16 a/b, M=128, N=128
#define GEMM_IDESC ((1u << 4) | (1u << 7) | (1u << 10) | (16u << 17) | (8u << 24))

// ---------------------------------------------------------------------------
// k_sq (fp32, full precision)
// ---------------------------------------------------------------------------
__global__ __launch_bounds__(256) void ksq_kernel(const float* __restrict__ K) {
    int gw = (blockIdx.x * blockDim.x + threadIdx.x) >> 5;
    int lane = threadIdx.x & 31;
    if (gw >= NB * SK) return;
    const float* row = K + (size_t)gw * DH;
    float s = 0.f;
    #pragma unroll
    for (int i = lane * 4; i < DH; i += 128) {
        float4 v = *(const float4*)(row + i);
        s = fmaf(v.x, v.x, s); s = fmaf(v.y, v.y, s);
        s = fmaf(v.z, v.z, s); s = fmaf(v.w, v.w, s);
    }
    #pragma unroll
    for (int o = 16; o > 0; o >>= 1) s += __shfl_xor_sync(0xffffffffu, s, o);
    if (lane == 0) g_ksq[gw] = s;
}

// ---------------------------------------------------------------------------
// V transpose + split:  Vt[b][d][k] = V[b][k][d]  (hi/lo bf16)
// ---------------------------------------------------------------------------
__global__ __launch_bounds__(256) void vsplit_kernel(const float* __restrict__ V) {
    __shared__ float t[32][33];
    const int b = blockIdx.z;
    const int d0 = blockIdx.x * 32, k0 = blockIdx.y * 32;
    const float* Vb = V + (size_t)b * SK * DH;
    const int tx = threadIdx.x, ty = threadIdx.y; // 32 x 8
    #pragma unroll
    for (int j = 0; j < 4; j++)
        t[ty + j * 8][tx] = Vb[(size_t)(k0 + ty + j * 8) * DH + d0 + tx];
    __syncthreads();
    #pragma unroll
    for (int j = 0; j < 4; j++) {
        float x = t[tx][ty + j * 8];
        __nv_bfloat16 h = __float2bfloat16(x);
        __nv_bfloat16 l = __float2bfloat16(x - __bfloat162float(h));
        size_t o = (size_t)b * DH * SK + (size_t)(d0 + ty + j * 8) * SK + k0 + tx;
        g_Vth[o] = h;
        g_Vtl[o] = l;
    }
}

// ---------------------------------------------------------------------------
// SMEM tile loaders (tcgen05 path)
// ---------------------------------------------------------------------------
__device__ __forceinline__ void load_convert_fp32(const float* __restrict__ src, int rbase,
                                                  int kdim, int k0, char* dst_hi, char* dst_lo,
                                                  int tid) {
    // 128 rows x 64 fp32 -> two 128x64 bf16 tiles (hi, lo), SW128 swizzled
    #pragma unroll
    for (int i = 0; i < 8; i++) {
        int idx = tid + i * 256;          // 0..2047
        int row = idx >> 4, c4 = idx & 15;
        float4 v = *(const float4*)(src + (size_t)(rbase + row) * kdim + k0 + c4 * 4);
        __nv_bfloat162 h01(__float2bfloat16(v.x), __float2bfloat16(v.y));
        __nv_bfloat162 h23(__float2bfloat16(v.z), __float2bfloat16(v.w));
        __nv_bfloat162 l01(__float2bfloat16(v.x - __bfloat162float(h01.x)),
                           __float2bfloat16(v.y - __bfloat162float(h01.y)));
        __nv_bfloat162 l23(__float2bfloat16(v.z - __bfloat162float(h23.x)),
                           __float2bfloat16(v.w - __bfloat162float(h23.y)));
        uint32_t off = row * 128 + c4 * 8;
        off ^= (off >> 3) & 0x70;
        *(uint2*)(dst_hi + off) = make_uint2(*(uint32_t*)&h01, *(uint32_t*)&h23);
        *(uint2*)(dst_lo + off) = make_uint2(*(uint32_t*)&l01, *(uint32_t*)&l23);
    }
}
__device__ __forceinline__ void load_bf16_tile(const __nv_bfloat16* __restrict__ src, int rbase,
                                               int kdim, int k0, char* dst, int tid) {
    #pragma unroll
    for (int i = 0; i < 4; i++) {
        int idx = tid + i * 256;          // 0..1023
        int row = idx >> 3, c8 = idx & 7;
        uint4 v = *(const uint4*)(src + (size_t)(rbase + row) * kdim + k0 + c8 * 8);
        uint32_t off = row * 128 + c8 * 16;
        off ^= (off >> 3) & 0x70;
        *(uint4*)(dst + off) = v;
    }
}

// ---------------------------------------------------------------------------
// GEMM:  D[m][n] = sum_k A[m][k]*B[n][k]   (fp32 accum, split-bf16 3-product)
//   A: fp32 [m][k], converted to hi/lo in the load stage.
//   B: fp32 [n][k] (QK) converted in-kernel, or pre-split bf16 pair (PV).
// ---------------------------------------------------------------------------
template <int KDIM, int LDOUT, int BROWS, bool B_BF16, bool IS_QK>
__global__ __launch_bounds__(256, 1) void gemm5_kernel(
    const float* __restrict__ Afp, const float* __restrict__ Bfp,
    const __nv_bfloat16* __restrict__ Bbh, const __nv_bfloat16* __restrict__ Bbl,
    float* __restrict__ Out, const float* __restrict__ temp) {
    extern __shared__ __align__(1024) char smem[];

    const int tid = threadIdx.x;
    const int wid = tid >> 5, lid = tid & 31;
    const int b = blockIdx.z;
    const int m0 = blockIdx.y * 128, n0 = blockIdx.x * 128;

    const float* Ab = Afp + (size_t)b * SQ * KDIM;

#if HAS_TCGEN05
    const uint32_t sbase = smem_u32(smem);

    if (wid == 0) {
        tmem_alloc(sbase, 128);
        tmem_relinquish();
    }
    if (tid == 0) {
        mbar_init(sbase + 8, 1);
        mbar_init(sbase + 16, 1);
        mbar_init(sbase + 24, 1);
    }
    __syncthreads();
    uint32_t tmem;
    asm volatile("ld.shared.b32 %0, [%1];" : "=r"(tmem) : "r"(sbase));

    constexpr int NSTAGE = KDIM / KTILE;

    for (int s = 0; s < NSTAGE; s++) {
        const int buf = s % NBUF;
        if (s >= NBUF)
            mbar_wait(sbase + 8 + buf * 8, (s / NBUF - 1) & 1);

        const int k0 = s * KTILE;
        char* bufp = smem + SMEM_TILES + buf * (4 * TILE_B);
        // A (always fp32 -> hi/lo)
        load_convert_fp32(Ab, m0, KDIM, k0, bufp, bufp + TILE_B, tid);
        // B
        if (B_BF16) {
            const __nv_bfloat16* Bh = Bbh + (size_t)b * BROWS * KDIM;
            const __nv_bfloat16* Bl = Bbl + (size_t)b * BROWS * KDIM;
            load_bf16_tile(Bh, n0, KDIM, k0, bufp + 2 * TILE_B, tid);
            load_bf16_tile(Bl, n0, KDIM, k0, bufp + 3 * TILE_B, tid);
        } else {
            const float* Bb = Bfp + (size_t)b * BROWS * KDIM;
            load_convert_fp32(Bb, n0, KDIM, k0, bufp + 2 * TILE_B, bufp + 3 * TILE_B, tid);
        }
        __syncthreads();
        if (wid == 0) {
            fence_async_shared();
            if (elect1()) {
                uint32_t base = sbase + SMEM_TILES + buf * (4 * TILE_B);
                uint64_t dAh = mk_desc(base);
                uint64_t dAl = mk_desc(base + TILE_B);
                uint64_t dBh = mk_desc(base + 2 * TILE_B);
                uint64_t dBl = mk_desc(base + 3 * TILE_B);
                #pragma unroll
                for (int ks = 0; ks < KTILE / 16; ks++) {
                    uint32_t acc0 = (s == 0 && ks == 0) ? 0u : 1u;
                    mma_bf16_ss(tmem, dAh + ks * 2, dBh + ks * 2, GEMM_IDESC, acc0);
                    mma_bf16_ss(tmem, dAh + ks * 2, dBl + ks * 2, GEMM_IDESC, 1u);
                    mma_bf16_ss(tmem, dAl + ks * 2, dBh + ks * 2, GEMM_IDESC, 1u);
                }
                mma_commit(sbase + 8 + buf * 8);
            }
        }
    }

    // commit covers ALL prior MMAs -> waiting the last stage's commit drains everything
    {
        const int slast = NSTAGE - 1;
        mbar_wait(sbase + 8 + (slast % NBUF) * 8, (slast / NBUF) & 1);
    }
    tc_fence_after();

    if (wid < 4) {
        const int m = m0 + wid * 32 + lid;
        float invT = 1.0f;
        if (IS_QK) invT = 1.0f / temp[0];
        #pragma unroll
        for (int cb = 0; cb < 128; cb += 32) {
            uint32_t r[32];
            ldtm32(r, tmem + cb);
            tc_wait_ld();
            float* op = Out + (size_t)b * SQ * LDOUT + (size_t)m * LDOUT + n0 + cb;
            if (IS_QK) {
                const float* kq = g_ksq + b * SK + n0 + cb;
                #pragma unroll
                for (int c = 0; c < 32; c += 4) {
                    float4 o;
                    o.x = (2.f * __uint_as_float(r[c + 0]) - kq[c + 0]) * invT;
                    o.y = (2.f * __uint_as_float(r[c + 1]) - kq[c + 1]) * invT;
                    o.z = (2.f * __uint_as_float(r[c + 2]) - kq[c + 2]) * invT;
                    o.w = (2.f * __uint_as_float(r[c + 3]) - kq[c + 3]) * invT;
                    *(float4*)(op + c) = o;
                }
            } else {
                #pragma unroll
                for (int c = 0; c < 32; c += 4) {
                    float4 o;
                    o.x = __uint_as_float(r[c + 0]);
                    o.y = __uint_as_float(r[c + 1]);
                    o.z = __uint_as_float(r[c + 2]);
                    o.w = __uint_as_float(r[c + 3]);
                    *(float4*)(op + c) = o;
                }
            }
        }
    }
    __syncthreads();
    if (wid == 0) tmem_dealloc(tmem, 128);

#else  // ---------------- fp32 FFMA fallback (plain sm_103 pass) ----------------
    float (*As)[132] = (float (*)[132])smem;
    float (*Bs)[132] = (float (*)[132])(smem + 16 * 132 * sizeof(float));

    float* Ob = Out + (size_t)b * SQ * LDOUT;
    const int lr = tid >> 2;
    const int lc = (tid & 3) << 2;
    const int tm = (tid >> 4) << 3;
    const int tn = (tid & 15) << 3;

    float acc[8][8];
    #pragma unroll
    for (int i = 0; i < 8; i++)
        #pragma unroll
        for (int j = 0; j < 8; j++) acc[i][j] = 0.f;

    for (int k0 = 0; k0 < KDIM; k0 += 16) {
        #pragma unroll
        for (int i = 0; i < 2; i++) {
            int row = lr + i * 64;
            float4 v = *(const float4*)(Ab + (size_t)(m0 + row) * KDIM + k0 + lc);
            As[lc + 0][row] = v.x; As[lc + 1][row] = v.y;
            As[lc + 2][row] = v.z; As[lc + 3][row] = v.w;
            if (B_BF16) {
                const __nv_bfloat16* Bh = Bbh + (size_t)b * BROWS * KDIM;
                const __nv_bfloat16* Bl = Bbl + (size_t)b * BROWS * KDIM;
                #pragma unroll
                for (int c = 0; c < 4; c++) {
                    size_t o = (size_t)(n0 + row) * KDIM + k0 + lc + c;
                    Bs[lc + c][row] = __bfloat162float(Bh[o]) + __bfloat162float(Bl[o]);
                }
            } else {
                const float* Bb = Bfp + (size_t)b * BROWS * KDIM;
                float4 w = *(const float4*)(Bb + (size_t)(n0 + row) * KDIM + k0 + lc);
                Bs[lc + 0][row] = w.x; Bs[lc + 1][row] = w.y;
                Bs[lc + 2][row] = w.z; Bs[lc + 3][row] = w.w;
            }
        }
        __syncthreads();
        #pragma unroll
        for (int kk = 0; kk < 16; kk++) {
            float a[8], bb[8];
            #pragma unroll
            for (int i = 0; i < 8; i++) a[i] = As[kk][tm + i];
            #pragma unroll
            for (int j = 0; j < 8; j++) bb[j] = Bs[kk][tn + j];
            #pragma unroll
            for (int i = 0; i < 8; i++)
                #pragma unroll
                for (int j = 0; j < 8; j++)
                    acc[i][j] = fmaf(a[i], bb[j], acc[i][j]);
        }
        __syncthreads();
    }

    if (IS_QK) {
        const float invT = 1.0f / temp[0];
        float kq[8];
        #pragma unroll
        for (int j = 0; j < 8; j++) kq[j] = g_ksq[b * SK + n0 + tn + j];
        #pragma unroll
        for (int i = 0; i < 8; i++) {
            float* op = Ob + (size_t)(m0 + tm + i) * LDOUT + n0 + tn;
            #pragma unroll
            for (int j = 0; j < 8; j++)
                op[j] = (2.0f * acc[i][j] - kq[j]) * invT;
        }
    } else {
        #pragma unroll
        for (int i = 0; i < 8; i++) {
            float* op = Ob + (size_t)(m0 + tm + i) * LDOUT + n0 + tn;
            *(float4*)(op + 0) = make_float4(acc[i][0], acc[i][1], acc[i][2], acc[i][3]);
            *(float4*)(op + 4) = make_float4(acc[i][4], acc[i][5], acc[i][6], acc[i][7]);
        }
    }
#endif
}

// ---------------------------------------------------------------------------
// softmax (in-place fp32)
// ---------------------------------------------------------------------------
__global__ __launch_bounds__(256) void softmax_kernel(float* __restrict__ W) {
    const int row = blockIdx.x;
    float* r = W + (size_t)row * SK;
    const int tid = threadIdx.x;

    float vals[8];
    float m = -3.0e38f;
    #pragma unroll
    for (int i = 0; i < 8; i++) {
        vals[i] = r[tid + i * 256];
        m = fmaxf(m, vals[i]);
    }

    __shared__ float red[8];
    #pragma unroll
    for (int o = 16; o > 0; o >>= 1) m = fmaxf(m, __shfl_xor_sync(0xffffffffu, m, o));
    if ((tid & 31) == 0) red[tid >> 5] = m;
    __syncthreads();
    m = red[0];
    #pragma unroll
    for (int w = 1; w < 8; w++) m = fmaxf(m, red[w]);
    __syncthreads();

    float s = 0.f;
    #pragma unroll
    for (int i = 0; i < 8; i++) {
        vals[i] = __expf(vals[i] - m);
        s += vals[i];
    }
    #pragma unroll
    for (int o = 16; o > 0; o >>= 1) s += __shfl_xor_sync(0xffffffffu, s, o);
    if ((tid & 31) == 0) red[tid >> 5] = s;
    __syncthreads();
    s = red[0];
    #pragma unroll
    for (int w = 1; w < 8; w++) s += red[w];

    const float inv = 1.0f / s;
    #pragma unroll
    for (int i = 0; i < 8; i++) r[tid + i * 256] = vals[i] * inv;
}

// ---------------------------------------------------------------------------
extern "C" void kernel_launch(void* const* d_in, const int* in_sizes, int n_in,
                              void* d_out, int out_size) {
    const float* Q = (const float*)d_in[0];
    const float* K = (const float*)d_in[1];
    const float* V = (const float*)d_in[2];
    const float* T = (const float*)d_in[3];

    float* attended = (float*)d_out;                        // [B,SQ,DH]
    float* weights  = (float*)d_out + (size_t)NB * SQ * DH; // [B,SQ,SK]

    void *vth, *vtl;
    cudaGetSymbolAddress(&vth, g_Vth);
    cudaGetSymbolAddress(&vtl, g_Vtl);

    cudaFuncSetAttribute((const void*)gemm5_kernel<512, SK, SK, false, true>,
                         cudaFuncAttributeMaxDynamicSharedMemorySize, SMEM_TOTAL);
    cudaFuncSetAttribute((const void*)gemm5_kernel<2048, DH, DH, true, false>,
                         cudaFuncAttributeMaxDynamicSharedMemorySize, SMEM_TOTAL);

    // 1) ksq + V transpose/split
    ksq_kernel<<<NB * SK * 32 / 256, 256>>>(K);
    vsplit_kernel<<<dim3(DH / 32, SK / 32, NB), dim3(32, 8)>>>(V);

    // 2) logits = (2 q.k - ksq)/T  into weights region (tensor cores,
    //    fp32->bf16 hi/lo conversion fused into the load stage)
    gemm5_kernel<512, SK, SK, false, true><<<dim3(SK / 128, SQ / 128, NB), 256, SMEM_TOTAL>>>(
        Q, K, nullptr, nullptr, weights, T);

    // 3) softmax in-place
    softmax_kernel<<<NB * SQ, 256>>>(weights);

    // 4) attended = W @ V  (W converted on the fly, V pre-split/transposed)
    gemm5_kernel<2048, DH, DH, true, false><<<dim3(DH / 128, SQ / 128, NB), 256, SMEM_TOTAL>>>(
        weights, nullptr, (const __nv_bfloat16*)vth, (const __nv_bfloat16*)vtl,
        attended, nullptr);
}

// round 5
// speedup vs baseline: 1.4266x; 1.4266x over previous
#include <cuda_runtime.h>
#include <cuda_bf16.h>
#include <cstdint>

#define NB 8
#define SQ 2048
#define SK 2048
#define DH 512

#define CHUNK_B 32768          // one 128x64 tile pair: [hi 16KB][lo 16KB]
#define NBUF 3
#define SMEM_TILES 1024
#define SMEM_TOTAL (SMEM_TILES + NBUF * 2 * CHUNK_B)  // 197632 bytes

// tcgen05 is arch-accelerated ('a'): only emit in sm_10xa passes.
#if defined(__CUDA_ARCH_FEAT_SM103_ALL) || defined(__CUDA_ARCH_FEAT_SM100_ALL) || \
    defined(__CUDA_ARCH_FEAT_SM101_ALL) ||                                        \
    (defined(__CUDA_ARCH_SPECIFIC__) && (__CUDA_ARCH_SPECIFIC__ >= 1000)) ||      \
    (defined(__CUDA_ARCH_FAMILY_SPECIFIC__) && (__CUDA_ARCH_FAMILY_SPECIFIC__ >= 1000))
#define HAS_TCGEN05 1
#else
#define HAS_TCGEN05 0
#endif

// ------------------------- device scratch (chunked tile layouts) -----------
// chunk index = ((b*TILES + tile)*KST + kstage); each chunk = 32KB (hi+lo)
__device__ float g_ksq[NB * SK];
__device__ __align__(128) char g_Qs[(size_t)NB * 16 * 8 * CHUNK_B];   // 33.5MB
__device__ __align__(128) char g_Ks[(size_t)NB * 16 * 8 * CHUNK_B];   // 33.5MB
__device__ __align__(128) char g_Vs[(size_t)NB * 4 * 32 * CHUNK_B];   // 33.5MB
__device__ __align__(128) char g_Ws[(size_t)NB * 16 * 32 * CHUNK_B];  // 134MB

// ------------------------- ptx helpers -------------------------
__device__ __forceinline__ uint32_t smem_u32(const void* p) {
    uint32_t a;
    asm("{ .reg .u64 t; cvta.to.shared.u64 t, %1; cvt.u32.u64 %0, t; }" : "=r"(a) : "l"(p));
    return a;
}
__device__ __forceinline__ uint32_t elect1() {
    uint32_t p;
    asm volatile("{\n\t.reg .pred p;\n\telect.sync _|p, 0xFFFFFFFF;\n\tselp.b32 %0,1,0,p;\n\t}" : "=r"(p));
    return p;
}
__device__ __forceinline__ void mbar_init(uint32_t addr, uint32_t cnt) {
    asm volatile("mbarrier.init.shared.b64 [%0], %1;" :: "r"(addr), "r"(cnt) : "memory");
}
__device__ __forceinline__ void mbar_wait(uint32_t mbar, uint32_t parity) {
    asm volatile(
        "{\n\t.reg .pred P;\n\t"
        "W_%=:\n\t"
        "mbarrier.try_wait.parity.acquire.cta.shared::cta.b64 P, [%0], %1, 0x989680;\n\t"
        "@P bra.uni D_%=;\n\t"
        "bra.uni W_%=;\n\t"
        "D_%=:\n\t}"
        :: "r"(mbar), "r"(parity) : "memory");
}
__device__ __forceinline__ void mbar_expect_tx(uint32_t mbar, uint32_t bytes) {
    asm volatile("mbarrier.arrive.expect_tx.shared.b64 _, [%0], %1;"
                 :: "r"(mbar), "r"(bytes) : "memory");
}
__device__ __forceinline__ void bulk_g2s(uint32_t dst, const void* src, uint32_t bytes,
                                         uint32_t mbar) {
    asm volatile(
        "cp.async.bulk.shared::cluster.global.mbarrier::complete_tx::bytes [%0], [%1], %2, [%3];"
        :: "r"(dst), "l"(src), "r"(bytes), "r"(mbar) : "memory");
}

#if HAS_TCGEN05
__device__ __forceinline__ void tmem_alloc(uint32_t smem_addr, uint32_t ncols) {
    asm volatile("tcgen05.alloc.cta_group::1.sync.aligned.shared::cta.b32 [%0], %1;"
                 :: "r"(smem_addr), "r"(ncols) : "memory");
}
__device__ __forceinline__ void tmem_dealloc(uint32_t tmem, uint32_t ncols) {
    asm volatile("tcgen05.dealloc.cta_group::1.sync.aligned.b32 %0, %1;" :: "r"(tmem), "r"(ncols));
}
__device__ __forceinline__ void tmem_relinquish() {
    asm volatile("tcgen05.relinquish_alloc_permit.cta_group::1.sync.aligned;");
}
__device__ __forceinline__ void mma_commit(uint32_t mbar) {
    asm volatile("tcgen05.commit.cta_group::1.mbarrier::arrive::one.shared::cluster.b64 [%0];"
                 :: "r"(mbar) : "memory");
}
__device__ __forceinline__ void tc_fence_after() {
    asm volatile("tcgen05.fence::after_thread_sync;" ::: "memory");
}
__device__ __forceinline__ void tc_wait_ld() {
    asm volatile("tcgen05.wait::ld.sync.aligned;" ::: "memory");
}
__device__ __forceinline__ uint64_t mk_desc(uint32_t addr) {
    // SW128, version=1, SBO=64, LBO=1 (K-major, 128B rows)
    return (2ULL << 61) | (1ULL << 46) | (64ULL << 32) | (1ULL << 16) |
           ((uint64_t)(addr >> 4) & 0x3FFF);
}
__device__ __forceinline__ void mma_bf16_ss(uint32_t d, uint64_t da, uint64_t db,
                                            uint32_t idesc, uint32_t acc) {
    asm volatile(
        "{\n\t.reg .pred p;\n\t"
        "setp.ne.u32 p, %4, 0;\n\t"
        "tcgen05.mma.cta_group::1.kind::f16 [%0], %1, %2, %3, {%5, %5, %5, %5}, p;\n\t}"
        :: "r"(d), "l"(da), "l"(db), "r"(idesc), "r"(acc), "r"(0u) : "memory");
}
__device__ __forceinline__ void ldtm32(uint32_t* r, uint32_t a) {
    asm volatile(
        "tcgen05.ld.sync.aligned.32x32b.x32.b32 "
        "{%0,%1,%2,%3,%4,%5,%6,%7,%8,%9,%10,%11,%12,%13,%14,%15,"
        "%16,%17,%18,%19,%20,%21,%22,%23,%24,%25,%26,%27,%28,%29,%30,%31}, [%32];"
        : "=r"(r[0]), "=r"(r[1]), "=r"(r[2]), "=r"(r[3]), "=r"(r[4]), "=r"(r[5]), "=r"(r[6]), "=r"(r[7]),
          "=r"(r[8]), "=r"(r[9]), "=r"(r[10]), "=r"(r[11]), "=r"(r[12]), "=r"(r[13]), "=r"(r[14]), "=r"(r[15]),
          "=r"(r[16]), "=r"(r[17]), "=r"(r[18]), "=r"(r[19]), "=r"(r[20]), "=r"(r[21]), "=r"(r[22]), "=r"(r[23]),
          "=r"(r[24]), "=r"(r[25]), "=r"(r[26]), "=r"(r[27]), "=r"(r[28]), "=r"(r[29]), "=r"(r[30]), "=r"(r[31])
        : "r"(a));
}
#endif // HAS_TCGEN05

// idesc: F32 accum, BF16 a/b, M=128, N=128
#define GEMM_IDESC ((1u << 4) | (1u << 7) | (1u << 10) | (16u << 17) | (8u << 24))

// ---------------------------------------------------------------------------
// k_sq
// ---------------------------------------------------------------------------
__global__ __launch_bounds__(256) void ksq_kernel(const float* __restrict__ K) {
    int gw = (blockIdx.x * blockDim.x + threadIdx.x) >> 5;
    int lane = threadIdx.x & 31;
    if (gw >= NB * SK) return;
    const float* row = K + (size_t)gw * DH;
    float s = 0.f;
    #pragma unroll
    for (int i = lane * 4; i < DH; i += 128) {
        float4 v = *(const float4*)(row + i);
        s = fmaf(v.x, v.x, s); s = fmaf(v.y, v.y, s);
        s = fmaf(v.z, v.z, s); s = fmaf(v.w, v.w, s);
    }
    #pragma unroll
    for (int o = 16; o > 0; o >>= 1) s += __shfl_xor_sync(0xffffffffu, s, o);
    if (lane == 0) g_ksq[gw] = s;
}

// ---------------------------------------------------------------------------
// helpers for hi/lo packing
// ---------------------------------------------------------------------------
__device__ __forceinline__ void split8(const float* v, uint32_t* hi, uint32_t* lo) {
    #pragma unroll
    for (int p = 0; p < 4; p++) {
        __nv_bfloat162 h(__float2bfloat16(v[2 * p]), __float2bfloat16(v[2 * p + 1]));
        __nv_bfloat162 l(__float2bfloat16(v[2 * p] - __bfloat162float(h.x)),
                         __float2bfloat16(v[2 * p + 1] - __bfloat162float(h.y)));
        hi[p] = *(uint32_t*)&h;
        lo[p] = *(uint32_t*)&l;
    }
}

// ---------------------------------------------------------------------------
// Q/K split into chunked swizzled hi/lo layout. kst = KDIM/64 (8 here).
// thread handles 8 consecutive k of one row.
// ---------------------------------------------------------------------------
__global__ __launch_bounds__(256) void splitqk_kernel(const float* __restrict__ X,
                                                      char* __restrict__ dst, int kst) {
    const int kdim = kst * 64;
    const int tpr = kst * 8;  // threads per row
    int idx = blockIdx.x * 256 + threadIdx.x;
    int mg = idx / tpr;
    int k0 = (idx % tpr) * 8;
    int b = mg >> 11, m = mg & 2047;
    int mtile = m >> 7, row = m & 127;
    int kstage = k0 >> 6, colc = k0 & 63;

    float v[8];
    const float* src = X + (size_t)mg * kdim + k0;
    *(float4*)(v) = *(const float4*)(src);
    *(float4*)(v + 4) = *(const float4*)(src + 4);
    uint32_t hi[4], lo[4];
    split8(v, hi, lo);

    size_t base = (size_t)((b * 16 + mtile) * kst + kstage) * CHUNK_B;
    uint32_t off = row * 128 + colc * 2;
    off ^= (off >> 3) & 0x70;
    *(uint4*)(dst + base + off) = make_uint4(hi[0], hi[1], hi[2], hi[3]);
    *(uint4*)(dst + base + 16384 + off) = make_uint4(lo[0], lo[1], lo[2], lo[3]);
}

// ---------------------------------------------------------------------------
// V transpose + split into chunked layout: row=d, col=k. KST=32, NTILES=4.
// ---------------------------------------------------------------------------
__global__ __launch_bounds__(256) void vsplit_kernel(const float* __restrict__ V) {
    __shared__ float t[32][33];
    const int b = blockIdx.z;
    const int d0 = blockIdx.x * 32, k0 = blockIdx.y * 32;
    const float* Vb = V + (size_t)b * SK * DH;
    const int tid = threadIdx.x;
    // load 32k x 32d
    #pragma unroll
    for (int i = 0; i < 4; i++) {
        int kk = (tid >> 5) + i * 8, dd = tid & 31;
        t[kk][dd] = Vb[(size_t)(k0 + kk) * DH + d0 + dd];
    }
    __syncthreads();
    // write: thread -> (d_local, 4 consecutive k)
    int d_local = tid >> 3, k_local = (tid & 7) * 4;
    float v[4];
    #pragma unroll
    for (int i = 0; i < 4; i++) v[i] = t[k_local + i][d_local];
    uint32_t hi[2], lo[2];
    #pragma unroll
    for (int p = 0; p < 2; p++) {
        __nv_bfloat162 h(__float2bfloat16(v[2 * p]), __float2bfloat16(v[2 * p + 1]));
        __nv_bfloat162 l(__float2bfloat16(v[2 * p] - __bfloat162float(h.x)),
                         __float2bfloat16(v[2 * p + 1] - __bfloat162float(h.y)));
        hi[p] = *(uint32_t*)&h;
        lo[p] = *(uint32_t*)&l;
    }
    int d = d0 + d_local, k = k0 + k_local;
    int ntile = d >> 7, row = d & 127, kstage = k >> 6, colc = k & 63;
    size_t base = (size_t)((b * 4 + ntile) * 32 + kstage) * CHUNK_B;
    uint32_t off = row * 128 + colc * 2;
    off ^= (off >> 3) & 0x70;
    *(uint2*)(g_Vs + base + off) = make_uint2(hi[0], hi[1]);
    *(uint2*)(g_Vs + base + 16384 + off) = make_uint2(lo[0], lo[1]);
}

// ---------------------------------------------------------------------------
// GEMM: D[m][n] = sum_k A[m][k]*B[n][k], split-bf16 3-product, fp32 accum.
// Operands pre-chunked; mainloop = cp.async.bulk + tcgen05, one elected thread.
// ---------------------------------------------------------------------------
template <int MT, int NT, int KST, bool IS_QK>
__global__ __launch_bounds__(256, 1) void gemm5_kernel(
    const char* __restrict__ Achunks, const char* __restrict__ Bchunks,
    float* __restrict__ Out, const float* __restrict__ temp) {
    extern __shared__ __align__(1024) char smem[];
    constexpr int LDOUT = NT * 128;

    const int tid = threadIdx.x;
    const int wid = tid >> 5, lid = tid & 31;
    const int b = blockIdx.z;
    const int my = blockIdx.y, nx = blockIdx.x;
    const int m0 = my * 128, n0 = nx * 128;

#if HAS_TCGEN05
    const uint32_t sbase = smem_u32(smem);
    // mbar layout: full[3]@+8,16,24  empty[3]@+32,40,48  done@+56
    if (wid == 0) {
        tmem_alloc(sbase, 128);
        tmem_relinquish();
    }
    if (tid == 0) {
        #pragma unroll
        for (int i = 0; i < 3; i++) {
            mbar_init(sbase + 8 + i * 8, 1);
            mbar_init(sbase + 32 + i * 8, 1);
        }
        mbar_init(sbase + 56, 1);
    }
    __syncthreads();
    uint32_t tmem;
    asm volatile("ld.shared.b32 %0, [%1];" : "=r"(tmem) : "r"(sbase));

    const char* Abase = Achunks + (size_t)(b * MT + my) * KST * CHUNK_B;
    const char* Bbase = Bchunks + (size_t)(b * NT + nx) * KST * CHUNK_B;

    if (wid == 0 && elect1()) {
        // prologue: fill all buffers
        #pragma unroll
        for (int p = 0; p < NBUF; p++) {
            uint32_t fm = sbase + 8 + p * 8;
            uint32_t dst = sbase + SMEM_TILES + p * 2 * CHUNK_B;
            mbar_expect_tx(fm, 2 * CHUNK_B);
            bulk_g2s(dst, Abase + (size_t)p * CHUNK_B, CHUNK_B, fm);
            bulk_g2s(dst + CHUNK_B, Bbase + (size_t)p * CHUNK_B, CHUNK_B, fm);
        }
        for (int s = 0; s < KST; s++) {
            const int buf = s % NBUF;
            mbar_wait(sbase + 8 + buf * 8, (s / NBUF) & 1);
            uint32_t tb = sbase + SMEM_TILES + buf * 2 * CHUNK_B;
            uint64_t dAh = mk_desc(tb);
            uint64_t dAl = mk_desc(tb + 16384);
            uint64_t dBh = mk_desc(tb + CHUNK_B);
            uint64_t dBl = mk_desc(tb + CHUNK_B + 16384);
            #pragma unroll
            for (int ks = 0; ks < 4; ks++) {
                uint32_t acc0 = (s == 0 && ks == 0) ? 0u : 1u;
                mma_bf16_ss(tmem, dAh + ks * 2, dBh + ks * 2, GEMM_IDESC, acc0);
                mma_bf16_ss(tmem, dAh + ks * 2, dBl + ks * 2, GEMM_IDESC, 1u);
                mma_bf16_ss(tmem, dAl + ks * 2, dBh + ks * 2, GEMM_IDESC, 1u);
            }
            mma_commit(sbase + 32 + buf * 8);
            if (s + NBUF < KST) {
                // buffer reusable once this stage's MMAs complete
                mbar_wait(sbase + 32 + buf * 8, (s / NBUF) & 1);
                uint32_t fm = sbase + 8 + buf * 8;
                mbar_expect_tx(fm, 2 * CHUNK_B);
                bulk_g2s(tb, Abase + (size_t)(s + NBUF) * CHUNK_B, CHUNK_B, fm);
                bulk_g2s(tb + CHUNK_B, Bbase + (size_t)(s + NBUF) * CHUNK_B, CHUNK_B, fm);
            }
        }
        mma_commit(sbase + 56);
    }

    mbar_wait(sbase + 56, 0);
    tc_fence_after();

    if (wid < 4) {
        const int m = m0 + wid * 32 + lid;
        float invT = 1.0f;
        if (IS_QK) invT = 1.0f / temp[0];
        #pragma unroll
        for (int cb = 0; cb < 128; cb += 32) {
            uint32_t r[32];
            ldtm32(r, tmem + cb);
            tc_wait_ld();
            float* op = Out + (size_t)b * SQ * LDOUT + (size_t)m * LDOUT + n0 + cb;
            if (IS_QK) {
                const float* kq = g_ksq + b * SK + n0 + cb;
                #pragma unroll
                for (int c = 0; c < 32; c += 4) {
                    float4 o;
                    o.x = (2.f * __uint_as_float(r[c + 0]) - kq[c + 0]) * invT;
                    o.y = (2.f * __uint_as_float(r[c + 1]) - kq[c + 1]) * invT;
                    o.z = (2.f * __uint_as_float(r[c + 2]) - kq[c + 2]) * invT;
                    o.w = (2.f * __uint_as_float(r[c + 3]) - kq[c + 3]) * invT;
                    *(float4*)(op + c) = o;
                }
            } else {
                #pragma unroll
                for (int c = 0; c < 32; c += 4) {
                    float4 o;
                    o.x = __uint_as_float(r[c + 0]);
                    o.y = __uint_as_float(r[c + 1]);
                    o.z = __uint_as_float(r[c + 2]);
                    o.w = __uint_as_float(r[c + 3]);
                    *(float4*)(op + c) = o;
                }
            }
        }
    }
    __syncthreads();
    if (wid == 0) tmem_dealloc(tmem, 128);

#else  // ---------------- naive correct fallback (plain sm_103 pass; unused) ----
    const float invT = IS_QK ? 1.f / temp[0] : 1.f;
    const char* ca0 = Achunks + (size_t)(b * MT + my) * KST * CHUNK_B;
    const char* cb0 = Bchunks + (size_t)(b * NT + nx) * KST * CHUNK_B;
    for (int e = tid; e < 128 * 128; e += 256) {
        int i = e >> 7, j = e & 127;
        float acc = 0.f;
        for (int s = 0; s < KST; s++) {
            const char* ca = ca0 + (size_t)s * CHUNK_B;
            const char* cb = cb0 + (size_t)s * CHUNK_B;
            for (int k = 0; k < 64; k++) {
                uint32_t oa = i * 128 + k * 2; oa ^= (oa >> 3) & 0x70;
                uint32_t ob = j * 128 + k * 2; ob ^= (ob >> 3) & 0x70;
                float a = __bfloat162float(*(const __nv_bfloat16*)(ca + oa)) +
                          __bfloat162float(*(const __nv_bfloat16*)(ca + 16384 + oa));
                float bb = __bfloat162float(*(const __nv_bfloat16*)(cb + ob)) +
                           __bfloat162float(*(const __nv_bfloat16*)(cb + 16384 + ob));
                acc = fmaf(a, bb, acc);
            }
        }
        float* op = Out + (size_t)b * SQ * LDOUT + (size_t)(m0 + i) * LDOUT + n0 + j;
        *op = IS_QK ? (2.f * acc - g_ksq[b * SK + n0 + j]) * invT : acc;
    }
#endif
}

// ---------------------------------------------------------------------------
// softmax (in-place fp32) + write hi/lo chunked W tiles for PV
// thread handles 8 consecutive cols.
// ---------------------------------------------------------------------------
__global__ __launch_bounds__(256) void softmax_kernel(float* __restrict__ W) {
    const int rowg = blockIdx.x;
    float* r = W + (size_t)rowg * SK;
    const int tid = threadIdx.x;

    float vals[8];
    *(float4*)(vals) = *(const float4*)(r + tid * 8);
    *(float4*)(vals + 4) = *(const float4*)(r + tid * 8 + 4);
    float m = vals[0];
    #pragma unroll
    for (int i = 1; i < 8; i++) m = fmaxf(m, vals[i]);

    __shared__ float red[8];
    #pragma unroll
    for (int o = 16; o > 0; o >>= 1) m = fmaxf(m, __shfl_xor_sync(0xffffffffu, m, o));
    if ((tid & 31) == 0) red[tid >> 5] = m;
    __syncthreads();
    m = red[0];
    #pragma unroll
    for (int w = 1; w < 8; w++) m = fmaxf(m, red[w]);
    __syncthreads();

    float s = 0.f;
    #pragma unroll
    for (int i = 0; i < 8; i++) {
        vals[i] = __expf(vals[i] - m);
        s += vals[i];
    }
    #pragma unroll
    for (int o = 16; o > 0; o >>= 1) s += __shfl_xor_sync(0xffffffffu, s, o);
    if ((tid & 31) == 0) red[tid >> 5] = s;
    __syncthreads();
    s = red[0];
    #pragma unroll
    for (int w = 1; w < 8; w++) s += red[w];

    const float inv = 1.0f / s;
    #pragma unroll
    for (int i = 0; i < 8; i++) vals[i] *= inv;
    *(float4*)(r + tid * 8) = *(float4*)(vals);
    *(float4*)(r + tid * 8 + 4) = *(float4*)(vals + 4);

    // chunked hi/lo write for PV A-operand
    uint32_t hi[4], lo[4];
    split8(vals, hi, lo);
    const int b = rowg >> 11, q = rowg & 2047;
    const int mtile = q >> 7, row = q & 127;
    const int kstage = tid >> 3, colc = (tid * 8) & 63;
    size_t base = (size_t)((b * 16 + mtile) * 32 + kstage) * CHUNK_B;
    uint32_t off = row * 128 + colc * 2;
    off ^= (off >> 3) & 0x70;
    *(uint4*)(g_Ws + base + off) = make_uint4(hi[0], hi[1], hi[2], hi[3]);
    *(uint4*)(g_Ws + base + 16384 + off) = make_uint4(lo[0], lo[1], lo[2], lo[3]);
}

// ---------------------------------------------------------------------------
extern "C" void kernel_launch(void* const* d_in, const int* in_sizes, int n_in,
                              void* d_out, int out_size) {
    const float* Q = (const float*)d_in[0];
    const float* K = (const float*)d_in[1];
    const float* V = (const float*)d_in[2];
    const float* T = (const float*)d_in[3];

    float* attended = (float*)d_out;                        // [B,SQ,DH]
    float* weights  = (float*)d_out + (size_t)NB * SQ * DH; // [B,SQ,SK]

    void *qs, *ks, *vs, *ws;
    cudaGetSymbolAddress(&qs, g_Qs);
    cudaGetSymbolAddress(&ks, g_Ks);
    cudaGetSymbolAddress(&vs, g_Vs);
    cudaGetSymbolAddress(&ws, g_Ws);

    cudaFuncSetAttribute((const void*)gemm5_kernel<16, 16, 8, true>,
                         cudaFuncAttributeMaxDynamicSharedMemorySize, SMEM_TOTAL);
    cudaFuncSetAttribute((const void*)gemm5_kernel<16, 4, 32, false>,
                         cudaFuncAttributeMaxDynamicSharedMemorySize, SMEM_TOTAL);

    // 1) prep: ksq, Q/K split, V transpose+split
    ksq_kernel<<<NB * SK * 32 / 256, 256>>>(K);
    splitqk_kernel<<<NB * SQ * 64 / 256, 256>>>(Q, (char*)qs, 8);
    splitqk_kernel<<<NB * SK * 64 / 256, 256>>>(K, (char*)ks, 8);
    vsplit_kernel<<<dim3(DH / 32, SK / 32, NB), 256>>>(V);

    // 2) logits = (2 q.k - ksq)/T into weights region
    gemm5_kernel<16, 16, 8, true><<<dim3(16, 16, NB), 256, SMEM_TOTAL>>>(
        (const char*)qs, (const char*)ks, weights, T);

    // 3) softmax in-place + chunked hi/lo W
    softmax_kernel<<<NB * SQ, 256>>>(weights);

    // 4) attended = W @ V
    gemm5_kernel<16, 4, 32, false><<<dim3(4, 16, NB), 256, SMEM_TOTAL>>>(
        (const char*)ws, (const char*)vs, attended, nullptr);
}

// round 6
// speedup vs baseline: 1.5057x; 1.0555x over previous
#include <cuda_runtime.h>
#include <cuda_bf16.h>
#include <cstdint>

#define NB 8
#define SQ 2048
#define SK 2048
#define DH 512

#define CHUNK_B 32768          // one 128x64 tile pair: [hi 16KB][lo 16KB]
#define NBUF 3
#define TPT 4                  // tiles per CTA
#define SMEM_TILES 1024
#define SMEM_TOTAL (SMEM_TILES + NBUF * 2 * CHUNK_B)  // 197632 bytes

// tcgen05 is arch-accelerated ('a'): only emit in sm_10xa passes.
#if defined(__CUDA_ARCH_FEAT_SM103_ALL) || defined(__CUDA_ARCH_FEAT_SM100_ALL) || \
    defined(__CUDA_ARCH_FEAT_SM101_ALL) ||                                        \
    (defined(__CUDA_ARCH_SPECIFIC__) && (__CUDA_ARCH_SPECIFIC__ >= 1000)) ||      \
    (defined(__CUDA_ARCH_FAMILY_SPECIFIC__) && (__CUDA_ARCH_FAMILY_SPECIFIC__ >= 1000))
#define HAS_TCGEN05 1
#else
#define HAS_TCGEN05 0
#endif

// ------------------------- device scratch (chunked tile layouts) -----------
__device__ float g_ksq[NB * SK];
__device__ __align__(128) char g_Qs[(size_t)NB * 16 * 8 * CHUNK_B];   // 33.5MB
__device__ __align__(128) char g_Ks[(size_t)NB * 16 * 8 * CHUNK_B];   // 33.5MB
__device__ __align__(128) char g_Vs[(size_t)NB * 4 * 32 * CHUNK_B];   // 33.5MB
__device__ __align__(128) char g_Ws[(size_t)NB * 16 * 32 * CHUNK_B];  // 134MB

// ------------------------- ptx helpers -------------------------
__device__ __forceinline__ uint32_t smem_u32(const void* p) {
    uint32_t a;
    asm("{ .reg .u64 t; cvta.to.shared.u64 t, %1; cvt.u32.u64 %0, t; }" : "=r"(a) : "l"(p));
    return a;
}
__device__ __forceinline__ uint32_t elect1() {
    uint32_t p;
    asm volatile("{\n\t.reg .pred p;\n\telect.sync _|p, 0xFFFFFFFF;\n\tselp.b32 %0,1,0,p;\n\t}" : "=r"(p));
    return p;
}
__device__ __forceinline__ void mbar_init(uint32_t addr, uint32_t cnt) {
    asm volatile("mbarrier.init.shared.b64 [%0], %1;" :: "r"(addr), "r"(cnt) : "memory");
}
__device__ __forceinline__ void mbar_wait(uint32_t mbar, uint32_t parity) {
    asm volatile(
        "{\n\t.reg .pred P;\n\t"
        "W_%=:\n\t"
        "mbarrier.try_wait.parity.acquire.cta.shared::cta.b64 P, [%0], %1, 0x989680;\n\t"
        "@P bra.uni D_%=;\n\t"
        "bra.uni W_%=;\n\t"
        "D_%=:\n\t}"
        :: "r"(mbar), "r"(parity) : "memory");
}
__device__ __forceinline__ void mbar_arrive(uint32_t mbar) {
    asm volatile("mbarrier.arrive.shared.b64 _, [%0];" :: "r"(mbar) : "memory");
}
__device__ __forceinline__ void mbar_expect_tx(uint32_t mbar, uint32_t bytes) {
    asm volatile("mbarrier.arrive.expect_tx.shared.b64 _, [%0], %1;"
                 :: "r"(mbar), "r"(bytes) : "memory");
}
__device__ __forceinline__ void bulk_g2s(uint32_t dst, const void* src, uint32_t bytes,
                                         uint32_t mbar) {
    asm volatile(
        "cp.async.bulk.shared::cluster.global.mbarrier::complete_tx::bytes [%0], [%1], %2, [%3];"
        :: "r"(dst), "l"(src), "r"(bytes), "r"(mbar) : "memory");
}

#if HAS_TCGEN05
__device__ __forceinline__ void tmem_alloc(uint32_t smem_addr, uint32_t ncols) {
    asm volatile("tcgen05.alloc.cta_group::1.sync.aligned.shared::cta.b32 [%0], %1;"
                 :: "r"(smem_addr), "r"(ncols) : "memory");
}
__device__ __forceinline__ void tmem_dealloc(uint32_t tmem, uint32_t ncols) {
    asm volatile("tcgen05.dealloc.cta_group::1.sync.aligned.b32 %0, %1;" :: "r"(tmem), "r"(ncols));
}
__device__ __forceinline__ void tmem_relinquish() {
    asm volatile("tcgen05.relinquish_alloc_permit.cta_group::1.sync.aligned;");
}
__device__ __forceinline__ void mma_commit(uint32_t mbar) {
    asm volatile("tcgen05.commit.cta_group::1.mbarrier::arrive::one.shared::cluster.b64 [%0];"
                 :: "r"(mbar) : "memory");
}
__device__ __forceinline__ void tc_fence_after() {
    asm volatile("tcgen05.fence::after_thread_sync;" ::: "memory");
}
__device__ __forceinline__ void tc_wait_ld() {
    asm volatile("tcgen05.wait::ld.sync.aligned;" ::: "memory");
}
__device__ __forceinline__ uint64_t mk_desc(uint32_t addr) {
    // SW128, version=1, SBO=64, LBO=1 (K-major, 128B rows)
    return (2ULL << 61) | (1ULL << 46) | (64ULL << 32) | (1ULL << 16) |
           ((uint64_t)(addr >> 4) & 0x3FFF);
}
__device__ __forceinline__ void mma_bf16_ss(uint32_t d, uint64_t da, uint64_t db,
                                            uint32_t idesc, uint32_t acc) {
    asm volatile(
        "{\n\t.reg .pred p;\n\t"
        "setp.ne.u32 p, %4, 0;\n\t"
        "tcgen05.mma.cta_group::1.kind::f16 [%0], %1, %2, %3, {%5, %5, %5, %5}, p;\n\t}"
        :: "r"(d), "l"(da), "l"(db), "r"(idesc), "r"(acc), "r"(0u) : "memory");
}
__device__ __forceinline__ void ldtm32(uint32_t* r, uint32_t a) {
    asm volatile(
        "tcgen05.ld.sync.aligned.32x32b.x32.b32 "
        "{%0,%1,%2,%3,%4,%5,%6,%7,%8,%9,%10,%11,%12,%13,%14,%15,"
        "%16,%17,%18,%19,%20,%21,%22,%23,%24,%25,%26,%27,%28,%29,%30,%31}, [%32];"
        : "=r"(r[0]), "=r"(r[1]), "=r"(r[2]), "=r"(r[3]), "=r"(r[4]), "=r"(r[5]), "=r"(r[6]), "=r"(r[7]),
          "=r"(r[8]), "=r"(r[9]), "=r"(r[10]), "=r"(r[11]), "=r"(r[12]), "=r"(r[13]), "=r"(r[14]), "=r"(r[15]),
          "=r"(r[16]), "=r"(r[17]), "=r"(r[18]), "=r"(r[19]), "=r"(r[20]), "=r"(r[21]), "=r"(r[22]), "=r"(r[23]),
          "=r"(r[24]), "=r"(r[25]), "=r"(r[26]), "=r"(r[27]), "=r"(r[28]), "=r"(r[29]), "=r"(r[30]), "=r"(r[31])
        : "r"(a));
}
#endif // HAS_TCGEN05

// idesc: F32 accum, BF16 a/b, M=128, N=128
#define GEMM_IDESC ((1u << 4) | (1u << 7) | (1u << 10) | (16u << 17) | (8u << 24))

// ---------------------------------------------------------------------------
// k_sq
// ---------------------------------------------------------------------------
__global__ __launch_bounds__(256) void ksq_kernel(const float* __restrict__ K) {
    int gw = (blockIdx.x * blockDim.x + threadIdx.x) >> 5;
    int lane = threadIdx.x & 31;
    if (gw >= NB * SK) return;
    const float* row = K + (size_t)gw * DH;
    float s = 0.f;
    #pragma unroll
    for (int i = lane * 4; i < DH; i += 128) {
        float4 v = *(const float4*)(row + i);
        s = fmaf(v.x, v.x, s); s = fmaf(v.y, v.y, s);
        s = fmaf(v.z, v.z, s); s = fmaf(v.w, v.w, s);
    }
    #pragma unroll
    for (int o = 16; o > 0; o >>= 1) s += __shfl_xor_sync(0xffffffffu, s, o);
    if (lane == 0) g_ksq[gw] = s;
}

// ---------------------------------------------------------------------------
__device__ __forceinline__ void split8(const float* v, uint32_t* hi, uint32_t* lo) {
    #pragma unroll
    for (int p = 0; p < 4; p++) {
        __nv_bfloat162 h(__float2bfloat16(v[2 * p]), __float2bfloat16(v[2 * p + 1]));
        __nv_bfloat162 l(__float2bfloat16(v[2 * p] - __bfloat162float(h.x)),
                         __float2bfloat16(v[2 * p + 1] - __bfloat162float(h.y)));
        hi[p] = *(uint32_t*)&h;
        lo[p] = *(uint32_t*)&l;
    }
}

// ---------------------------------------------------------------------------
// Q/K split into chunked swizzled hi/lo layout.
// ---------------------------------------------------------------------------
__global__ __launch_bounds__(256) void splitqk_kernel(const float* __restrict__ X,
                                                      char* __restrict__ dst, int kst) {
    const int kdim = kst * 64;
    const int tpr = kst * 8;
    int idx = blockIdx.x * 256 + threadIdx.x;
    int mg = idx / tpr;
    int k0 = (idx % tpr) * 8;
    int b = mg >> 11, m = mg & 2047;
    int mtile = m >> 7, row = m & 127;
    int kstage = k0 >> 6, colc = k0 & 63;

    float v[8];
    const float* src = X + (size_t)mg * kdim + k0;
    *(float4*)(v) = *(const float4*)(src);
    *(float4*)(v + 4) = *(const float4*)(src + 4);
    uint32_t hi[4], lo[4];
    split8(v, hi, lo);

    size_t base = (size_t)((b * 16 + mtile) * kst + kstage) * CHUNK_B;
    uint32_t off = row * 128 + colc * 2;
    off ^= (off >> 3) & 0x70;
    *(uint4*)(dst + base + off) = make_uint4(hi[0], hi[1], hi[2], hi[3]);
    *(uint4*)(dst + base + 16384 + off) = make_uint4(lo[0], lo[1], lo[2], lo[3]);
}

// ---------------------------------------------------------------------------
// V transpose + split into chunked layout: row=d, col=k. KST=32, NTILES=4.
// ---------------------------------------------------------------------------
__global__ __launch_bounds__(256) void vsplit_kernel(const float* __restrict__ V) {
    __shared__ float t[32][33];
    const int b = blockIdx.z;
    const int d0 = blockIdx.x * 32, k0 = blockIdx.y * 32;
    const float* Vb = V + (size_t)b * SK * DH;
    const int tid = threadIdx.x;
    #pragma unroll
    for (int i = 0; i < 4; i++) {
        int kk = (tid >> 5) + i * 8, dd = tid & 31;
        t[kk][dd] = Vb[(size_t)(k0 + kk) * DH + d0 + dd];
    }
    __syncthreads();
    int d_local = tid >> 3, k_local = (tid & 7) * 4;
    float v[4];
    #pragma unroll
    for (int i = 0; i < 4; i++) v[i] = t[k_local + i][d_local];
    uint32_t hi[2], lo[2];
    #pragma unroll
    for (int p = 0; p < 2; p++) {
        __nv_bfloat162 h(__float2bfloat16(v[2 * p]), __float2bfloat16(v[2 * p + 1]));
        __nv_bfloat162 l(__float2bfloat16(v[2 * p] - __bfloat162float(h.x)),
                         __float2bfloat16(v[2 * p + 1] - __bfloat162float(h.y)));
        hi[p] = *(uint32_t*)&h;
        lo[p] = *(uint32_t*)&l;
    }
    int d = d0 + d_local, k = k0 + k_local;
    int ntile = d >> 7, row = d & 127, kstage = k >> 6, colc = k & 63;
    size_t base = (size_t)((b * 4 + ntile) * 32 + kstage) * CHUNK_B;
    uint32_t off = row * 128 + colc * 2;
    off ^= (off >> 3) & 0x70;
    *(uint2*)(g_Vs + base + off) = make_uint2(hi[0], hi[1]);
    *(uint2*)(g_Vs + base + 16384 + off) = make_uint2(lo[0], lo[1]);
}

// ---------------------------------------------------------------------------
// Persistent GEMM: each CTA does TPT consecutive tiles with double-buffered
// TMEM; producer warp (1) bulk-loads, MMA warp (0) issues, warps 4-7 drain
// the previous tile's accumulator concurrently.
// ---------------------------------------------------------------------------
template <int MT, int NT, int KST, bool IS_QK>
__global__ __launch_bounds__(256, 1) void gemm5_kernel(
    const char* __restrict__ Achunks, const char* __restrict__ Bchunks,
    float* __restrict__ Out, const float* __restrict__ temp) {
    extern __shared__ __align__(1024) char smem[];
    constexpr int LDOUT = NT * 128;
    constexpr int TILES_PER_B = MT * NT;

    const int tid = threadIdx.x;
    const int wid = tid >> 5, lid = tid & 31;
    const int tile0 = blockIdx.x * TPT;

#if HAS_TCGEN05
    const uint32_t sbase = smem_u32(smem);
    // mbars: full[3]@+8..24, empty[3]@+32..48, done[2]@+56..64, efree[2]@+72..80
    if (wid == 0) {
        tmem_alloc(sbase, 256);
        tmem_relinquish();
    }
    if (tid == 0) {
        #pragma unroll
        for (int i = 0; i < 3; i++) {
            mbar_init(sbase + 8 + i * 8, 1);
            mbar_init(sbase + 32 + i * 8, 1);
        }
        mbar_init(sbase + 56, 1);
        mbar_init(sbase + 64, 1);
        mbar_init(sbase + 72, 4);
        mbar_init(sbase + 80, 4);
    }
    __syncthreads();
    uint32_t tmem;
    asm volatile("ld.shared.b32 %0, [%1];" : "=r"(tmem) : "r"(sbase));

    if (wid == 1 && elect1()) {
        // ---------------- producer: continuous bulk-load ring ----------------
        for (int gs = 0; gs < TPT * KST; gs++) {
            const int t = gs / KST, s = gs % KST;
            const int T = tile0 + t;
            const int b = T / TILES_PER_B, rem = T % TILES_PER_B;
            const int my = rem / NT, nx = rem % NT;
            const int buf = gs % NBUF;
            if (gs >= NBUF) mbar_wait(sbase + 32 + buf * 8, ((gs - NBUF) / NBUF) & 1);
            uint32_t fm = sbase + 8 + buf * 8;
            uint32_t dst = sbase + SMEM_TILES + buf * 2 * CHUNK_B;
            mbar_expect_tx(fm, 2 * CHUNK_B);
            bulk_g2s(dst, Achunks + (size_t)((b * MT + my) * KST + s) * CHUNK_B, CHUNK_B, fm);
            bulk_g2s(dst + CHUNK_B, Bchunks + (size_t)((b * NT + nx) * KST + s) * CHUNK_B,
                     CHUNK_B, fm);
        }
    } else if (wid == 0 && elect1()) {
        // ---------------- MMA issuer ----------------
        for (int t = 0; t < TPT; t++) {
            const uint32_t dbuf = tmem + (t & 1) * 128;
            if (t >= 2) {
                mbar_wait(sbase + 72 + (t & 1) * 8, ((t >> 1) - 1) & 1);
                tc_fence_after();
            }
            for (int s = 0; s < KST; s++) {
                const int gs = t * KST + s;
                const int buf = gs % NBUF;
                mbar_wait(sbase + 8 + buf * 8, (gs / NBUF) & 1);
                uint32_t tb = sbase + SMEM_TILES + buf * 2 * CHUNK_B;
                uint64_t dAh = mk_desc(tb);
                uint64_t dAl = mk_desc(tb + 16384);
                uint64_t dBh = mk_desc(tb + CHUNK_B);
                uint64_t dBl = mk_desc(tb + CHUNK_B + 16384);
                #pragma unroll
                for (int ks = 0; ks < 4; ks++) {
                    uint32_t acc0 = (s == 0 && ks == 0) ? 0u : 1u;
                    mma_bf16_ss(dbuf, dAh + ks * 2, dBh + ks * 2, GEMM_IDESC, acc0);
                    mma_bf16_ss(dbuf, dAh + ks * 2, dBl + ks * 2, GEMM_IDESC, 1u);
                    mma_bf16_ss(dbuf, dAl + ks * 2, dBh + ks * 2, GEMM_IDESC, 1u);
                }
                mma_commit(sbase + 32 + buf * 8);
            }
            mma_commit(sbase + 56 + (t & 1) * 8);
        }
    } else if (wid >= 4) {
        // ---------------- epilogue warps (4..7) ----------------
        const int wsub = wid - 4;
        const float invT = IS_QK ? 1.0f / temp[0] : 1.0f;
        for (int t = 0; t < TPT; t++) {
            const int T = tile0 + t;
            const int b = T / TILES_PER_B, rem = T % TILES_PER_B;
            const int my = rem / NT, nx = rem % NT;
            const int m0 = my * 128, n0 = nx * 128;
            mbar_wait(sbase + 56 + (t & 1) * 8, (t >> 1) & 1);
            tc_fence_after();
            const uint32_t dbuf = tmem + (t & 1) * 128;
            const int m = m0 + wsub * 32 + lid;
            #pragma unroll
            for (int cb = 0; cb < 128; cb += 32) {
                uint32_t r[32];
                ldtm32(r, dbuf + cb);
                tc_wait_ld();
                float* op = Out + (size_t)b * SQ * LDOUT + (size_t)m * LDOUT + n0 + cb;
                if (IS_QK) {
                    const float* kq = g_ksq + b * SK + n0 + cb;
                    #pragma unroll
                    for (int c = 0; c < 32; c += 4) {
                        float4 o;
                        o.x = (2.f * __uint_as_float(r[c + 0]) - kq[c + 0]) * invT;
                        o.y = (2.f * __uint_as_float(r[c + 1]) - kq[c + 1]) * invT;
                        o.z = (2.f * __uint_as_float(r[c + 2]) - kq[c + 2]) * invT;
                        o.w = (2.f * __uint_as_float(r[c + 3]) - kq[c + 3]) * invT;
                        *(float4*)(op + c) = o;
                    }
                } else {
                    #pragma unroll
                    for (int c = 0; c < 32; c += 4) {
                        float4 o;
                        o.x = __uint_as_float(r[c + 0]);
                        o.y = __uint_as_float(r[c + 1]);
                        o.z = __uint_as_float(r[c + 2]);
                        o.w = __uint_as_float(r[c + 3]);
                        *(float4*)(op + c) = o;
                    }
                }
            }
            if (elect1()) mbar_arrive(sbase + 72 + (t & 1) * 8);
        }
    }

    __syncthreads();
    if (wid == 0) tmem_dealloc(tmem, 256);

#else  // ---------------- naive correct fallback (plain sm_103 pass; unused) ----
    const float invT = IS_QK ? 1.f / temp[0] : 1.f;
    for (int t = 0; t < TPT; t++) {
        const int T = tile0 + t;
        const int b = T / TILES_PER_B, rem = T % TILES_PER_B;
        const int my = rem / NT, nx = rem % NT;
        const int m0 = my * 128, n0 = nx * 128;
        const char* ca0 = Achunks + (size_t)(b * MT + my) * KST * CHUNK_B;
        const char* cb0 = Bchunks + (size_t)(b * NT + nx) * KST * CHUNK_B;
        for (int e = tid; e < 128 * 128; e += 256) {
            int i = e >> 7, j = e & 127;
            float acc = 0.f;
            for (int s = 0; s < KST; s++) {
                const char* ca = ca0 + (size_t)s * CHUNK_B;
                const char* cb = cb0 + (size_t)s * CHUNK_B;
                for (int k = 0; k < 64; k++) {
                    uint32_t oa = i * 128 + k * 2; oa ^= (oa >> 3) & 0x70;
                    uint32_t ob = j * 128 + k * 2; ob ^= (ob >> 3) & 0x70;
                    float a = __bfloat162float(*(const __nv_bfloat16*)(ca + oa)) +
                              __bfloat162float(*(const __nv_bfloat16*)(ca + 16384 + oa));
                    float bb = __bfloat162float(*(const __nv_bfloat16*)(cb + ob)) +
                               __bfloat162float(*(const __nv_bfloat16*)(cb + 16384 + ob));
                    acc = fmaf(a, bb, acc);
                }
            }
            float* op = Out + (size_t)b * SQ * LDOUT + (size_t)(m0 + i) * LDOUT + n0 + j;
            *op = IS_QK ? (2.f * acc - g_ksq[b * SK + n0 + j]) * invT : acc;
        }
        __syncthreads();
    }
#endif
}

// ---------------------------------------------------------------------------
// softmax (in-place fp32) + write hi/lo chunked W tiles for PV
// ---------------------------------------------------------------------------
__global__ __launch_bounds__(256) void softmax_kernel(float* __restrict__ W) {
    const int rowg = blockIdx.x;
    float* r = W + (size_t)rowg * SK;
    const int tid = threadIdx.x;

    float vals[8];
    *(float4*)(vals) = *(const float4*)(r + tid * 8);
    *(float4*)(vals + 4) = *(const float4*)(r + tid * 8 + 4);
    float m = vals[0];
    #pragma unroll
    for (int i = 1; i < 8; i++) m = fmaxf(m, vals[i]);

    __shared__ float red[8];
    #pragma unroll
    for (int o = 16; o > 0; o >>= 1) m = fmaxf(m, __shfl_xor_sync(0xffffffffu, m, o));
    if ((tid & 31) == 0) red[tid >> 5] = m;
    __syncthreads();
    m = red[0];
    #pragma unroll
    for (int w = 1; w < 8; w++) m = fmaxf(m, red[w]);
    __syncthreads();

    float s = 0.f;
    #pragma unroll
    for (int i = 0; i < 8; i++) {
        vals[i] = __expf(vals[i] - m);
        s += vals[i];
    }
    #pragma unroll
    for (int o = 16; o > 0; o >>= 1) s += __shfl_xor_sync(0xffffffffu, s, o);
    if ((tid & 31) == 0) red[tid >> 5] = s;
    __syncthreads();
    s = red[0];
    #pragma unroll
    for (int w = 1; w < 8; w++) s += red[w];

    const float inv = 1.0f / s;
    #pragma unroll
    for (int i = 0; i < 8; i++) vals[i] *= inv;
    *(float4*)(r + tid * 8) = *(float4*)(vals);
    *(float4*)(r + tid * 8 + 4) = *(float4*)(vals + 4);

    uint32_t hi[4], lo[4];
    split8(vals, hi, lo);
    const int b = rowg >> 11, q = rowg & 2047;
    const int mtile = q >> 7, row = q & 127;
    const int kstage = tid >> 3, colc = (tid * 8) & 63;
    size_t base = (size_t)((b * 16 + mtile) * 32 + kstage) * CHUNK_B;
    uint32_t off = row * 128 + colc * 2;
    off ^= (off >> 3) & 0x70;
    *(uint4*)(g_Ws + base + off) = make_uint4(hi[0], hi[1], hi[2], hi[3]);
    *(uint4*)(g_Ws + base + 16384 + off) = make_uint4(lo[0], lo[1], lo[2], lo[3]);
}

// ---------------------------------------------------------------------------
extern "C" void kernel_launch(void* const* d_in, const int* in_sizes, int n_in,
                              void* d_out, int out_size) {
    const float* Q = (const float*)d_in[0];
    const float* K = (const float*)d_in[1];
    const float* V = (const float*)d_in[2];
    const float* T = (const float*)d_in[3];

    float* attended = (float*)d_out;                        // [B,SQ,DH]
    float* weights  = (float*)d_out + (size_t)NB * SQ * DH; // [B,SQ,SK]

    void *qs, *ks, *vs, *ws;
    cudaGetSymbolAddress(&qs, g_Qs);
    cudaGetSymbolAddress(&ks, g_Ks);
    cudaGetSymbolAddress(&vs, g_Vs);
    cudaGetSymbolAddress(&ws, g_Ws);

    cudaFuncSetAttribute((const void*)gemm5_kernel<16, 16, 8, true>,
                         cudaFuncAttributeMaxDynamicSharedMemorySize, SMEM_TOTAL);
    cudaFuncSetAttribute((const void*)gemm5_kernel<16, 4, 32, false>,
                         cudaFuncAttributeMaxDynamicSharedMemorySize, SMEM_TOTAL);

    // 1) prep
    ksq_kernel<<<NB * SK * 32 / 256, 256>>>(K);
    splitqk_kernel<<<NB * SQ * 64 / 256, 256>>>(Q, (char*)qs, 8);
    splitqk_kernel<<<NB * SK * 64 / 256, 256>>>(K, (char*)ks, 8);
    vsplit_kernel<<<dim3(DH / 32, SK / 32, NB), 256>>>(V);

    // 2) logits = (2 q.k - ksq)/T  (2048 tiles / TPT)
    gemm5_kernel<16, 16, 8, true><<<NB * 16 * 16 / TPT, 256, SMEM_TOTAL>>>(
        (const char*)qs, (const char*)ks, weights, T);

    // 3) softmax in-place + chunked hi/lo W
    softmax_kernel<<<NB * SQ, 256>>>(weights);

    // 4) attended = W @ V  (512 tiles / TPT)
    gemm5_kernel<16, 4, 32, false><<<NB * 16 * 4 / TPT, 256, SMEM_TOTAL>>>(
        (const char*)ws, (const char*)vs, attended, nullptr);
}

// round 7
// speedup vs baseline: 1.5716x; 1.0437x over previous
#include <cuda_runtime.h>
#include <cuda_bf16.h>
#include <cstdint>

#define NB 8
#define SQ 2048
#define SK 2048
#define DH 512

#define CHUNK_B 32768          // one 128x64 tile pair: [hi 16KB][lo 16KB]
#define NBUF 2
#define STAGE_B (3 * CHUNK_B)  // A chunk + two B chunks = 96KB
#define SMEM_TILES 1024
#define SMEM_TOTAL (SMEM_TILES + NBUF * STAGE_B)  // 197632 bytes

// tcgen05 is arch-accelerated ('a'): only emit in sm_10xa passes.
#if defined(__CUDA_ARCH_FEAT_SM103_ALL) || defined(__CUDA_ARCH_FEAT_SM100_ALL) || \
    defined(__CUDA_ARCH_FEAT_SM101_ALL) ||                                        \
    (defined(__CUDA_ARCH_SPECIFIC__) && (__CUDA_ARCH_SPECIFIC__ >= 1000)) ||      \
    (defined(__CUDA_ARCH_FAMILY_SPECIFIC__) && (__CUDA_ARCH_FAMILY_SPECIFIC__ >= 1000))
#define HAS_TCGEN05 1
#else
#define HAS_TCGEN05 0
#endif

// ------------------------- device scratch (chunked tile layouts) -----------
__device__ float g_ksq[NB * SK];
__device__ __align__(128) char g_Qs[(size_t)NB * 16 * 8 * CHUNK_B];   // 33.5MB
__device__ __align__(128) char g_Ks[(size_t)NB * 16 * 8 * CHUNK_B];   // 33.5MB
__device__ __align__(128) char g_Vs[(size_t)NB * 4 * 32 * CHUNK_B];   // 33.5MB
__device__ __align__(128) char g_Ws[(size_t)NB * 16 * 32 * CHUNK_B];  // 134MB

// ------------------------- ptx helpers -------------------------
__device__ __forceinline__ uint32_t smem_u32(const void* p) {
    uint32_t a;
    asm("{ .reg .u64 t; cvta.to.shared.u64 t, %1; cvt.u32.u64 %0, t; }" : "=r"(a) : "l"(p));
    return a;
}
__device__ __forceinline__ uint32_t elect1() {
    uint32_t p;
    asm volatile("{\n\t.reg .pred p;\n\telect.sync _|p, 0xFFFFFFFF;\n\tselp.b32 %0,1,0,p;\n\t}" : "=r"(p));
    return p;
}
__device__ __forceinline__ void mbar_init(uint32_t addr, uint32_t cnt) {
    asm volatile("mbarrier.init.shared.b64 [%0], %1;" :: "r"(addr), "r"(cnt) : "memory");
}
__device__ __forceinline__ void mbar_wait(uint32_t mbar, uint32_t parity) {
    asm volatile(
        "{\n\t.reg .pred P;\n\t"
        "W_%=:\n\t"
        "mbarrier.try_wait.parity.acquire.cta.shared::cta.b64 P, [%0], %1, 0x989680;\n\t"
        "@P bra.uni D_%=;\n\t"
        "bra.uni W_%=;\n\t"
        "D_%=:\n\t}"
        :: "r"(mbar), "r"(parity) : "memory");
}
__device__ __forceinline__ void mbar_arrive(uint32_t mbar) {
    asm volatile("mbarrier.arrive.shared.b64 _, [%0];" :: "r"(mbar) : "memory");
}
__device__ __forceinline__ void mbar_expect_tx(uint32_t mbar, uint32_t bytes) {
    asm volatile("mbarrier.arrive.expect_tx.shared.b64 _, [%0], %1;"
                 :: "r"(mbar), "r"(bytes) : "memory");
}
__device__ __forceinline__ void bulk_g2s(uint32_t dst, const void* src, uint32_t bytes,
                                         uint32_t mbar) {
    asm volatile(
        "cp.async.bulk.shared::cluster.global.mbarrier::complete_tx::bytes [%0], [%1], %2, [%3];"
        :: "r"(dst), "l"(src), "r"(bytes), "r"(mbar) : "memory");
}

#if HAS_TCGEN05
__device__ __forceinline__ void tmem_alloc(uint32_t smem_addr, uint32_t ncols) {
    asm volatile("tcgen05.alloc.cta_group::1.sync.aligned.shared::cta.b32 [%0], %1;"
                 :: "r"(smem_addr), "r"(ncols) : "memory");
}
__device__ __forceinline__ void tmem_dealloc(uint32_t tmem, uint32_t ncols) {
    asm volatile("tcgen05.dealloc.cta_group::1.sync.aligned.b32 %0, %1;" :: "r"(tmem), "r"(ncols));
}
__device__ __forceinline__ void tmem_relinquish() {
    asm volatile("tcgen05.relinquish_alloc_permit.cta_group::1.sync.aligned;");
}
__device__ __forceinline__ void mma_commit(uint32_t mbar) {
    asm volatile("tcgen05.commit.cta_group::1.mbarrier::arrive::one.shared::cluster.b64 [%0];"
                 :: "r"(mbar) : "memory");
}
__device__ __forceinline__ void tc_fence_after() {
    asm volatile("tcgen05.fence::after_thread_sync;" ::: "memory");
}
__device__ __forceinline__ void tc_wait_ld() {
    asm volatile("tcgen05.wait::ld.sync.aligned;" ::: "memory");
}
__device__ __forceinline__ uint64_t mk_desc(uint32_t addr) {
    // SW128, version=1, SBO=64, LBO=1 (K-major, 128B rows)
    return (2ULL << 61) | (1ULL << 46) | (64ULL << 32) | (1ULL << 16) |
           ((uint64_t)(addr >> 4) & 0x3FFF);
}
__device__ __forceinline__ void mma_bf16_ss(uint32_t d, uint64_t da, uint64_t db,
                                            uint32_t idesc, uint32_t acc) {
    asm volatile(
        "{\n\t.reg .pred p;\n\t"
        "setp.ne.u32 p, %4, 0;\n\t"
        "tcgen05.mma.cta_group::1.kind::f16 [%0], %1, %2, %3, {%5, %5, %5, %5}, p;\n\t}"
        :: "r"(d), "l"(da), "l"(db), "r"(idesc), "r"(acc), "r"(0u) : "memory");
}
__device__ __forceinline__ void ldtm32(uint32_t* r, uint32_t a) {
    asm volatile(
        "tcgen05.ld.sync.aligned.32x32b.x32.b32 "
        "{%0,%1,%2,%3,%4,%5,%6,%7,%8,%9,%10,%11,%12,%13,%14,%15,"
        "%16,%17,%18,%19,%20,%21,%22,%23,%24,%25,%26,%27,%28,%29,%30,%31}, [%32];"
        : "=r"(r[0]), "=r"(r[1]), "=r"(r[2]), "=r"(r[3]), "=r"(r[4]), "=r"(r[5]), "=r"(r[6]), "=r"(r[7]),
          "=r"(r[8]), "=r"(r[9]), "=r"(r[10]), "=r"(r[11]), "=r"(r[12]), "=r"(r[13]), "=r"(r[14]), "=r"(r[15]),
          "=r"(r[16]), "=r"(r[17]), "=r"(r[18]), "=r"(r[19]), "=r"(r[20]), "=r"(r[21]), "=r"(r[22]), "=r"(r[23]),
          "=r"(r[24]), "=r"(r[25]), "=r"(r[26]), "=r"(r[27]), "=r"(r[28]), "=r"(r[29]), "=r"(r[30]), "=r"(r[31])
        : "r"(a));
}
#endif // HAS_TCGEN05

// idesc: F32 accum, BF16 a/b, M=128, N=128
#define GEMM_IDESC ((1u << 4) | (1u << 7) | (1u << 10) | (16u << 17) | (8u << 24))

// ---------------------------------------------------------------------------
// k_sq
// ---------------------------------------------------------------------------
__global__ __launch_bounds__(256) void ksq_kernel(const float* __restrict__ K) {
    int gw = (blockIdx.x * blockDim.x + threadIdx.x) >> 5;
    int lane = threadIdx.x & 31;
    if (gw >= NB * SK) return;
    const float* row = K + (size_t)gw * DH;
    float s = 0.f;
    #pragma unroll
    for (int i = lane * 4; i < DH; i += 128) {
        float4 v = *(const float4*)(row + i);
        s = fmaf(v.x, v.x, s); s = fmaf(v.y, v.y, s);
        s = fmaf(v.z, v.z, s); s = fmaf(v.w, v.w, s);
    }
    #pragma unroll
    for (int o = 16; o > 0; o >>= 1) s += __shfl_xor_sync(0xffffffffu, s, o);
    if (lane == 0) g_ksq[gw] = s;
}

// ---------------------------------------------------------------------------
__device__ __forceinline__ void split8(const float* v, uint32_t* hi, uint32_t* lo) {
    #pragma unroll
    for (int p = 0; p < 4; p++) {
        __nv_bfloat162 h(__float2bfloat16(v[2 * p]), __float2bfloat16(v[2 * p + 1]));
        __nv_bfloat162 l(__float2bfloat16(v[2 * p] - __bfloat162float(h.x)),
                         __float2bfloat16(v[2 * p + 1] - __bfloat162float(h.y)));
        hi[p] = *(uint32_t*)&h;
        lo[p] = *(uint32_t*)&l;
    }
}

// ---------------------------------------------------------------------------
// Q/K split into chunked swizzled hi/lo layout.
// ---------------------------------------------------------------------------
__global__ __launch_bounds__(256) void splitqk_kernel(const float* __restrict__ X,
                                                      char* __restrict__ dst, int kst) {
    const int kdim = kst * 64;
    const int tpr = kst * 8;
    int idx = blockIdx.x * 256 + threadIdx.x;
    int mg = idx / tpr;
    int k0 = (idx % tpr) * 8;
    int b = mg >> 11, m = mg & 2047;
    int mtile = m >> 7, row = m & 127;
    int kstage = k0 >> 6, colc = k0 & 63;

    float v[8];
    const float* src = X + (size_t)mg * kdim + k0;
    *(float4*)(v) = *(const float4*)(src);
    *(float4*)(v + 4) = *(const float4*)(src + 4);
    uint32_t hi[4], lo[4];
    split8(v, hi, lo);

    size_t base = (size_t)((b * 16 + mtile) * kst + kstage) * CHUNK_B;
    uint32_t off = row * 128 + colc * 2;
    off ^= (off >> 3) & 0x70;
    *(uint4*)(dst + base + off) = make_uint4(hi[0], hi[1], hi[2], hi[3]);
    *(uint4*)(dst + base + 16384 + off) = make_uint4(lo[0], lo[1], lo[2], lo[3]);
}

// ---------------------------------------------------------------------------
// V transpose + split into chunked layout: row=d, col=k. KST=32, NTILES=4.
// ---------------------------------------------------------------------------
__global__ __launch_bounds__(256) void vsplit_kernel(const float* __restrict__ V) {
    __shared__ float t[32][33];
    const int b = blockIdx.z;
    const int d0 = blockIdx.x * 32, k0 = blockIdx.y * 32;
    const float* Vb = V + (size_t)b * SK * DH;
    const int tid = threadIdx.x;
    #pragma unroll
    for (int i = 0; i < 4; i++) {
        int kk = (tid >> 5) + i * 8, dd = tid & 31;
        t[kk][dd] = Vb[(size_t)(k0 + kk) * DH + d0 + dd];
    }
    __syncthreads();
    int d_local = tid >> 3, k_local = (tid & 7) * 4;
    float v[4];
    #pragma unroll
    for (int i = 0; i < 4; i++) v[i] = t[k_local + i][d_local];
    uint32_t hi[2], lo[2];
    #pragma unroll
    for (int p = 0; p < 2; p++) {
        __nv_bfloat162 h(__float2bfloat16(v[2 * p]), __float2bfloat16(v[2 * p + 1]));
        __nv_bfloat162 l(__float2bfloat16(v[2 * p] - __bfloat162float(h.x)),
                         __float2bfloat16(v[2 * p + 1] - __bfloat162float(h.y)));
        hi[p] = *(uint32_t*)&h;
        lo[p] = *(uint32_t*)&l;
    }
    int d = d0 + d_local, k = k0 + k_local;
    int ntile = d >> 7, row = d & 127, kstage = k >> 6, colc = k & 63;
    size_t base = (size_t)((b * 4 + ntile) * 32 + kstage) * CHUNK_B;
    uint32_t off = row * 128 + colc * 2;
    off ^= (off >> 3) & 0x70;
    *(uint2*)(g_Vs + base + off) = make_uint2(hi[0], hi[1]);
    *(uint2*)(g_Vs + base + 16384 + off) = make_uint2(lo[0], lo[1]);
}

// ---------------------------------------------------------------------------
// Persistent GEMM with 128x256 tiles. Producer warp (1) bulk-loads
// A(32KB)+B0+B1(64KB) per stage; MMA warp (0) issues 2x(3 MMAs)/K-step into
// the two TMEM D-halves; warps 4-7 drain the previous tile concurrently.
// Tiles per CTA = TPT_, N-256-tiles per batch = NXT2.
// ---------------------------------------------------------------------------
template <int MT, int NXT2, int KST, int TPT_, bool IS_QK>
__global__ __launch_bounds__(256, 1) void gemm5_kernel(
    const char* __restrict__ Achunks, const char* __restrict__ Bchunks,
    float* __restrict__ Out, const float* __restrict__ temp) {
    extern __shared__ __align__(1024) char smem[];
    constexpr int LDOUT = NXT2 * 256;
    constexpr int TILES_PER_B = MT * NXT2;

    const int tid = threadIdx.x;
    const int wid = tid >> 5, lid = tid & 31;
    const int tile0 = blockIdx.x * TPT_;

#if HAS_TCGEN05
    const uint32_t sbase = smem_u32(smem);
    // mbars: full[2]@+8,16  empty[2]@+32,40  done[2]@+56,64  efree[2]@+72,80
    if (wid == 0) {
        tmem_alloc(sbase, 512);
        tmem_relinquish();
    }
    if (tid == 0) {
        #pragma unroll
        for (int i = 0; i < NBUF; i++) {
            mbar_init(sbase + 8 + i * 8, 1);
            mbar_init(sbase + 32 + i * 8, 1);
        }
        mbar_init(sbase + 56, 1);
        mbar_init(sbase + 64, 1);
        mbar_init(sbase + 72, 4);
        mbar_init(sbase + 80, 4);
    }
    __syncthreads();
    uint32_t tmem;
    asm volatile("ld.shared.b32 %0, [%1];" : "=r"(tmem) : "r"(sbase));

    if (wid == 1 && elect1()) {
        // ---------------- producer ----------------
        for (int gs = 0; gs < TPT_ * KST; gs++) {
            const int t = gs / KST, s = gs % KST;
            const int T = tile0 + t;
            const int b = T / TILES_PER_B, rem = T % TILES_PER_B;
            const int my = rem / NXT2, nx2 = rem % NXT2;
            const int buf = gs % NBUF;
            if (gs >= NBUF) mbar_wait(sbase + 32 + buf * 8, ((gs - NBUF) / NBUF) & 1);
            uint32_t fm = sbase + 8 + buf * 8;
            uint32_t dst = sbase + SMEM_TILES + buf * STAGE_B;
            mbar_expect_tx(fm, STAGE_B);
            bulk_g2s(dst, Achunks + (size_t)((b * MT + my) * KST + s) * CHUNK_B, CHUNK_B, fm);
            bulk_g2s(dst + CHUNK_B,
                     Bchunks + (size_t)((b * NXT2 * 2 + nx2 * 2) * KST + s) * CHUNK_B,
                     CHUNK_B, fm);
            bulk_g2s(dst + 2 * CHUNK_B,
                     Bchunks + (size_t)((b * NXT2 * 2 + nx2 * 2 + 1) * KST + s) * CHUNK_B,
                     CHUNK_B, fm);
        }
    } else if (wid == 0 && elect1()) {
        // ---------------- MMA issuer ----------------
        for (int t = 0; t < TPT_; t++) {
            const uint32_t dbuf = tmem + (t & 1) * 256;
            if (t >= 2) {
                mbar_wait(sbase + 72 + (t & 1) * 8, ((t >> 1) - 1) & 1);
                tc_fence_after();
            }
            for (int s = 0; s < KST; s++) {
                const int gs = t * KST + s;
                const int buf = gs % NBUF;
                mbar_wait(sbase + 8 + buf * 8, (gs / NBUF) & 1);
                uint32_t tb = sbase + SMEM_TILES + buf * STAGE_B;
                uint64_t dAh = mk_desc(tb);
                uint64_t dAl = mk_desc(tb + 16384);
                #pragma unroll
                for (int h = 0; h < 2; h++) {
                    uint64_t dBh = mk_desc(tb + (1 + h) * CHUNK_B);
                    uint64_t dBl = mk_desc(tb + (1 + h) * CHUNK_B + 16384);
                    const uint32_t dh = dbuf + h * 128;
                    #pragma unroll
                    for (int ks = 0; ks < 4; ks++) {
                        uint32_t acc0 = (s == 0 && ks == 0) ? 0u : 1u;
                        mma_bf16_ss(dh, dAh + ks * 2, dBh + ks * 2, GEMM_IDESC, acc0);
                        mma_bf16_ss(dh, dAh + ks * 2, dBl + ks * 2, GEMM_IDESC, 1u);
                        mma_bf16_ss(dh, dAl + ks * 2, dBh + ks * 2, GEMM_IDESC, 1u);
                    }
                }
                mma_commit(sbase + 32 + buf * 8);
            }
            mma_commit(sbase + 56 + (t & 1) * 8);
        }
    } else if (wid >= 4) {
        // ---------------- epilogue warps (4..7) ----------------
        const int wsub = wid - 4;
        const float invT = IS_QK ? 1.0f / temp[0] : 1.0f;
        for (int t = 0; t < TPT_; t++) {
            const int T = tile0 + t;
            const int b = T / TILES_PER_B, rem = T % TILES_PER_B;
            const int my = rem / NXT2, nx2 = rem % NXT2;
            const int m0 = my * 128, n0 = nx2 * 256;
            mbar_wait(sbase + 56 + (t & 1) * 8, (t >> 1) & 1);
            tc_fence_after();
            const uint32_t dbuf = tmem + (t & 1) * 256;
            const int m = m0 + wsub * 32 + lid;
            #pragma unroll
            for (int cb = 0; cb < 256; cb += 32) {
                uint32_t r[32];
                ldtm32(r, dbuf + cb);
                tc_wait_ld();
                float* op = Out + (size_t)b * SQ * LDOUT + (size_t)m * LDOUT + n0 + cb;
                if (IS_QK) {
                    const float* kq = g_ksq + b * SK + n0 + cb;
                    #pragma unroll
                    for (int c = 0; c < 32; c += 4) {
                        float4 o;
                        o.x = (2.f * __uint_as_float(r[c + 0]) - kq[c + 0]) * invT;
                        o.y = (2.f * __uint_as_float(r[c + 1]) - kq[c + 1]) * invT;
                        o.z = (2.f * __uint_as_float(r[c + 2]) - kq[c + 2]) * invT;
                        o.w = (2.f * __uint_as_float(r[c + 3]) - kq[c + 3]) * invT;
                        *(float4*)(op + c) = o;
                    }
                } else {
                    #pragma unroll
                    for (int c = 0; c < 32; c += 4) {
                        float4 o;
                        o.x = __uint_as_float(r[c + 0]);
                        o.y = __uint_as_float(r[c + 1]);
                        o.z = __uint_as_float(r[c + 2]);
                        o.w = __uint_as_float(r[c + 3]);
                        *(float4*)(op + c) = o;
                    }
                }
            }
            if (elect1()) mbar_arrive(sbase + 72 + (t & 1) * 8);
        }
    }

    __syncthreads();
    if (wid == 0) tmem_dealloc(tmem, 512);

#else  // ---------------- naive correct fallback (plain sm_103 pass; unused) ----
    const float invT = IS_QK ? 1.f / temp[0] : 1.f;
    for (int t = 0; t < TPT_; t++) {
        const int T = tile0 + t;
        const int b = T / TILES_PER_B, rem = T % TILES_PER_B;
        const int my = rem / NXT2, nx2 = rem % NXT2;
        const int m0 = my * 128, n0 = nx2 * 256;
        const char* ca0 = Achunks + (size_t)(b * MT + my) * KST * CHUNK_B;
        for (int e = tid; e < 128 * 256; e += 256) {
            int i = e >> 8, j = e & 255;
            const char* cb0 =
                Bchunks + (size_t)(b * NXT2 * 2 + nx2 * 2 + (j >> 7)) * KST * CHUNK_B;
            int jj = j & 127;
            float acc = 0.f;
            for (int s = 0; s < KST; s++) {
                const char* ca = ca0 + (size_t)s * CHUNK_B;
                const char* cb = cb0 + (size_t)s * CHUNK_B;
                for (int k = 0; k < 64; k++) {
                    uint32_t oa = i * 128 + k * 2; oa ^= (oa >> 3) & 0x70;
                    uint32_t ob = jj * 128 + k * 2; ob ^= (ob >> 3) & 0x70;
                    float a = __bfloat162float(*(const __nv_bfloat16*)(ca + oa)) +
                              __bfloat162float(*(const __nv_bfloat16*)(ca + 16384 + oa));
                    float bb = __bfloat162float(*(const __nv_bfloat16*)(cb + ob)) +
                               __bfloat162float(*(const __nv_bfloat16*)(cb + 16384 + ob));
                    acc = fmaf(a, bb, acc);
                }
            }
            float* op = Out + (size_t)b * SQ * LDOUT + (size_t)(m0 + i) * LDOUT + n0 + j;
            *op = IS_QK ? (2.f * acc - g_ksq[b * SK + n0 + j]) * invT : acc;
        }
        __syncthreads();
    }
#endif
}

// ---------------------------------------------------------------------------
// softmax (in-place fp32) + write hi/lo chunked W tiles for PV
// ---------------------------------------------------------------------------
__global__ __launch_bounds__(256) void softmax_kernel(float* __restrict__ W) {
    const int rowg = blockIdx.x;
    float* r = W + (size_t)rowg * SK;
    const int tid = threadIdx.x;

    float vals[8];
    *(float4*)(vals) = *(const float4*)(r + tid * 8);
    *(float4*)(vals + 4) = *(const float4*)(r + tid * 8 + 4);
    float m = vals[0];
    #pragma unroll
    for (int i = 1; i < 8; i++) m = fmaxf(m, vals[i]);

    __shared__ float red[8];
    #pragma unroll
    for (int o = 16; o > 0; o >>= 1) m = fmaxf(m, __shfl_xor_sync(0xffffffffu, m, o));
    if ((tid & 31) == 0) red[tid >> 5] = m;
    __syncthreads();
    m = red[0];
    #pragma unroll
    for (int w = 1; w < 8; w++) m = fmaxf(m, red[w]);
    __syncthreads();

    float s = 0.f;
    #pragma unroll
    for (int i = 0; i < 8; i++) {
        vals[i] = __expf(vals[i] - m);
        s += vals[i];
    }
    #pragma unroll
    for (int o = 16; o > 0; o >>= 1) s += __shfl_xor_sync(0xffffffffu, s, o);
    if ((tid & 31) == 0) red[tid >> 5] = s;
    __syncthreads();
    s = red[0];
    #pragma unroll
    for (int w = 1; w < 8; w++) s += red[w];

    const float inv = 1.0f / s;
    #pragma unroll
    for (int i = 0; i < 8; i++) vals[i] *= inv;
    *(float4*)(r + tid * 8) = *(float4*)(vals);
    *(float4*)(r + tid * 8 + 4) = *(float4*)(vals + 4);

    uint32_t hi[4], lo[4];
    split8(vals, hi, lo);
    const int b = rowg >> 11, q = rowg & 2047;
    const int mtile = q >> 7, row = q & 127;
    const int kstage = tid >> 3, colc = (tid * 8) & 63;
    size_t base = (size_t)((b * 16 + mtile) * 32 + kstage) * CHUNK_B;
    uint32_t off = row * 128 + colc * 2;
    off ^= (off >> 3) & 0x70;
    *(uint4*)(g_Ws + base + off) = make_uint4(hi[0], hi[1], hi[2], hi[3]);
    *(uint4*)(g_Ws + base + 16384 + off) = make_uint4(lo[0], lo[1], lo[2], lo[3]);
}

// ---------------------------------------------------------------------------
extern "C" void kernel_launch(void* const* d_in, const int* in_sizes, int n_in,
                              void* d_out, int out_size) {
    const float* Q = (const float*)d_in[0];
    const float* K = (const float*)d_in[1];
    const float* V = (const float*)d_in[2];
    const float* T = (const float*)d_in[3];

    float* attended = (float*)d_out;                        // [B,SQ,DH]
    float* weights  = (float*)d_out + (size_t)NB * SQ * DH; // [B,SQ,SK]

    void *qs, *ks, *vs, *ws;
    cudaGetSymbolAddress(&qs, g_Qs);
    cudaGetSymbolAddress(&ks, g_Ks);
    cudaGetSymbolAddress(&vs, g_Vs);
    cudaGetSymbolAddress(&ws, g_Ws);

    cudaFuncSetAttribute((const void*)gemm5_kernel<16, 8, 8, 4, true>,
                         cudaFuncAttributeMaxDynamicSharedMemorySize, SMEM_TOTAL);
    cudaFuncSetAttribute((const void*)gemm5_kernel<16, 2, 32, 2, false>,
                         cudaFuncAttributeMaxDynamicSharedMemorySize, SMEM_TOTAL);

    // 1) prep
    ksq_kernel<<<NB * SK * 32 / 256, 256>>>(K);
    splitqk_kernel<<<NB * SQ * 64 / 256, 256>>>(Q, (char*)qs, 8);
    splitqk_kernel<<<NB * SK * 64 / 256, 256>>>(K, (char*)ks, 8);
    vsplit_kernel<<<dim3(DH / 32, SK / 32, NB), 256>>>(V);

    // 2) logits = (2 q.k - ksq)/T   (8*16*8 = 1024 tiles, TPT=4 -> 256 CTAs)
    gemm5_kernel<16, 8, 8, 4, true><<<NB * 16 * 8 / 4, 256, SMEM_TOTAL>>>(
        (const char*)qs, (const char*)ks, weights, T);

    // 3) softmax in-place + chunked hi/lo W
    softmax_kernel<<<NB * SQ, 256>>>(weights);

    // 4) attended = W @ V   (8*16*2 = 256 tiles, TPT=2 -> 128 CTAs, 1 wave)
    gemm5_kernel<16, 2, 32, 2, false><<<NB * 16 * 2 / 2, 256, SMEM_TOTAL>>>(
        (const char*)ws, (const char*)vs, attended, nullptr);
}

// round 8
// speedup vs baseline: 1.6813x; 1.0698x over previous
#include <cuda_runtime.h>
#include <cuda_bf16.h>
#include <cstdint>

#define NB 8
#define SQ 2048
#define SK 2048
#define DH 512

#define CHUNK_B 32768          // one 128x64 tile pair: [hi 16KB][lo 16KB]
#define NBUF 2
#define STAGE_B (3 * CHUNK_B)  // A chunk + two B chunks = 96KB
#define SMEM_TILES 1024
#define SMEM_TOTAL (SMEM_TILES + NBUF * STAGE_B)  // 197632 bytes

// tcgen05 is arch-accelerated ('a'): only emit in sm_10xa passes.
#if defined(__CUDA_ARCH_FEAT_SM103_ALL) || defined(__CUDA_ARCH_FEAT_SM100_ALL) || \
    defined(__CUDA_ARCH_FEAT_SM101_ALL) ||                                        \
    (defined(__CUDA_ARCH_SPECIFIC__) && (__CUDA_ARCH_SPECIFIC__ >= 1000)) ||      \
    (defined(__CUDA_ARCH_FAMILY_SPECIFIC__) && (__CUDA_ARCH_FAMILY_SPECIFIC__ >= 1000))
#define HAS_TCGEN05 1
#else
#define HAS_TCGEN05 0
#endif

// ------------------------- device scratch (chunked tile layouts) -----------
__device__ float g_ksq[NB * SK];
__device__ __align__(128) char g_Qs[(size_t)NB * 16 * 8 * CHUNK_B];   // 33.5MB
__device__ __align__(128) char g_Ks[(size_t)NB * 16 * 8 * CHUNK_B];   // 33.5MB
__device__ __align__(128) char g_Vs[(size_t)NB * 4 * 32 * CHUNK_B];   // 33.5MB
__device__ __align__(128) char g_Ws[(size_t)NB * 16 * 32 * CHUNK_B];  // 134MB

// ------------------------- ptx helpers -------------------------
__device__ __forceinline__ uint32_t smem_u32(const void* p) {
    uint32_t a;
    asm("{ .reg .u64 t; cvta.to.shared.u64 t, %1; cvt.u32.u64 %0, t; }" : "=r"(a) : "l"(p));
    return a;
}
__device__ __forceinline__ uint32_t elect1() {
    uint32_t p;
    asm volatile("{\n\t.reg .pred p;\n\telect.sync _|p, 0xFFFFFFFF;\n\tselp.b32 %0,1,0,p;\n\t}" : "=r"(p));
    return p;
}
__device__ __forceinline__ uint32_t ctarank() {
    uint32_t r;
    asm("mov.u32 %0, %%cluster_ctarank;" : "=r"(r));
    return r;
}
__device__ __forceinline__ void cluster_sync_all() {
    asm volatile("barrier.cluster.arrive.aligned;" ::: "memory");
    asm volatile("barrier.cluster.wait.aligned;" ::: "memory");
}
__device__ __forceinline__ void mbar_init(uint32_t addr, uint32_t cnt) {
    asm volatile("mbarrier.init.shared.b64 [%0], %1;" :: "r"(addr), "r"(cnt) : "memory");
}
__device__ __forceinline__ void mbar_wait(uint32_t mbar, uint32_t parity) {
    asm volatile(
        "{\n\t.reg .pred P;\n\t"
        "W_%=:\n\t"
        "mbarrier.try_wait.parity.acquire.cta.shared::cta.b64 P, [%0], %1, 0x989680;\n\t"
        "@P bra.uni D_%=;\n\t"
        "bra.uni W_%=;\n\t"
        "D_%=:\n\t}"
        :: "r"(mbar), "r"(parity) : "memory");
}
__device__ __forceinline__ void mbar_arrive(uint32_t mbar) {
    asm volatile("mbarrier.arrive.shared.b64 _, [%0];" :: "r"(mbar) : "memory");
}
__device__ __forceinline__ void mbar_expect_tx(uint32_t mbar, uint32_t bytes) {
    asm volatile("mbarrier.arrive.expect_tx.shared.b64 _, [%0], %1;"
                 :: "r"(mbar), "r"(bytes) : "memory");
}
__device__ __forceinline__ void bulk_g2s(uint32_t dst, const void* src, uint32_t bytes,
                                         uint32_t mbar) {
    asm volatile(
        "cp.async.bulk.shared::cluster.global.mbarrier::complete_tx::bytes [%0], [%1], %2, [%3];"
        :: "r"(dst), "l"(src), "r"(bytes), "r"(mbar) : "memory");
}
__device__ __forceinline__ void bulk_g2s_mc(uint32_t dst, const void* src, uint32_t bytes,
                                            uint32_t mbar, uint16_t mask) {
    asm volatile(
        "cp.async.bulk.shared::cluster.global.mbarrier::complete_tx::bytes.multicast::cluster "
        "[%0], [%1], %2, [%3], %4;"
        :: "r"(dst), "l"(src), "r"(bytes), "r"(mbar), "h"(mask) : "memory");
}

#if HAS_TCGEN05
__device__ __forceinline__ void tmem_alloc(uint32_t smem_addr, uint32_t ncols) {
    asm volatile("tcgen05.alloc.cta_group::1.sync.aligned.shared::cta.b32 [%0], %1;"
                 :: "r"(smem_addr), "r"(ncols) : "memory");
}
__device__ __forceinline__ void tmem_dealloc(uint32_t tmem, uint32_t ncols) {
    asm volatile("tcgen05.dealloc.cta_group::1.sync.aligned.b32 %0, %1;" :: "r"(tmem), "r"(ncols));
}
__device__ __forceinline__ void tmem_relinquish() {
    asm volatile("tcgen05.relinquish_alloc_permit.cta_group::1.sync.aligned;");
}
__device__ __forceinline__ void mma_commit(uint32_t mbar) {
    asm volatile("tcgen05.commit.cta_group::1.mbarrier::arrive::one.shared::cluster.b64 [%0];"
                 :: "r"(mbar) : "memory");
}
__device__ __forceinline__ void mma_commit_mc(uint32_t mbar, uint16_t mask) {
    asm volatile(
        "tcgen05.commit.cta_group::1.mbarrier::arrive::one.shared::cluster.multicast::cluster.b64 "
        "[%0], %1;"
        :: "r"(mbar), "h"(mask) : "memory");
}
__device__ __forceinline__ void tc_fence_after() {
    asm volatile("tcgen05.fence::after_thread_sync;" ::: "memory");
}
__device__ __forceinline__ void tc_wait_ld() {
    asm volatile("tcgen05.wait::ld.sync.aligned;" ::: "memory");
}
__device__ __forceinline__ uint64_t mk_desc(uint32_t addr) {
    // SW128, version=1, SBO=64, LBO=1 (K-major, 128B rows)
    return (2ULL << 61) | (1ULL << 46) | (64ULL << 32) | (1ULL << 16) |
           ((uint64_t)(addr >> 4) & 0x3FFF);
}
__device__ __forceinline__ void mma_bf16_ss(uint32_t d, uint64_t da, uint64_t db,
                                            uint32_t idesc, uint32_t acc) {
    asm volatile(
        "{\n\t.reg .pred p;\n\t"
        "setp.ne.u32 p, %4, 0;\n\t"
        "tcgen05.mma.cta_group::1.kind::f16 [%0], %1, %2, %3, {%5, %5, %5, %5}, p;\n\t}"
        :: "r"(d), "l"(da), "l"(db), "r"(idesc), "r"(acc), "r"(0u) : "memory");
}
__device__ __forceinline__ void ldtm32(uint32_t* r, uint32_t a) {
    asm volatile(
        "tcgen05.ld.sync.aligned.32x32b.x32.b32 "
        "{%0,%1,%2,%3,%4,%5,%6,%7,%8,%9,%10,%11,%12,%13,%14,%15,"
        "%16,%17,%18,%19,%20,%21,%22,%23,%24,%25,%26,%27,%28,%29,%30,%31}, [%32];"
        : "=r"(r[0]), "=r"(r[1]), "=r"(r[2]), "=r"(r[3]), "=r"(r[4]), "=r"(r[5]), "=r"(r[6]), "=r"(r[7]),
          "=r"(r[8]), "=r"(r[9]), "=r"(r[10]), "=r"(r[11]), "=r"(r[12]), "=r"(r[13]), "=r"(r[14]), "=r"(r[15]),
          "=r"(r[16]), "=r"(r[17]), "=r"(r[18]), "=r"(r[19]), "=r"(r[20]), "=r"(r[21]), "=r"(r[22]), "=r"(r[23]),
          "=r"(r[24]), "=r"(r[25]), "=r"(r[26]), "=r"(r[27]), "=r"(r[28]), "=r"(r[29]), "=r"(r[30]), "=r"(r[31])
        : "r"(a));
}
#endif // HAS_TCGEN05

// idesc: F32 accum, BF16 a/b, M=128, N=128
#define GEMM_IDESC ((1u << 4) | (1u << 7) | (1u << 10) | (16u << 17) | (8u << 24))

// ---------------------------------------------------------------------------
// k_sq
// ---------------------------------------------------------------------------
__global__ __launch_bounds__(256) void ksq_kernel(const float* __restrict__ K) {
    int gw = (blockIdx.x * blockDim.x + threadIdx.x) >> 5;
    int lane = threadIdx.x & 31;
    if (gw >= NB * SK) return;
    const float* row = K + (size_t)gw * DH;
    float s = 0.f;
    #pragma unroll
    for (int i = lane * 4; i < DH; i += 128) {
        float4 v = *(const float4*)(row + i);
        s = fmaf(v.x, v.x, s); s = fmaf(v.y, v.y, s);
        s = fmaf(v.z, v.z, s); s = fmaf(v.w, v.w, s);
    }
    #pragma unroll
    for (int o = 16; o > 0; o >>= 1) s += __shfl_xor_sync(0xffffffffu, s, o);
    if (lane == 0) g_ksq[gw] = s;
}

// ---------------------------------------------------------------------------
__device__ __forceinline__ void split8(const float* v, uint32_t* hi, uint32_t* lo) {
    #pragma unroll
    for (int p = 0; p < 4; p++) {
        __nv_bfloat162 h(__float2bfloat16(v[2 * p]), __float2bfloat16(v[2 * p + 1]));
        __nv_bfloat162 l(__float2bfloat16(v[2 * p] - __bfloat162float(h.x)),
                         __float2bfloat16(v[2 * p + 1] - __bfloat162float(h.y)));
        hi[p] = *(uint32_t*)&h;
        lo[p] = *(uint32_t*)&l;
    }
}

// ---------------------------------------------------------------------------
// Q/K split into chunked swizzled hi/lo layout.
// ---------------------------------------------------------------------------
__global__ __launch_bounds__(256) void splitqk_kernel(const float* __restrict__ X,
                                                      char* __restrict__ dst, int kst) {
    const int kdim = kst * 64;
    const int tpr = kst * 8;
    int idx = blockIdx.x * 256 + threadIdx.x;
    int mg = idx / tpr;
    int k0 = (idx % tpr) * 8;
    int b = mg >> 11, m = mg & 2047;
    int mtile = m >> 7, row = m & 127;
    int kstage = k0 >> 6, colc = k0 & 63;

    float v[8];
    const float* src = X + (size_t)mg * kdim + k0;
    *(float4*)(v) = *(const float4*)(src);
    *(float4*)(v + 4) = *(const float4*)(src + 4);
    uint32_t hi[4], lo[4];
    split8(v, hi, lo);

    size_t base = (size_t)((b * 16 + mtile) * kst + kstage) * CHUNK_B;
    uint32_t off = row * 128 + colc * 2;
    off ^= (off >> 3) & 0x70;
    *(uint4*)(dst + base + off) = make_uint4(hi[0], hi[1], hi[2], hi[3]);
    *(uint4*)(dst + base + 16384 + off) = make_uint4(lo[0], lo[1], lo[2], lo[3]);
}

// ---------------------------------------------------------------------------
// V transpose + split into chunked layout: row=d, col=k. KST=32, NTILES=4.
// ---------------------------------------------------------------------------
__global__ __launch_bounds__(256) void vsplit_kernel(const float* __restrict__ V) {
    __shared__ float t[32][33];
    const int b = blockIdx.z;
    const int d0 = blockIdx.x * 32, k0 = blockIdx.y * 32;
    const float* Vb = V + (size_t)b * SK * DH;
    const int tid = threadIdx.x;
    #pragma unroll
    for (int i = 0; i < 4; i++) {
        int kk = (tid >> 5) + i * 8, dd = tid & 31;
        t[kk][dd] = Vb[(size_t)(k0 + kk) * DH + d0 + dd];
    }
    __syncthreads();
    int d_local = tid >> 3, k_local = (tid & 7) * 4;
    float v[4];
    #pragma unroll
    for (int i = 0; i < 4; i++) v[i] = t[k_local + i][d_local];
    uint32_t hi[2], lo[2];
    #pragma unroll
    for (int p = 0; p < 2; p++) {
        __nv_bfloat162 h(__float2bfloat16(v[2 * p]), __float2bfloat16(v[2 * p + 1]));
        __nv_bfloat162 l(__float2bfloat16(v[2 * p] - __bfloat162float(h.x)),
                         __float2bfloat16(v[2 * p + 1] - __bfloat162float(h.y)));
        hi[p] = *(uint32_t*)&h;
        lo[p] = *(uint32_t*)&l;
    }
    int d = d0 + d_local, k = k0 + k_local;
    int ntile = d >> 7, row = d & 127, kstage = k >> 6, colc = k & 63;
    size_t base = (size_t)((b * 4 + ntile) * 32 + kstage) * CHUNK_B;
    uint32_t off = row * 128 + colc * 2;
    off ^= (off >> 3) & 0x70;
    *(uint2*)(g_Vs + base + off) = make_uint2(hi[0], hi[1]);
    *(uint2*)(g_Vs + base + 16384 + off) = make_uint2(lo[0], lo[1]);
}

// ---------------------------------------------------------------------------
// Persistent 128x256-tile GEMM, 2-CTA cluster, multicast-B.
// Cluster pair: my = 2*mypair + rank (A differs), SAME nx2 schedule (B shared).
// Per stage: rank loads own A (32KB) + multicasts its 32KB B slice to both.
// empty[buf] (count=2) receives commit-multicast from both CTAs' MMA warps.
// ---------------------------------------------------------------------------
template <int MT, int NXT2, int KST, int TPT_, bool IS_QK>
__global__ __launch_bounds__(256, 1) __cluster_dims__(2, 1, 1)
void gemm5_kernel(const char* __restrict__ Achunks, const char* __restrict__ Bchunks,
                  float* __restrict__ Out, const float* __restrict__ temp) {
    extern __shared__ __align__(1024) char smem[];
    constexpr int LDOUT = NXT2 * 256;
    constexpr int GROUPS = NXT2 / TPT_;

    const int tid = threadIdx.x;
    const int wid = tid >> 5, lid = tid & 31;

#if HAS_TCGEN05
    const uint32_t rank = ctarank();
    const int cluster = blockIdx.x >> 1;
    constexpr int CPB = (MT / 2) * GROUPS;  // clusters per batch
    const int b = cluster / CPB, c = cluster % CPB;
    const int mypair = c / GROUPS, group = c % GROUPS;
    const int my = mypair * 2 + (int)rank;
    const int m0 = my * 128;

    const uint32_t sbase = smem_u32(smem);
    // mbars: full[2]@+8,16  empty[2]@+32,40  done[2]@+56,64  efree[2]@+72,80
    if (wid == 0) {
        tmem_alloc(sbase, 512);
        tmem_relinquish();
    }
    if (tid == 0) {
        #pragma unroll
        for (int i = 0; i < NBUF; i++) {
            mbar_init(sbase + 8 + i * 8, 1);
            mbar_init(sbase + 32 + i * 8, 2);   // one commit from each CTA
        }
        mbar_init(sbase + 56, 1);
        mbar_init(sbase + 64, 1);
        mbar_init(sbase + 72, 4);
        mbar_init(sbase + 80, 4);
    }
    __syncthreads();
    cluster_sync_all();   // peer mbarriers must be live before any multicast
    uint32_t tmem;
    asm volatile("ld.shared.b32 %0, [%1];" : "=r"(tmem) : "r"(sbase));

    if (wid == 1 && elect1()) {
        // ---------------- producer ----------------
        const char* Abase = Achunks + (size_t)((b * MT + my) * KST) * CHUNK_B;
        for (int gs = 0; gs < TPT_ * KST; gs++) {
            const int t = gs / KST, s = gs % KST;
            const int nx2 = group * TPT_ + t;
            const int buf = gs % NBUF;
            if (gs >= NBUF) mbar_wait(sbase + 32 + buf * 8, ((gs - NBUF) / NBUF) & 1);
            uint32_t fm = sbase + 8 + buf * 8;
            uint32_t dst = sbase + SMEM_TILES + buf * STAGE_B;
            mbar_expect_tx(fm, STAGE_B);  // 32KB A + 2x32KB multicast B slices
            bulk_g2s(dst, Abase + (size_t)s * CHUNK_B, CHUNK_B, fm);
            // this rank's B slice, multicast to both CTAs
            bulk_g2s_mc(dst + (1 + rank) * CHUNK_B,
                        Bchunks + (size_t)((b * NXT2 * 2 + nx2 * 2 + rank) * KST + s) * CHUNK_B,
                        CHUNK_B, fm, 0x3);
        }
    } else if (wid == 0 && elect1()) {
        // ---------------- MMA issuer ----------------
        for (int t = 0; t < TPT_; t++) {
            const uint32_t dbuf = tmem + (t & 1) * 256;
            if (t >= 2) {
                mbar_wait(sbase + 72 + (t & 1) * 8, ((t >> 1) - 1) & 1);
                tc_fence_after();
            }
            for (int s = 0; s < KST; s++) {
                const int gs = t * KST + s;
                const int buf = gs % NBUF;
                mbar_wait(sbase + 8 + buf * 8, (gs / NBUF) & 1);
                uint32_t tb = sbase + SMEM_TILES + buf * STAGE_B;
                uint64_t dAh = mk_desc(tb);
                uint64_t dAl = mk_desc(tb + 16384);
                #pragma unroll
                for (int h = 0; h < 2; h++) {
                    uint64_t dBh = mk_desc(tb + (1 + h) * CHUNK_B);
                    uint64_t dBl = mk_desc(tb + (1 + h) * CHUNK_B + 16384);
                    const uint32_t dh = dbuf + h * 128;
                    #pragma unroll
                    for (int ks = 0; ks < 4; ks++) {
                        uint32_t acc0 = (s == 0 && ks == 0) ? 0u : 1u;
                        mma_bf16_ss(dh, dAh + ks * 2, dBh + ks * 2, GEMM_IDESC, acc0);
                        mma_bf16_ss(dh, dAh + ks * 2, dBl + ks * 2, GEMM_IDESC, 1u);
                        mma_bf16_ss(dh, dAl + ks * 2, dBh + ks * 2, GEMM_IDESC, 1u);
                    }
                }
                // stage consumed on THIS CTA -> arrive on BOTH CTAs' empty bars
                mma_commit_mc(sbase + 32 + buf * 8, 0x3);
            }
            mma_commit(sbase + 56 + (t & 1) * 8);
        }
    } else if (wid >= 4) {
        // ---------------- epilogue warps (4..7) ----------------
        const int wsub = wid - 4;
        const float invT = IS_QK ? 1.0f / temp[0] : 1.0f;
        for (int t = 0; t < TPT_; t++) {
            const int nx2 = group * TPT_ + t;
            const int n0 = nx2 * 256;
            mbar_wait(sbase + 56 + (t & 1) * 8, (t >> 1) & 1);
            tc_fence_after();
            const uint32_t dbuf = tmem + (t & 1) * 256;
            const int m = m0 + wsub * 32 + lid;
            #pragma unroll
            for (int cb = 0; cb < 256; cb += 32) {
                uint32_t r[32];
                ldtm32(r, dbuf + cb);
                tc_wait_ld();
                float* op = Out + (size_t)b * SQ * LDOUT + (size_t)m * LDOUT + n0 + cb;
                if (IS_QK) {
                    const float* kq = g_ksq + b * SK + n0 + cb;
                    #pragma unroll
                    for (int cc = 0; cc < 32; cc += 4) {
                        float4 o;
                        o.x = (2.f * __uint_as_float(r[cc + 0]) - kq[cc + 0]) * invT;
                        o.y = (2.f * __uint_as_float(r[cc + 1]) - kq[cc + 1]) * invT;
                        o.z = (2.f * __uint_as_float(r[cc + 2]) - kq[cc + 2]) * invT;
                        o.w = (2.f * __uint_as_float(r[cc + 3]) - kq[cc + 3]) * invT;
                        *(float4*)(op + cc) = o;
                    }
                } else {
                    #pragma unroll
                    for (int cc = 0; cc < 32; cc += 4) {
                        float4 o;
                        o.x = __uint_as_float(r[cc + 0]);
                        o.y = __uint_as_float(r[cc + 1]);
                        o.z = __uint_as_float(r[cc + 2]);
                        o.w = __uint_as_float(r[cc + 3]);
                        *(float4*)(op + cc) = o;
                    }
                }
            }
            if (elect1()) mbar_arrive(sbase + 72 + (t & 1) * 8);
        }
    }

    __syncthreads();
    cluster_sync_all();   // no CTA exits while peer may still multicast into it
    if (wid == 0) tmem_dealloc(tmem, 512);

#else  // ---------------- naive correct fallback (plain sm_103 pass; unused) ----
    const int cluster = blockIdx.x >> 1;
    const int rank = blockIdx.x & 1;
    constexpr int CPB = (MT / 2) * GROUPS;
    const int b = cluster / CPB, c = cluster % CPB;
    const int mypair = c / GROUPS, group = c % GROUPS;
    const int my = mypair * 2 + rank;
    const int m0 = my * 128;
    const float invT = IS_QK ? 1.f / temp[0] : 1.f;
    for (int t = 0; t < TPT_; t++) {
        const int nx2 = group * TPT_ + t;
        const int n0 = nx2 * 256;
        const char* ca0 = Achunks + (size_t)(b * MT + my) * KST * CHUNK_B;
        for (int e = tid; e < 128 * 256; e += 256) {
            int i = e >> 8, j = e & 255;
            const char* cb0 =
                Bchunks + (size_t)(b * NXT2 * 2 + nx2 * 2 + (j >> 7)) * KST * CHUNK_B;
            int jj = j & 127;
            float acc = 0.f;
            for (int s = 0; s < KST; s++) {
                const char* ca = ca0 + (size_t)s * CHUNK_B;
                const char* cb = cb0 + (size_t)s * CHUNK_B;
                for (int k = 0; k < 64; k++) {
                    uint32_t oa = i * 128 + k * 2; oa ^= (oa >> 3) & 0x70;
                    uint32_t ob = jj * 128 + k * 2; ob ^= (ob >> 3) & 0x70;
                    float a = __bfloat162float(*(const __nv_bfloat16*)(ca + oa)) +
                              __bfloat162float(*(const __nv_bfloat16*)(ca + 16384 + oa));
                    float bb = __bfloat162float(*(const __nv_bfloat16*)(cb + ob)) +
                               __bfloat162float(*(const __nv_bfloat16*)(cb + 16384 + ob));
                    acc = fmaf(a, bb, acc);
                }
            }
            float* op = Out + (size_t)b * SQ * LDOUT + (size_t)(m0 + i) * LDOUT + n0 + j;
            *op = IS_QK ? (2.f * acc - g_ksq[b * SK + n0 + j]) * invT : acc;
        }
        __syncthreads();
    }
#endif
}

// ---------------------------------------------------------------------------
// softmax (in-place fp32) + write hi/lo chunked W tiles for PV
// ---------------------------------------------------------------------------
__global__ __launch_bounds__(256) void softmax_kernel(float* __restrict__ W) {
    const int rowg = blockIdx.x;
    float* r = W + (size_t)rowg * SK;
    const int tid = threadIdx.x;

    float vals[8];
    *(float4*)(vals) = *(const float4*)(r + tid * 8);
    *(float4*)(vals + 4) = *(const float4*)(r + tid * 8 + 4);
    float m = vals[0];
    #pragma unroll
    for (int i = 1; i < 8; i++) m = fmaxf(m, vals[i]);

    __shared__ float red[8];
    #pragma unroll
    for (int o = 16; o > 0; o >>= 1) m = fmaxf(m, __shfl_xor_sync(0xffffffffu, m, o));
    if ((tid & 31) == 0) red[tid >> 5] = m;
    __syncthreads();
    m = red[0];
    #pragma unroll
    for (int w = 1; w < 8; w++) m = fmaxf(m, red[w]);
    __syncthreads();

    float s = 0.f;
    #pragma unroll
    for (int i = 0; i < 8; i++) {
        vals[i] = __expf(vals[i] - m);
        s += vals[i];
    }
    #pragma unroll
    for (int o = 16; o > 0; o >>= 1) s += __shfl_xor_sync(0xffffffffu, s, o);
    if ((tid & 31) == 0) red[tid >> 5] = s;
    __syncthreads();
    s = red[0];
    #pragma unroll
    for (int w = 1; w < 8; w++) s += red[w];

    const float inv = 1.0f / s;
    #pragma unroll
    for (int i = 0; i < 8; i++) vals[i] *= inv;
    *(float4*)(r + tid * 8) = *(float4*)(vals);
    *(float4*)(r + tid * 8 + 4) = *(float4*)(vals + 4);

    uint32_t hi[4], lo[4];
    split8(vals, hi, lo);
    const int b = rowg >> 11, q = rowg & 2047;
    const int mtile = q >> 7, row = q & 127;
    const int kstage = tid >> 3, colc = (tid * 8) & 63;
    size_t base = (size_t)((b * 16 + mtile) * 32 + kstage) * CHUNK_B;
    uint32_t off = row * 128 + colc * 2;
    off ^= (off >> 3) & 0x70;
    *(uint4*)(g_Ws + base + off) = make_uint4(hi[0], hi[1], hi[2], hi[3]);
    *(uint4*)(g_Ws + base + 16384 + off) = make_uint4(lo[0], lo[1], lo[2], lo[3]);
}

// ---------------------------------------------------------------------------
extern "C" void kernel_launch(void* const* d_in, const int* in_sizes, int n_in,
                              void* d_out, int out_size) {
    const float* Q = (const float*)d_in[0];
    const float* K = (const float*)d_in[1];
    const float* V = (const float*)d_in[2];
    const float* T = (const float*)d_in[3];

    float* attended = (float*)d_out;                        // [B,SQ,DH]
    float* weights  = (float*)d_out + (size_t)NB * SQ * DH; // [B,SQ,SK]

    void *qs, *ks, *vs, *ws;
    cudaGetSymbolAddress(&qs, g_Qs);
    cudaGetSymbolAddress(&ks, g_Ks);
    cudaGetSymbolAddress(&vs, g_Vs);
    cudaGetSymbolAddress(&ws, g_Ws);

    cudaFuncSetAttribute((const void*)gemm5_kernel<16, 8, 8, 8, true>,
                         cudaFuncAttributeMaxDynamicSharedMemorySize, SMEM_TOTAL);
    cudaFuncSetAttribute((const void*)gemm5_kernel<16, 2, 32, 2, false>,
                         cudaFuncAttributeMaxDynamicSharedMemorySize, SMEM_TOTAL);

    // 1) prep
    ksq_kernel<<<NB * SK * 32 / 256, 256>>>(K);
    splitqk_kernel<<<NB * SQ * 64 / 256, 256>>>(Q, (char*)qs, 8);
    splitqk_kernel<<<NB * SK * 64 / 256, 256>>>(K, (char*)ks, 8);
    vsplit_kernel<<<dim3(DH / 32, SK / 32, NB), 256>>>(V);

    // 2) logits = (2 q.k - ksq)/T
    //    8 batches x 8 my-pairs x 1 group -> 64 clusters = 128 CTAs (TPT=8)
    gemm5_kernel<16, 8, 8, 8, true><<<128, 256, SMEM_TOTAL>>>(
        (const char*)qs, (const char*)ks, weights, T);

    // 3) softmax in-place + chunked hi/lo W
    softmax_kernel<<<NB * SQ, 256>>>(weights);

    // 4) attended = W @ V
    //    8 batches x 8 my-pairs x 1 group -> 64 clusters = 128 CTAs (TPT=2)
    gemm5_kernel<16, 2, 32, 2, false><<<128, 256, SMEM_TOTAL>>>(
        (const char*)ws, (const char*)vs, attended, nullptr);
}

// round 9
// speedup vs baseline: 1.7458x; 1.0383x over previous
#include <cuda_runtime.h>
#include <cuda_bf16.h>
#include <cstdint>

#define NB 8
#define SQ 2048
#define SK 2048
#define DH 512

#define CHUNK_B 32768          // one 128x64 tile pair: [hi 16KB][lo 16KB]
#define NBUF 3
#define STAGE_B 65536          // A pair 32KB + B halves 32KB
#define SMEM_TILES 1024
#define SMEM_TOTAL (SMEM_TILES + NBUF * STAGE_B)  // 197632 bytes

// tcgen05 is arch-accelerated ('a'): only emit in sm_10xa passes.
#if defined(__CUDA_ARCH_FEAT_SM103_ALL) || defined(__CUDA_ARCH_FEAT_SM100_ALL) || \
    defined(__CUDA_ARCH_FEAT_SM101_ALL) ||                                        \
    (defined(__CUDA_ARCH_SPECIFIC__) && (__CUDA_ARCH_SPECIFIC__ >= 1000)) ||      \
    (defined(__CUDA_ARCH_FAMILY_SPECIFIC__) && (__CUDA_ARCH_FAMILY_SPECIFIC__ >= 1000))
#define HAS_TCGEN05 1
#else
#define HAS_TCGEN05 0
#endif

// ------------------------- device scratch (chunked tile layouts) -----------
__device__ float g_ksq[NB * SK];
__device__ __align__(128) char g_Qs[(size_t)NB * 16 * 8 * CHUNK_B];   // 33.5MB
__device__ __align__(128) char g_Ks[(size_t)NB * 16 * 8 * CHUNK_B];   // 33.5MB
__device__ __align__(128) char g_Vs[(size_t)NB * 4 * 32 * CHUNK_B];   // 33.5MB
__device__ __align__(128) char g_Ws[(size_t)NB * 16 * 32 * CHUNK_B];  // 134MB

// ------------------------- ptx helpers -------------------------
__device__ __forceinline__ uint32_t smem_u32(const void* p) {
    uint32_t a;
    asm("{ .reg .u64 t; cvta.to.shared.u64 t, %1; cvt.u32.u64 %0, t; }" : "=r"(a) : "l"(p));
    return a;
}
__device__ __forceinline__ uint32_t elect1() {
    uint32_t p;
    asm volatile("{\n\t.reg .pred p;\n\telect.sync _|p, 0xFFFFFFFF;\n\tselp.b32 %0,1,0,p;\n\t}" : "=r"(p));
    return p;
}
__device__ __forceinline__ uint32_t ctarank() {
    uint32_t r;
    asm("mov.u32 %0, %%cluster_ctarank;" : "=r"(r));
    return r;
}
__device__ __forceinline__ void cluster_sync_all() {
    asm volatile("barrier.cluster.arrive.aligned;" ::: "memory");
    asm volatile("barrier.cluster.wait.aligned;" ::: "memory");
}
__device__ __forceinline__ void mbar_init(uint32_t addr, uint32_t cnt) {
    asm volatile("mbarrier.init.shared.b64 [%0], %1;" :: "r"(addr), "r"(cnt) : "memory");
}
__device__ __forceinline__ void mbar_wait(uint32_t mbar, uint32_t parity) {
    asm volatile(
        "{\n\t.reg .pred P;\n\t"
        "W_%=:\n\t"
        "mbarrier.try_wait.parity.acquire.cta.shared::cta.b64 P, [%0], %1, 0x989680;\n\t"
        "@P bra.uni D_%=;\n\t"
        "bra.uni W_%=;\n\t"
        "D_%=:\n\t}"
        :: "r"(mbar), "r"(parity) : "memory");
}
__device__ __forceinline__ void mbar_arrive(uint32_t mbar) {
    asm volatile("mbarrier.arrive.shared.b64 _, [%0];" :: "r"(mbar) : "memory");
}
// arrive on the same-offset mbarrier in cluster CTA `target_rank`
__device__ __forceinline__ void mbar_arrive_cluster(uint32_t mbar, uint32_t target_rank) {
    asm volatile(
        "{\n\t.reg .b32 r;\n\t"
        "mapa.shared::cluster.u32 r, %0, %1;\n\t"
        "mbarrier.arrive.shared::cluster.b64 _, [r];\n\t}"
        :: "r"(mbar), "r"(target_rank) : "memory");
}
__device__ __forceinline__ void mbar_expect_tx(uint32_t mbar, uint32_t bytes) {
    asm volatile("mbarrier.arrive.expect_tx.shared.b64 _, [%0], %1;"
                 :: "r"(mbar), "r"(bytes) : "memory");
}
__device__ __forceinline__ void bulk_g2s(uint32_t dst, const void* src, uint32_t bytes,
                                         uint32_t mbar) {
    asm volatile(
        "cp.async.bulk.shared::cluster.global.mbarrier::complete_tx::bytes [%0], [%1], %2, [%3];"
        :: "r"(dst), "l"(src), "r"(bytes), "r"(mbar) : "memory");
}

#if HAS_TCGEN05
__device__ __forceinline__ void tmem_alloc_cg2(uint32_t smem_addr, uint32_t ncols) {
    asm volatile("tcgen05.alloc.cta_group::2.sync.aligned.shared::cta.b32 [%0], %1;"
                 :: "r"(smem_addr), "r"(ncols) : "memory");
}
__device__ __forceinline__ void tmem_dealloc_cg2(uint32_t tmem, uint32_t ncols) {
    asm volatile("tcgen05.dealloc.cta_group::2.sync.aligned.b32 %0, %1;" :: "r"(tmem), "r"(ncols));
}
__device__ __forceinline__ void tmem_relinquish_cg2() {
    asm volatile("tcgen05.relinquish_alloc_permit.cta_group::2.sync.aligned;");
}
__device__ __forceinline__ void mma_commit_mc_cg2(uint32_t mbar, uint16_t mask) {
    asm volatile(
        "tcgen05.commit.cta_group::2.mbarrier::arrive::one.shared::cluster.multicast::cluster.b64 "
        "[%0], %1;"
        :: "r"(mbar), "h"(mask) : "memory");
}
__device__ __forceinline__ void tc_fence_after() {
    asm volatile("tcgen05.fence::after_thread_sync;" ::: "memory");
}
__device__ __forceinline__ void tc_wait_ld() {
    asm volatile("tcgen05.wait::ld.sync.aligned;" ::: "memory");
}
__device__ __forceinline__ uint64_t mk_desc(uint32_t addr) {
    // SW128, version=1, SBO=64, LBO=1 (K-major, 128B rows)
    return (2ULL << 61) | (1ULL << 46) | (64ULL << 32) | (1ULL << 16) |
           ((uint64_t)(addr >> 4) & 0x3FFF);
}
// cg2 bf16 SS MMA: M=256 (128 rows per CTA), fp32 accum
__device__ __forceinline__ void mma_bf16_ss_cg2(uint32_t d, uint64_t da, uint64_t db,
                                                uint32_t idesc, uint32_t acc) {
    asm volatile(
        "{\n\t.reg .pred p;\n\t"
        "setp.ne.u32 p, %4, 0;\n\t"
        "tcgen05.mma.cta_group::2.kind::f16 [%0], %1, %2, %3, "
        "{%5, %5, %5, %5, %5, %5, %5, %5}, p;\n\t}"
        :: "r"(d), "l"(da), "l"(db), "r"(idesc), "r"(acc), "r"(0u) : "memory");
}
__device__ __forceinline__ void ldtm32(uint32_t* r, uint32_t a) {
    asm volatile(
        "tcgen05.ld.sync.aligned.32x32b.x32.b32 "
        "{%0,%1,%2,%3,%4,%5,%6,%7,%8,%9,%10,%11,%12,%13,%14,%15,"
        "%16,%17,%18,%19,%20,%21,%22,%23,%24,%25,%26,%27,%28,%29,%30,%31}, [%32];"
        : "=r"(r[0]), "=r"(r[1]), "=r"(r[2]), "=r"(r[3]), "=r"(r[4]), "=r"(r[5]), "=r"(r[6]), "=r"(r[7]),
          "=r"(r[8]), "=r"(r[9]), "=r"(r[10]), "=r"(r[11]), "=r"(r[12]), "=r"(r[13]), "=r"(r[14]), "=r"(r[15]),
          "=r"(r[16]), "=r"(r[17]), "=r"(r[18]), "=r"(r[19]), "=r"(r[20]), "=r"(r[21]), "=r"(r[22]), "=r"(r[23]),
          "=r"(r[24]), "=r"(r[25]), "=r"(r[26]), "=r"(r[27]), "=r"(r[28]), "=r"(r[29]), "=r"(r[30]), "=r"(r[31])
        : "r"(a));
}
#endif // HAS_TCGEN05

// idesc: F32 accum, BF16 a/b, M=256 (cg2), N=128
#define GEMM_IDESC_CG2 ((1u << 4) | (1u << 7) | (1u << 10) | (16u << 17) | (16u << 24))

// ---------------------------------------------------------------------------
// k_sq
// ---------------------------------------------------------------------------
__global__ __launch_bounds__(256) void ksq_kernel(const float* __restrict__ K) {
    int gw = (blockIdx.x * blockDim.x + threadIdx.x) >> 5;
    int lane = threadIdx.x & 31;
    if (gw >= NB * SK) return;
    const float* row = K + (size_t)gw * DH;
    float s = 0.f;
    #pragma unroll
    for (int i = lane * 4; i < DH; i += 128) {
        float4 v = *(const float4*)(row + i);
        s = fmaf(v.x, v.x, s); s = fmaf(v.y, v.y, s);
        s = fmaf(v.z, v.z, s); s = fmaf(v.w, v.w, s);
    }
    #pragma unroll
    for (int o = 16; o > 0; o >>= 1) s += __shfl_xor_sync(0xffffffffu, s, o);
    if (lane == 0) g_ksq[gw] = s;
}

// ---------------------------------------------------------------------------
__device__ __forceinline__ void split8(const float* v, uint32_t* hi, uint32_t* lo) {
    #pragma unroll
    for (int p = 0; p < 4; p++) {
        __nv_bfloat162 h(__float2bfloat16(v[2 * p]), __float2bfloat16(v[2 * p + 1]));
        __nv_bfloat162 l(__float2bfloat16(v[2 * p] - __bfloat162float(h.x)),
                         __float2bfloat16(v[2 * p + 1] - __bfloat162float(h.y)));
        hi[p] = *(uint32_t*)&h;
        lo[p] = *(uint32_t*)&l;
    }
}

// ---------------------------------------------------------------------------
// Q/K split into chunked swizzled hi/lo layout.
// ---------------------------------------------------------------------------
__global__ __launch_bounds__(256) void splitqk_kernel(const float* __restrict__ X,
                                                      char* __restrict__ dst, int kst) {
    const int kdim = kst * 64;
    const int tpr = kst * 8;
    int idx = blockIdx.x * 256 + threadIdx.x;
    int mg = idx / tpr;
    int k0 = (idx % tpr) * 8;
    int b = mg >> 11, m = mg & 2047;
    int mtile = m >> 7, row = m & 127;
    int kstage = k0 >> 6, colc = k0 & 63;

    float v[8];
    const float* src = X + (size_t)mg * kdim + k0;
    *(float4*)(v) = *(const float4*)(src);
    *(float4*)(v + 4) = *(const float4*)(src + 4);
    uint32_t hi[4], lo[4];
    split8(v, hi, lo);

    size_t base = (size_t)((b * 16 + mtile) * kst + kstage) * CHUNK_B;
    uint32_t off = row * 128 + colc * 2;
    off ^= (off >> 3) & 0x70;
    *(uint4*)(dst + base + off) = make_uint4(hi[0], hi[1], hi[2], hi[3]);
    *(uint4*)(dst + base + 16384 + off) = make_uint4(lo[0], lo[1], lo[2], lo[3]);
}

// ---------------------------------------------------------------------------
// V transpose + split into chunked layout: row=d, col=k. KST=32, NTILES=4.
// ---------------------------------------------------------------------------
__global__ __launch_bounds__(256) void vsplit_kernel(const float* __restrict__ V) {
    __shared__ float t[32][33];
    const int b = blockIdx.z;
    const int d0 = blockIdx.x * 32, k0 = blockIdx.y * 32;
    const float* Vb = V + (size_t)b * SK * DH;
    const int tid = threadIdx.x;
    #pragma unroll
    for (int i = 0; i < 4; i++) {
        int kk = (tid >> 5) + i * 8, dd = tid & 31;
        t[kk][dd] = Vb[(size_t)(k0 + kk) * DH + d0 + dd];
    }
    __syncthreads();
    int d_local = tid >> 3, k_local = (tid & 7) * 4;
    float v[4];
    #pragma unroll
    for (int i = 0; i < 4; i++) v[i] = t[k_local + i][d_local];
    uint32_t hi[2], lo[2];
    #pragma unroll
    for (int p = 0; p < 2; p++) {
        __nv_bfloat162 h(__float2bfloat16(v[2 * p]), __float2bfloat16(v[2 * p + 1]));
        __nv_bfloat162 l(__float2bfloat16(v[2 * p] - __bfloat162float(h.x)),
                         __float2bfloat16(v[2 * p + 1] - __bfloat162float(h.y)));
        hi[p] = *(uint32_t*)&h;
        lo[p] = *(uint32_t*)&l;
    }
    int d = d0 + d_local, k = k0 + k_local;
    int ntile = d >> 7, row = d & 127, kstage = k >> 6, colc = k & 63;
    size_t base = (size_t)((b * 4 + ntile) * 32 + kstage) * CHUNK_B;
    uint32_t off = row * 128 + colc * 2;
    off ^= (off >> 3) & 0x70;
    *(uint2*)(g_Vs + base + off) = make_uint2(hi[0], hi[1]);
    *(uint2*)(g_Vs + base + 16384 + off) = make_uint2(lo[0], lo[1]);
}

// ---------------------------------------------------------------------------
// Persistent cg2 GEMM: 256x256 macro tiles per 2-CTA cluster.
// Per stage per CTA: A 32KB (own M-half) + B halves 32KB (rows rank*64..).
// rank0 warp0 issues cg2 MMAs; rank1 warp0 forwards its full-barrier to
// rank0's peerfull; warps 4-7 (both CTAs) drain the previous tile's TMEM.
// smem stage layout: [Ah 16K][Al 16K][B c0h 8K][c0l 8K][c1h 8K][c1l 8K]
// ---------------------------------------------------------------------------
template <int MT, int NXT2, int KST, int TPT_, bool IS_QK>
__global__ __launch_bounds__(256, 1) __cluster_dims__(2, 1, 1)
void gemm5_kernel(const char* __restrict__ Achunks, const char* __restrict__ Bchunks,
                  float* __restrict__ Out, const float* __restrict__ temp) {
    extern __shared__ __align__(1024) char smem[];
    constexpr int LDOUT = NXT2 * 256;
    constexpr int GROUPS = NXT2 / TPT_;
    constexpr int CPB = (MT / 2) * GROUPS;  // clusters per batch

    const int tid = threadIdx.x;
    const int wid = tid >> 5, lid = tid & 31;

#if HAS_TCGEN05
    const uint32_t rank = ctarank();
    const int cluster = blockIdx.x >> 1;
    const int b = cluster / CPB, c = cluster % CPB;
    const int mypair = c / GROUPS, group = c % GROUPS;
    const int my = mypair * 2 + (int)rank;   // this CTA's 128-row A tile

    const uint32_t sbase = smem_u32(smem);
    // mbars: full[3]@+8..24  empty[3]@+32..48  done[2]@+56,64
    //        efree[2]@+72,80  peerfull[3]@+88..104
    if (wid == 0) {
        tmem_alloc_cg2(sbase, 512);
        tmem_relinquish_cg2();
    }
    if (tid == 0) {
        #pragma unroll
        for (int i = 0; i < NBUF; i++) {
            mbar_init(sbase + 8 + i * 8, 1);    // full: local expect_tx
            mbar_init(sbase + 32 + i * 8, 1);   // empty: cg2 commit-mc
            mbar_init(sbase + 88 + i * 8, 1);   // peerfull: rank1 arrive
        }
        mbar_init(sbase + 56, 1);
        mbar_init(sbase + 64, 1);
        mbar_init(sbase + 72, 8);               // efree: 4 warps x 2 CTAs
        mbar_init(sbase + 80, 8);
    }
    __syncthreads();
    cluster_sync_all();   // peer mbarriers live before any cross-CTA arrive
    uint32_t tmem;
    asm volatile("ld.shared.b32 %0, [%1];" : "=r"(tmem) : "r"(sbase));

    if (wid == 1 && elect1()) {
        // ---------------- producer (both ranks) ----------------
        const char* Abase = Achunks + (size_t)((b * MT + my) * KST) * CHUNK_B;
        for (int gs = 0; gs < TPT_ * KST; gs++) {
            const int t = gs / KST, s = gs % KST;
            const int nx2 = group * TPT_ + t;
            const int buf = gs % NBUF;
            if (gs >= NBUF) mbar_wait(sbase + 32 + buf * 8, ((gs - NBUF) / NBUF) & 1);
            uint32_t fm = sbase + 8 + buf * 8;
            uint32_t dst = sbase + SMEM_TILES + buf * STAGE_B;
            mbar_expect_tx(fm, STAGE_B);
            bulk_g2s(dst, Abase + (size_t)s * CHUNK_B, CHUNK_B, fm);
            const char* c0 = Bchunks + (size_t)((b * NXT2 * 2 + nx2 * 2) * KST + s) * CHUNK_B;
            const char* c1 = c0 + (size_t)KST * CHUNK_B;
            bulk_g2s(dst + 32768, c0 + rank * 8192, 8192, fm);
            bulk_g2s(dst + 40960, c0 + 16384 + rank * 8192, 8192, fm);
            bulk_g2s(dst + 49152, c1 + rank * 8192, 8192, fm);
            bulk_g2s(dst + 57344, c1 + 16384 + rank * 8192, 8192, fm);
        }
    } else if (wid == 0 && elect1()) {
        if (rank == 1) {
            // ---------------- full-barrier forwarder ----------------
            for (int gs = 0; gs < TPT_ * KST; gs++) {
                const int buf = gs % NBUF;
                mbar_wait(sbase + 8 + buf * 8, (gs / NBUF) & 1);
                mbar_arrive_cluster(sbase + 88 + buf * 8, 0);
            }
        } else {
            // ---------------- cg2 MMA issuer (rank 0) ----------------
            for (int t = 0; t < TPT_; t++) {
                const uint32_t dbuf = tmem + (t & 1) * 256;
                if (t >= 2) {
                    mbar_wait(sbase + 72 + (t & 1) * 8, ((t >> 1) - 1) & 1);
                    tc_fence_after();
                }
                for (int s = 0; s < KST; s++) {
                    const int gs = t * KST + s;
                    const int buf = gs % NBUF;
                    const uint32_t par = (gs / NBUF) & 1;
                    mbar_wait(sbase + 8 + buf * 8, par);    // own data
                    mbar_wait(sbase + 88 + buf * 8, par);   // peer data
                    uint32_t tb = sbase + SMEM_TILES + buf * STAGE_B;
                    uint64_t dAh = mk_desc(tb);
                    uint64_t dAl = mk_desc(tb + 16384);
                    #pragma unroll
                    for (int h = 0; h < 2; h++) {
                        uint64_t dBh = mk_desc(tb + 32768 + h * 16384);
                        uint64_t dBl = mk_desc(tb + 40960 + h * 16384);
                        const uint32_t dh = dbuf + h * 128;
                        #pragma unroll
                        for (int ks = 0; ks < 4; ks++) {
                            uint32_t acc0 = (s == 0 && ks == 0) ? 0u : 1u;
                            mma_bf16_ss_cg2(dh, dAh + ks * 2, dBh + ks * 2, GEMM_IDESC_CG2, acc0);
                            mma_bf16_ss_cg2(dh, dAh + ks * 2, dBl + ks * 2, GEMM_IDESC_CG2, 1u);
                            mma_bf16_ss_cg2(dh, dAl + ks * 2, dBh + ks * 2, GEMM_IDESC_CG2, 1u);
                        }
                    }
                    mma_commit_mc_cg2(sbase + 32 + buf * 8, 0x3);   // empty on both CTAs
                }
                mma_commit_mc_cg2(sbase + 56 + (t & 1) * 8, 0x3);   // done on both CTAs
            }
        }
    } else if (wid >= 4) {
        // ---------------- epilogue warps (4..7, both CTAs) ----------------
        const int wsub = wid - 4;
        const float invT = IS_QK ? 1.0f / temp[0] : 1.0f;
        const int m = mypair * 256 + (int)rank * 128 + wsub * 32 + lid;
        for (int t = 0; t < TPT_; t++) {
            const int nx2 = group * TPT_ + t;
            const int n0 = nx2 * 256;
            mbar_wait(sbase + 56 + (t & 1) * 8, (t >> 1) & 1);
            tc_fence_after();
            const uint32_t dbuf = tmem + (t & 1) * 256;
            #pragma unroll
            for (int cb = 0; cb < 256; cb += 32) {
                uint32_t r[32];
                ldtm32(r, dbuf + cb);
                tc_wait_ld();
                float* op = Out + (size_t)b * SQ * LDOUT + (size_t)m * LDOUT + n0 + cb;
                if (IS_QK) {
                    const float* kq = g_ksq + b * SK + n0 + cb;
                    #pragma unroll
                    for (int cc = 0; cc < 32; cc += 4) {
                        float4 o;
                        o.x = (2.f * __uint_as_float(r[cc + 0]) - kq[cc + 0]) * invT;
                        o.y = (2.f * __uint_as_float(r[cc + 1]) - kq[cc + 1]) * invT;
                        o.z = (2.f * __uint_as_float(r[cc + 2]) - kq[cc + 2]) * invT;
                        o.w = (2.f * __uint_as_float(r[cc + 3]) - kq[cc + 3]) * invT;
                        *(float4*)(op + cc) = o;
                    }
                } else {
                    #pragma unroll
                    for (int cc = 0; cc < 32; cc += 4) {
                        float4 o;
                        o.x = __uint_as_float(r[cc + 0]);
                        o.y = __uint_as_float(r[cc + 1]);
                        o.z = __uint_as_float(r[cc + 2]);
                        o.w = __uint_as_float(r[cc + 3]);
                        *(float4*)(op + cc) = o;
                    }
                }
            }
            if (elect1()) {
                if (rank == 0) mbar_arrive(sbase + 72 + (t & 1) * 8);
                else           mbar_arrive_cluster(sbase + 72 + (t & 1) * 8, 0);
            }
        }
    }

    __syncthreads();
    if (wid == 0) tmem_dealloc_cg2(tmem, 512);
    cluster_sync_all();   // no CTA exits while peer may still signal into it

#else  // ---------------- naive correct fallback (plain sm_103 pass; unused) ----
    const int cluster = blockIdx.x >> 1;
    const int rank = blockIdx.x & 1;
    const int b = cluster / CPB, c = cluster % CPB;
    const int mypair = c / GROUPS, group = c % GROUPS;
    const int my = mypair * 2 + rank;
    const int m0 = my * 128;
    const float invT = IS_QK ? 1.f / temp[0] : 1.f;
    for (int t = 0; t < TPT_; t++) {
        const int nx2 = group * TPT_ + t;
        const int n0 = nx2 * 256;
        const char* ca0 = Achunks + (size_t)(b * MT + my) * KST * CHUNK_B;
        for (int e = tid; e < 128 * 256; e += 256) {
            int i = e >> 8, j = e & 255;
            const char* cb0 =
                Bchunks + (size_t)(b * NXT2 * 2 + nx2 * 2 + (j >> 7)) * KST * CHUNK_B;
            int jj = j & 127;
            float acc = 0.f;
            for (int s = 0; s < KST; s++) {
                const char* ca = ca0 + (size_t)s * CHUNK_B;
                const char* cb = cb0 + (size_t)s * CHUNK_B;
                for (int k = 0; k < 64; k++) {
                    uint32_t oa = i * 128 + k * 2; oa ^= (oa >> 3) & 0x70;
                    uint32_t ob = jj * 128 + k * 2; ob ^= (ob >> 3) & 0x70;
                    float a = __bfloat162float(*(const __nv_bfloat16*)(ca + oa)) +
                              __bfloat162float(*(const __nv_bfloat16*)(ca + 16384 + oa));
                    float bb = __bfloat162float(*(const __nv_bfloat16*)(cb + ob)) +
                               __bfloat162float(*(const __nv_bfloat16*)(cb + 16384 + ob));
                    acc = fmaf(a, bb, acc);
                }
            }
            float* op = Out + (size_t)b * SQ * LDOUT + (size_t)(m0 + i) * LDOUT + n0 + j;
            *op = IS_QK ? (2.f * acc - g_ksq[b * SK + n0 + j]) * invT : acc;
        }
        __syncthreads();
    }
#endif
}

// ---------------------------------------------------------------------------
// softmax (in-place fp32) + write hi/lo chunked W tiles for PV
// ---------------------------------------------------------------------------
__global__ __launch_bounds__(256) void softmax_kernel(float* __restrict__ W) {
    const int rowg = blockIdx.x;
    float* r = W + (size_t)rowg * SK;
    const int tid = threadIdx.x;

    float vals[8];
    *(float4*)(vals) = *(const float4*)(r + tid * 8);
    *(float4*)(vals + 4) = *(const float4*)(r + tid * 8 + 4);
    float m = vals[0];
    #pragma unroll
    for (int i = 1; i < 8; i++) m = fmaxf(m, vals[i]);

    __shared__ float red[8];
    #pragma unroll
    for (int o = 16; o > 0; o >>= 1) m = fmaxf(m, __shfl_xor_sync(0xffffffffu, m, o));
    if ((tid & 31) == 0) red[tid >> 5] = m;
    __syncthreads();
    m = red[0];
    #pragma unroll
    for (int w = 1; w < 8; w++) m = fmaxf(m, red[w]);
    __syncthreads();

    float s = 0.f;
    #pragma unroll
    for (int i = 0; i < 8; i++) {
        vals[i] = __expf(vals[i] - m);
        s += vals[i];
    }
    #pragma unroll
    for (int o = 16; o > 0; o >>= 1) s += __shfl_xor_sync(0xffffffffu, s, o);
    if ((tid & 31) == 0) red[tid >> 5] = s;
    __syncthreads();
    s = red[0];
    #pragma unroll
    for (int w = 1; w < 8; w++) s += red[w];

    const float inv = 1.0f / s;
    #pragma unroll
    for (int i = 0; i < 8; i++) vals[i] *= inv;
    *(float4*)(r + tid * 8) = *(float4*)(vals);
    *(float4*)(r + tid * 8 + 4) = *(float4*)(vals + 4);

    uint32_t hi[4], lo[4];
    split8(vals, hi, lo);
    const int b = rowg >> 11, q = rowg & 2047;
    const int mtile = q >> 7, row = q & 127;
    const int kstage = tid >> 3, colc = (tid * 8) & 63;
    size_t base = (size_t)((b * 16 + mtile) * 32 + kstage) * CHUNK_B;
    uint32_t off = row * 128 + colc * 2;
    off ^= (off >> 3) & 0x70;
    *(uint4*)(g_Ws + base + off) = make_uint4(hi[0], hi[1], hi[2], hi[3]);
    *(uint4*)(g_Ws + base + 16384 + off) = make_uint4(lo[0], lo[1], lo[2], lo[3]);
}

// ---------------------------------------------------------------------------
extern "C" void kernel_launch(void* const* d_in, const int* in_sizes, int n_in,
                              void* d_out, int out_size) {
    const float* Q = (const float*)d_in[0];
    const float* K = (const float*)d_in[1];
    const float* V = (const float*)d_in[2];
    const float* T = (const float*)d_in[3];

    float* attended = (float*)d_out;                        // [B,SQ,DH]
    float* weights  = (float*)d_out + (size_t)NB * SQ * DH; // [B,SQ,SK]

    void *qs, *ks, *vs, *ws;
    cudaGetSymbolAddress(&qs, g_Qs);
    cudaGetSymbolAddress(&ks, g_Ks);
    cudaGetSymbolAddress(&vs, g_Vs);
    cudaGetSymbolAddress(&ws, g_Ws);

    cudaFuncSetAttribute((const void*)gemm5_kernel<16, 8, 8, 8, true>,
                         cudaFuncAttributeMaxDynamicSharedMemorySize, SMEM_TOTAL);
    cudaFuncSetAttribute((const void*)gemm5_kernel<16, 2, 32, 2, false>,
                         cudaFuncAttributeMaxDynamicSharedMemorySize, SMEM_TOTAL);

    // 1) prep
    ksq_kernel<<<NB * SK * 32 / 256, 256>>>(K);
    splitqk_kernel<<<NB * SQ * 64 / 256, 256>>>(Q, (char*)qs, 8);
    splitqk_kernel<<<NB * SK * 64 / 256, 256>>>(K, (char*)ks, 8);
    vsplit_kernel<<<dim3(DH / 32, SK / 32, NB), 256>>>(V);

    // 2) logits = (2 q.k - ksq)/T
    //    8 batches x 8 mpairs -> 64 clusters = 128 CTAs, TPT=8 (full row sweep)
    gemm5_kernel<16, 8, 8, 8, true><<<128, 256, SMEM_TOTAL>>>(
        (const char*)qs, (const char*)ks, weights, T);

    // 3) softmax in-place + chunked hi/lo W
    softmax_kernel<<<NB * SQ, 256>>>(weights);

    // 4) attended = W @ V
    //    8 batches x 8 mpairs -> 64 clusters = 128 CTAs, TPT=2
    gemm5_kernel<16, 2, 32, 2, false><<<128, 256, SMEM_TOTAL>>>(
        (const char*)ws, (const char*)vs, attended, nullptr);
}

// round 10
// speedup vs baseline: 1.9914x; 1.1407x over previous
#include <cuda_runtime.h>
#include <cuda_bf16.h>
#include <cuda_fp16.h>
#include <cstdint>

#define NB 8
#define SQ 2048
#define SK 2048
#define DH 512

#define CHUNK_B 32768          // 128x64 bf16/fp16 hi+lo tile pair: [hi 16KB][lo 16KB]
#define WCHUNK_B 16384         // 128x64 fp16 single tile
#define SMEM_TILES 1024
#define SMEM_TOTAL 197632      // 1024 + 3*65536 (QK) == 1024 + 4*49152 (PV)

// tcgen05 is arch-accelerated ('a'): only emit in sm_10xa passes.
#if defined(__CUDA_ARCH_FEAT_SM103_ALL) || defined(__CUDA_ARCH_FEAT_SM100_ALL) || \
    defined(__CUDA_ARCH_FEAT_SM101_ALL) ||                                        \
    (defined(__CUDA_ARCH_SPECIFIC__) && (__CUDA_ARCH_SPECIFIC__ >= 1000)) ||      \
    (defined(__CUDA_ARCH_FAMILY_SPECIFIC__) && (__CUDA_ARCH_FAMILY_SPECIFIC__ >= 1000))
#define HAS_TCGEN05 1
#else
#define HAS_TCGEN05 0
#endif

// ------------------------- device scratch (chunked tile layouts) -----------
__device__ float g_ksq[NB * SK];
__device__ __align__(128) char g_Qs[(size_t)NB * 16 * 8 * CHUNK_B];    // 33.5MB bf16 hi/lo
__device__ __align__(128) char g_Ks[(size_t)NB * 16 * 8 * CHUNK_B];    // 33.5MB bf16 hi/lo
__device__ __align__(128) char g_Vs[(size_t)NB * 4 * 32 * CHUNK_B];    // 33.5MB fp16 hi/lo
__device__ __align__(128) char g_Ws[(size_t)NB * 16 * 32 * WCHUNK_B];  // 67MB fp16

// ------------------------- ptx helpers -------------------------
__device__ __forceinline__ uint32_t smem_u32(const void* p) {
    uint32_t a;
    asm("{ .reg .u64 t; cvta.to.shared.u64 t, %1; cvt.u32.u64 %0, t; }" : "=r"(a) : "l"(p));
    return a;
}
__device__ __forceinline__ uint32_t elect1() {
    uint32_t p;
    asm volatile("{\n\t.reg .pred p;\n\telect.sync _|p, 0xFFFFFFFF;\n\tselp.b32 %0,1,0,p;\n\t}" : "=r"(p));
    return p;
}
__device__ __forceinline__ uint32_t ctarank() {
    uint32_t r;
    asm("mov.u32 %0, %%cluster_ctarank;" : "=r"(r));
    return r;
}
__device__ __forceinline__ void cluster_sync_all() {
    asm volatile("barrier.cluster.arrive.aligned;" ::: "memory");
    asm volatile("barrier.cluster.wait.aligned;" ::: "memory");
}
__device__ __forceinline__ void mbar_init(uint32_t addr, uint32_t cnt) {
    asm volatile("mbarrier.init.shared.b64 [%0], %1;" :: "r"(addr), "r"(cnt) : "memory");
}
__device__ __forceinline__ void mbar_wait(uint32_t mbar, uint32_t parity) {
    asm volatile(
        "{\n\t.reg .pred P;\n\t"
        "W_%=:\n\t"
        "mbarrier.try_wait.parity.acquire.cta.shared::cta.b64 P, [%0], %1, 0x989680;\n\t"
        "@P bra.uni D_%=;\n\t"
        "bra.uni W_%=;\n\t"
        "D_%=:\n\t}"
        :: "r"(mbar), "r"(parity) : "memory");
}
__device__ __forceinline__ void mbar_arrive(uint32_t mbar) {
    asm volatile("mbarrier.arrive.shared.b64 _, [%0];" :: "r"(mbar) : "memory");
}
__device__ __forceinline__ void mbar_arrive_cluster(uint32_t mbar, uint32_t target_rank) {
    asm volatile(
        "{\n\t.reg .b32 r;\n\t"
        "mapa.shared::cluster.u32 r, %0, %1;\n\t"
        "mbarrier.arrive.shared::cluster.b64 _, [r];\n\t}"
        :: "r"(mbar), "r"(target_rank) : "memory");
}
__device__ __forceinline__ void mbar_expect_tx(uint32_t mbar, uint32_t bytes) {
    asm volatile("mbarrier.arrive.expect_tx.shared.b64 _, [%0], %1;"
                 :: "r"(mbar), "r"(bytes) : "memory");
}
__device__ __forceinline__ void bulk_g2s(uint32_t dst, const void* src, uint32_t bytes,
                                         uint32_t mbar) {
    asm volatile(
        "cp.async.bulk.shared::cluster.global.mbarrier::complete_tx::bytes [%0], [%1], %2, [%3];"
        :: "r"(dst), "l"(src), "r"(bytes), "r"(mbar) : "memory");
}

#if HAS_TCGEN05
__device__ __forceinline__ void tmem_alloc_cg2(uint32_t smem_addr, uint32_t ncols) {
    asm volatile("tcgen05.alloc.cta_group::2.sync.aligned.shared::cta.b32 [%0], %1;"
                 :: "r"(smem_addr), "r"(ncols) : "memory");
}
__device__ __forceinline__ void tmem_dealloc_cg2(uint32_t tmem, uint32_t ncols) {
    asm volatile("tcgen05.dealloc.cta_group::2.sync.aligned.b32 %0, %1;" :: "r"(tmem), "r"(ncols));
}
__device__ __forceinline__ void tmem_relinquish_cg2() {
    asm volatile("tcgen05.relinquish_alloc_permit.cta_group::2.sync.aligned;");
}
__device__ __forceinline__ void mma_commit_mc_cg2(uint32_t mbar, uint16_t mask) {
    asm volatile(
        "tcgen05.commit.cta_group::2.mbarrier::arrive::one.shared::cluster.multicast::cluster.b64 "
        "[%0], %1;"
        :: "r"(mbar), "h"(mask) : "memory");
}
__device__ __forceinline__ void tc_fence_after() {
    asm volatile("tcgen05.fence::after_thread_sync;" ::: "memory");
}
__device__ __forceinline__ void tc_wait_ld() {
    asm volatile("tcgen05.wait::ld.sync.aligned;" ::: "memory");
}
__device__ __forceinline__ uint64_t mk_desc(uint32_t addr) {
    // SW128, version=1, SBO=64, LBO=1 (K-major, 128B rows)
    return (2ULL << 61) | (1ULL << 46) | (64ULL << 32) | (1ULL << 16) |
           ((uint64_t)(addr >> 4) & 0x3FFF);
}
__device__ __forceinline__ void mma_f16_ss_cg2(uint32_t d, uint64_t da, uint64_t db,
                                               uint32_t idesc, uint32_t acc) {
    asm volatile(
        "{\n\t.reg .pred p;\n\t"
        "setp.ne.u32 p, %4, 0;\n\t"
        "tcgen05.mma.cta_group::2.kind::f16 [%0], %1, %2, %3, "
        "{%5, %5, %5, %5, %5, %5, %5, %5}, p;\n\t}"
        :: "r"(d), "l"(da), "l"(db), "r"(idesc), "r"(acc), "r"(0u) : "memory");
}
__device__ __forceinline__ void ldtm32(uint32_t* r, uint32_t a) {
    asm volatile(
        "tcgen05.ld.sync.aligned.32x32b.x32.b32 "
        "{%0,%1,%2,%3,%4,%5,%6,%7,%8,%9,%10,%11,%12,%13,%14,%15,"
        "%16,%17,%18,%19,%20,%21,%22,%23,%24,%25,%26,%27,%28,%29,%30,%31}, [%32];"
        : "=r"(r[0]), "=r"(r[1]), "=r"(r[2]), "=r"(r[3]), "=r"(r[4]), "=r"(r[5]), "=r"(r[6]), "=r"(r[7]),
          "=r"(r[8]), "=r"(r[9]), "=r"(r[10]), "=r"(r[11]), "=r"(r[12]), "=r"(r[13]), "=r"(r[14]), "=r"(r[15]),
          "=r"(r[16]), "=r"(r[17]), "=r"(r[18]), "=r"(r[19]), "=r"(r[20]), "=r"(r[21]), "=r"(r[22]), "=r"(r[23]),
          "=r"(r[24]), "=r"(r[25]), "=r"(r[26]), "=r"(r[27]), "=r"(r[28]), "=r"(r[29]), "=r"(r[30]), "=r"(r[31])
        : "r"(a));
}
#endif // HAS_TCGEN05

// idesc cg2 (M=256, N=128, F32 accum): bf16 a/b (QK) and fp16 a/b (PV)
#define IDESC_QK ((1u << 4) | (1u << 7) | (1u << 10) | (16u << 17) | (16u << 24))
#define IDESC_PV ((1u << 4) | (16u << 17) | (16u << 24))

// ---------------------------------------------------------------------------
// helpers
// ---------------------------------------------------------------------------
__device__ __forceinline__ void split8_bf(const float* v, uint32_t* hi, uint32_t* lo) {
    #pragma unroll
    for (int p = 0; p < 4; p++) {
        __nv_bfloat162 h(__float2bfloat16(v[2 * p]), __float2bfloat16(v[2 * p + 1]));
        __nv_bfloat162 l(__float2bfloat16(v[2 * p] - __bfloat162float(h.x)),
                         __float2bfloat16(v[2 * p + 1] - __bfloat162float(h.y)));
        hi[p] = *(uint32_t*)&h;
        lo[p] = *(uint32_t*)&l;
    }
}

// ---------------------------------------------------------------------------
// Fused prep kernel (task-switched by blockIdx.x):
//   [0,4096)      split Q  -> g_Qs (bf16 hi/lo chunks)
//   [4096,8192)   split K  -> g_Ks
//   [8192,16384)  V transpose+split -> g_Vs (fp16 hi/lo chunks)
//   [16384,18432) ksq
// ---------------------------------------------------------------------------
__global__ __launch_bounds__(256) void prep_kernel(const float* __restrict__ Q,
                                                   const float* __restrict__ K,
                                                   const float* __restrict__ V) {
    __shared__ float t[32][33];
    const int bid = blockIdx.x;
    const int tid = threadIdx.x;

    if (bid < 8192) {
        // ------- split Q/K: thread = 8 consecutive k of one row -------
        const float* X = (bid < 4096) ? Q : K;
        char* dst = (bid < 4096) ? g_Qs : g_Ks;
        int idx = (bid & 4095) * 256 + tid;
        int mg = idx >> 6;                 // row (b*2048 + m)
        int k0 = (idx & 63) * 8;
        int b = mg >> 11, m = mg & 2047;
        int mtile = m >> 7, row = m & 127;
        int kstage = k0 >> 6, colc = k0 & 63;

        float v[8];
        const float* src = X + (size_t)mg * DH + k0;
        *(float4*)(v) = *(const float4*)(src);
        *(float4*)(v + 4) = *(const float4*)(src + 4);
        uint32_t hi[4], lo[4];
        split8_bf(v, hi, lo);

        size_t base = (size_t)((b * 16 + mtile) * 8 + kstage) * CHUNK_B;
        uint32_t off = row * 128 + colc * 2;
        off ^= (off >> 3) & 0x70;
        *(uint4*)(dst + base + off) = make_uint4(hi[0], hi[1], hi[2], hi[3]);
        *(uint4*)(dst + base + 16384 + off) = make_uint4(lo[0], lo[1], lo[2], lo[3]);
    } else if (bid < 16384) {
        // ------- V transpose + fp16 hi/lo split -------
        int r = bid - 8192;
        int b = r >> 10, rem = r & 1023;
        int k0 = (rem >> 4) * 32, d0 = (rem & 15) * 32;
        const float* Vb = V + (size_t)b * SK * DH;
        #pragma unroll
        for (int i = 0; i < 4; i++) {
            int kk = (tid >> 5) + i * 8, dd = tid & 31;
            t[kk][dd] = Vb[(size_t)(k0 + kk) * DH + d0 + dd];
        }
        __syncthreads();
        int d_local = tid >> 3, k_local = (tid & 7) * 4;
        float v[4];
        #pragma unroll
        for (int i = 0; i < 4; i++) v[i] = t[k_local + i][d_local];
        uint32_t hi[2], lo[2];
        #pragma unroll
        for (int p = 0; p < 2; p++) {
            __half h0 = __float2half_rn(v[2 * p]);
            __half h1 = __float2half_rn(v[2 * p + 1]);
            __half l0 = __float2half_rn(v[2 * p] - __half2float(h0));
            __half l1 = __float2half_rn(v[2 * p + 1] - __half2float(h1));
            __half2 hh = __halves2half2(h0, h1);
            __half2 ll = __halves2half2(l0, l1);
            hi[p] = *(uint32_t*)&hh;
            lo[p] = *(uint32_t*)&ll;
        }
        int d = d0 + d_local, k = k0 + k_local;
        int ntile = d >> 7, row = d & 127, kstage = k >> 6, colc = k & 63;
        size_t base = (size_t)((b * 4 + ntile) * 32 + kstage) * CHUNK_B;
        uint32_t off = row * 128 + colc * 2;
        off ^= (off >> 3) & 0x70;
        *(uint2*)(g_Vs + base + off) = make_uint2(hi[0], hi[1]);
        *(uint2*)(g_Vs + base + 16384 + off) = make_uint2(lo[0], lo[1]);
    } else {
        // ------- ksq: one warp per row -------
        int gw = (bid - 16384) * 8 + (tid >> 5);
        int lane = tid & 31;
        const float* row = K + (size_t)gw * DH;
        float s = 0.f;
        #pragma unroll
        for (int i = lane * 4; i < DH; i += 128) {
            float4 v = *(const float4*)(row + i);
            s = fmaf(v.x, v.x, s); s = fmaf(v.y, v.y, s);
            s = fmaf(v.z, v.z, s); s = fmaf(v.w, v.w, s);
        }
        #pragma unroll
        for (int o = 16; o > 0; o >>= 1) s += __shfl_xor_sync(0xffffffffu, s, o);
        if (lane == 0) g_ksq[gw] = s;
    }
}

// ---------------------------------------------------------------------------
// Persistent cg2 GEMM, 256x256 macro tiles per 2-CTA cluster.
//  QK: A = Q bf16 hi/lo (32KB chunk), B = K bf16 hi/lo, 3 MMAs/K16/half.
//  PV: A = W fp16 (16KB chunk),       B = V fp16 hi/lo, 2 MMAs/K16/half.
// Stage: [A (ACH)] [c0h 8K][c0l 8K][c1h 8K][c1l 8K]  (B halves = this rank's
// 64 rows of each of the two N-chunks).
// ---------------------------------------------------------------------------
template <int MT, int NXT2, int KST, int TPT_, int NBUF_, bool IS_QK>
__global__ __launch_bounds__(256, 1) __cluster_dims__(2, 1, 1)
void gemm5_kernel(const char* __restrict__ Achunks, const char* __restrict__ Bchunks,
                  float* __restrict__ Out, const float* __restrict__ temp) {
    extern __shared__ __align__(1024) char smem[];
    constexpr int LDOUT = NXT2 * 256;
    constexpr int GROUPS = NXT2 / TPT_;
    constexpr int CPB = (MT / 2) * GROUPS;
    constexpr int ACH = IS_QK ? 32768 : 16384;
    constexpr int STAGE = ACH + 32768;

    const int tid = threadIdx.x;
    const int wid = tid >> 5, lid = tid & 31;

#if HAS_TCGEN05
    const uint32_t rank = ctarank();
    const int cluster = blockIdx.x >> 1;
    const int b = cluster / CPB, c = cluster % CPB;
    const int mypair = c / GROUPS, group = c % GROUPS;
    const int my = mypair * 2 + (int)rank;

    const uint32_t sbase = smem_u32(smem);
    // mbars: full[i]@+8+8i  empty[i]@+40+8i  peerfull[i]@+72+8i
    //        done[2]@+104,112  efree[2]@+120,128
    if (wid == 0) {
        tmem_alloc_cg2(sbase, 512);
        tmem_relinquish_cg2();
    }
    if (tid == 0) {
        #pragma unroll
        for (int i = 0; i < NBUF_; i++) {
            mbar_init(sbase + 8 + i * 8, 1);
            mbar_init(sbase + 40 + i * 8, 1);
            mbar_init(sbase + 72 + i * 8, 1);
        }
        mbar_init(sbase + 104, 1);
        mbar_init(sbase + 112, 1);
        mbar_init(sbase + 120, 8);
        mbar_init(sbase + 128, 8);
    }
    __syncthreads();
    cluster_sync_all();
    uint32_t tmem;
    asm volatile("ld.shared.b32 %0, [%1];" : "=r"(tmem) : "r"(sbase));

    if (wid == 1 && elect1()) {
        // ---------------- producer ----------------
        const char* Abase = Achunks + (size_t)((b * MT + my) * KST) * ACH;
        for (int gs = 0; gs < TPT_ * KST; gs++) {
            const int t = gs / KST, s = gs % KST;
            const int nx2 = group * TPT_ + t;
            const int buf = gs % NBUF_;
            if (gs >= NBUF_) mbar_wait(sbase + 40 + buf * 8, ((gs - NBUF_) / NBUF_) & 1);
            uint32_t fm = sbase + 8 + buf * 8;
            uint32_t dst = sbase + SMEM_TILES + buf * STAGE;
            mbar_expect_tx(fm, STAGE);
            bulk_g2s(dst, Abase + (size_t)s * ACH, ACH, fm);
            const char* c0 = Bchunks + (size_t)((b * NXT2 * 2 + nx2 * 2) * KST + s) * CHUNK_B;
            const char* c1 = c0 + (size_t)KST * CHUNK_B;
            bulk_g2s(dst + ACH,         c0 + rank * 8192, 8192, fm);
            bulk_g2s(dst + ACH + 8192,  c0 + 16384 + rank * 8192, 8192, fm);
            bulk_g2s(dst + ACH + 16384, c1 + rank * 8192, 8192, fm);
            bulk_g2s(dst + ACH + 24576, c1 + 16384 + rank * 8192, 8192, fm);
        }
    } else if (wid == 0 && elect1()) {
        if (rank == 1) {
            // ---------------- full-barrier forwarder ----------------
            for (int gs = 0; gs < TPT_ * KST; gs++) {
                const int buf = gs % NBUF_;
                mbar_wait(sbase + 8 + buf * 8, (gs / NBUF_) & 1);
                mbar_arrive_cluster(sbase + 72 + buf * 8, 0);
            }
        } else {
            // ---------------- cg2 MMA issuer (rank 0) ----------------
            for (int t = 0; t < TPT_; t++) {
                const uint32_t dbuf = tmem + (t & 1) * 256;
                if (t >= 2) {
                    mbar_wait(sbase + 120 + (t & 1) * 8, ((t >> 1) - 1) & 1);
                    tc_fence_after();
                }
                for (int s = 0; s < KST; s++) {
                    const int gs = t * KST + s;
                    const int buf = gs % NBUF_;
                    const uint32_t par = (gs / NBUF_) & 1;
                    mbar_wait(sbase + 8 + buf * 8, par);
                    mbar_wait(sbase + 72 + buf * 8, par);
                    uint32_t tb = sbase + SMEM_TILES + buf * STAGE;
                    #pragma unroll
                    for (int h = 0; h < 2; h++) {
                        uint64_t dBh = mk_desc(tb + ACH + h * 16384);
                        uint64_t dBl = mk_desc(tb + ACH + 8192 + h * 16384);
                        const uint32_t dh = dbuf + h * 128;
                        if (IS_QK) {
                            uint64_t dAh = mk_desc(tb);
                            uint64_t dAl = mk_desc(tb + 16384);
                            #pragma unroll
                            for (int ks = 0; ks < 4; ks++) {
                                uint32_t acc0 = (s == 0 && ks == 0) ? 0u : 1u;
                                mma_f16_ss_cg2(dh, dAh + ks * 2, dBh + ks * 2, IDESC_QK, acc0);
                                mma_f16_ss_cg2(dh, dAh + ks * 2, dBl + ks * 2, IDESC_QK, 1u);
                                mma_f16_ss_cg2(dh, dAl + ks * 2, dBh + ks * 2, IDESC_QK, 1u);
                            }
                        } else {
                            uint64_t dA = mk_desc(tb);
                            #pragma unroll
                            for (int ks = 0; ks < 4; ks++) {
                                uint32_t acc0 = (s == 0 && ks == 0) ? 0u : 1u;
                                mma_f16_ss_cg2(dh, dA + ks * 2, dBh + ks * 2, IDESC_PV, acc0);
                                mma_f16_ss_cg2(dh, dA + ks * 2, dBl + ks * 2, IDESC_PV, 1u);
                            }
                        }
                    }
                    mma_commit_mc_cg2(sbase + 40 + buf * 8, 0x3);
                }
                mma_commit_mc_cg2(sbase + 104 + (t & 1) * 8, 0x3);
            }
        }
    } else if (wid >= 4) {
        // ---------------- epilogue warps (4..7, both CTAs) ----------------
        const int wsub = wid - 4;
        const float invT = IS_QK ? 1.0f / temp[0] : 1.0f;
        const int m = mypair * 256 + (int)rank * 128 + wsub * 32 + lid;
        for (int t = 0; t < TPT_; t++) {
            const int nx2 = group * TPT_ + t;
            const int n0 = nx2 * 256;
            mbar_wait(sbase + 104 + (t & 1) * 8, (t >> 1) & 1);
            tc_fence_after();
            const uint32_t dbuf = tmem + (t & 1) * 256;
            #pragma unroll
            for (int cb = 0; cb < 256; cb += 32) {
                uint32_t r[32];
                ldtm32(r, dbuf + cb);
                tc_wait_ld();
                float* op = Out + (size_t)b * SQ * LDOUT + (size_t)m * LDOUT + n0 + cb;
                if (IS_QK) {
                    const float* kq = g_ksq + b * SK + n0 + cb;
                    #pragma unroll
                    for (int cc = 0; cc < 32; cc += 4) {
                        float4 o;
                        o.x = (2.f * __uint_as_float(r[cc + 0]) - kq[cc + 0]) * invT;
                        o.y = (2.f * __uint_as_float(r[cc + 1]) - kq[cc + 1]) * invT;
                        o.z = (2.f * __uint_as_float(r[cc + 2]) - kq[cc + 2]) * invT;
                        o.w = (2.f * __uint_as_float(r[cc + 3]) - kq[cc + 3]) * invT;
                        *(float4*)(op + cc) = o;
                    }
                } else {
                    #pragma unroll
                    for (int cc = 0; cc < 32; cc += 4) {
                        float4 o;
                        o.x = __uint_as_float(r[cc + 0]);
                        o.y = __uint_as_float(r[cc + 1]);
                        o.z = __uint_as_float(r[cc + 2]);
                        o.w = __uint_as_float(r[cc + 3]);
                        *(float4*)(op + cc) = o;
                    }
                }
            }
            if (elect1()) {
                if (rank == 0) mbar_arrive(sbase + 120 + (t & 1) * 8);
                else           mbar_arrive_cluster(sbase + 120 + (t & 1) * 8, 0);
            }
        }
    }

    __syncthreads();
    if (wid == 0) tmem_dealloc_cg2(tmem, 512);
    cluster_sync_all();

#else  // ---------------- naive correct fallback (plain sm_103 pass; unused) ----
    const int cluster = blockIdx.x >> 1;
    const int rank = blockIdx.x & 1;
    const int b = cluster / CPB, c = cluster % CPB;
    const int mypair = c / GROUPS, group = c % GROUPS;
    const int my = mypair * 2 + rank;
    const int m0 = my * 128;
    const float invT = IS_QK ? 1.f / temp[0] : 1.f;
    for (int t = 0; t < TPT_; t++) {
        const int nx2 = group * TPT_ + t;
        const int n0 = nx2 * 256;
        const char* ca0 = Achunks + (size_t)(b * MT + my) * KST * ACH;
        for (int e = tid; e < 128 * 256; e += 256) {
            int i = e >> 8, j = e & 255;
            const char* cb0 =
                Bchunks + (size_t)(b * NXT2 * 2 + nx2 * 2 + (j >> 7)) * KST * CHUNK_B;
            int jj = j & 127;
            float acc = 0.f;
            for (int s = 0; s < KST; s++) {
                const char* ca = ca0 + (size_t)s * ACH;
                const char* cb = cb0 + (size_t)s * CHUNK_B;
                for (int k = 0; k < 64; k++) {
                    uint32_t oa = i * 128 + k * 2; oa ^= (oa >> 3) & 0x70;
                    uint32_t ob = jj * 128 + k * 2; ob ^= (ob >> 3) & 0x70;
                    float a, bb;
                    if (IS_QK) {
                        a = __bfloat162float(*(const __nv_bfloat16*)(ca + oa)) +
                            __bfloat162float(*(const __nv_bfloat16*)(ca + 16384 + oa));
                        bb = __bfloat162float(*(const __nv_bfloat16*)(cb + ob)) +
                             __bfloat162float(*(const __nv_bfloat16*)(cb + 16384 + ob));
                    } else {
                        a = __half2float(*(const __half*)(ca + oa));
                        bb = __half2float(*(const __half*)(cb + ob)) +
                             __half2float(*(const __half*)(cb + 16384 + ob));
                    }
                    acc = fmaf(a, bb, acc);
                }
            }
            float* op = Out + (size_t)b * SQ * LDOUT + (size_t)(m0 + i) * LDOUT + n0 + j;
            *op = IS_QK ? (2.f * acc - g_ksq[b * SK + n0 + j]) * invT : acc;
        }
        __syncthreads();
    }
#endif
}

// ---------------------------------------------------------------------------
// softmax (in-place fp32) + write fp16 chunked W tiles for PV
// ---------------------------------------------------------------------------
__global__ __launch_bounds__(256) void softmax_kernel(float* __restrict__ W) {
    const int rowg = blockIdx.x;
    float* r = W + (size_t)rowg * SK;
    const int tid = threadIdx.x;

    float vals[8];
    *(float4*)(vals) = *(const float4*)(r + tid * 8);
    *(float4*)(vals + 4) = *(const float4*)(r + tid * 8 + 4);
    float m = vals[0];
    #pragma unroll
    for (int i = 1; i < 8; i++) m = fmaxf(m, vals[i]);

    __shared__ float red[8];
    #pragma unroll
    for (int o = 16; o > 0; o >>= 1) m = fmaxf(m, __shfl_xor_sync(0xffffffffu, m, o));
    if ((tid & 31) == 0) red[tid >> 5] = m;
    __syncthreads();
    m = red[0];
    #pragma unroll
    for (int w = 1; w < 8; w++) m = fmaxf(m, red[w]);
    __syncthreads();

    float s = 0.f;
    #pragma unroll
    for (int i = 0; i < 8; i++) {
        vals[i] = __expf(vals[i] - m);
        s += vals[i];
    }
    #pragma unroll
    for (int o = 16; o > 0; o >>= 1) s += __shfl_xor_sync(0xffffffffu, s, o);
    if ((tid & 31) == 0) red[tid >> 5] = s;
    __syncthreads();
    s = red[0];
    #pragma unroll
    for (int w = 1; w < 8; w++) s += red[w];

    const float inv = 1.0f / s;
    #pragma unroll
    for (int i = 0; i < 8; i++) vals[i] *= inv;
    *(float4*)(r + tid * 8) = *(float4*)(vals);
    *(float4*)(r + tid * 8 + 4) = *(float4*)(vals + 4);

    // fp16 chunked write for PV A-operand
    uint32_t w4[4];
    #pragma unroll
    for (int p = 0; p < 4; p++) {
        __half2 hh = __halves2half2(__float2half_rn(vals[2 * p]),
                                    __float2half_rn(vals[2 * p + 1]));
        w4[p] = *(uint32_t*)&hh;
    }
    const int b = rowg >> 11, q = rowg & 2047;
    const int mtile = q >> 7, row = q & 127;
    const int kstage = tid >> 3, colc = (tid * 8) & 63;
    size_t base = (size_t)((b * 16 + mtile) * 32 + kstage) * WCHUNK_B;
    uint32_t off = row * 128 + colc * 2;
    off ^= (off >> 3) & 0x70;
    *(uint4*)(g_Ws + base + off) = make_uint4(w4[0], w4[1], w4[2], w4[3]);
}

// ---------------------------------------------------------------------------
extern "C" void kernel_launch(void* const* d_in, const int* in_sizes, int n_in,
                              void* d_out, int out_size) {
    const float* Q = (const float*)d_in[0];
    const float* K = (const float*)d_in[1];
    const float* V = (const float*)d_in[2];
    const float* T = (const float*)d_in[3];

    float* attended = (float*)d_out;                        // [B,SQ,DH]
    float* weights  = (float*)d_out + (size_t)NB * SQ * DH; // [B,SQ,SK]

    void *qs, *ks, *vs, *ws;
    cudaGetSymbolAddress(&qs, g_Qs);
    cudaGetSymbolAddress(&ks, g_Ks);
    cudaGetSymbolAddress(&vs, g_Vs);
    cudaGetSymbolAddress(&ws, g_Ws);

    cudaFuncSetAttribute((const void*)gemm5_kernel<16, 8, 8, 8, 3, true>,
                         cudaFuncAttributeMaxDynamicSharedMemorySize, SMEM_TOTAL);
    cudaFuncSetAttribute((const void*)gemm5_kernel<16, 2, 32, 2, 4, false>,
                         cudaFuncAttributeMaxDynamicSharedMemorySize, SMEM_TOTAL);

    // 1) fused prep (splits + vsplit + ksq)
    prep_kernel<<<18432, 256>>>(Q, K, V);

    // 2) logits = (2 q.k - ksq)/T   (64 clusters = 128 CTAs, TPT=8)
    gemm5_kernel<16, 8, 8, 8, 3, true><<<128, 256, SMEM_TOTAL>>>(
        (const char*)qs, (const char*)ks, weights, T);

    // 3) softmax in-place + fp16 chunked W
    softmax_kernel<<<NB * SQ, 256>>>(weights);

    // 4) attended = W @ V   (64 clusters = 128 CTAs, TPT=2)
    gemm5_kernel<16, 2, 32, 2, 4, false><<<128, 256, SMEM_TOTAL>>>(
        (const char*)ws, (const char*)vs, attended, nullptr);
}

// round 11
// speedup vs baseline: 2.2442x; 1.1270x over previous
#include <cuda_runtime.h>
#include <cuda_bf16.h>
#include <cuda_fp16.h>
#include <cstdint>

#define NB 8
#define SQ 2048
#define SK 2048
#define DH 512

#define CHUNK_B 32768          // 128x64 bf16 hi+lo tile pair: [hi 16KB][lo 16KB]
#define HCHUNK_B 16384         // 128x64 fp16 single tile
#define SMEM_TILES 1024
#define SMEM_TOTAL 197632      // 1024 + 3*65536 (QK) == 1024 + 6*32768 (PV)

// tcgen05 is arch-accelerated ('a'): only emit in sm_10xa passes.
#if defined(__CUDA_ARCH_FEAT_SM103_ALL) || defined(__CUDA_ARCH_FEAT_SM100_ALL) || \
    defined(__CUDA_ARCH_FEAT_SM101_ALL) ||                                        \
    (defined(__CUDA_ARCH_SPECIFIC__) && (__CUDA_ARCH_SPECIFIC__ >= 1000)) ||      \
    (defined(__CUDA_ARCH_FAMILY_SPECIFIC__) && (__CUDA_ARCH_FAMILY_SPECIFIC__ >= 1000))
#define HAS_TCGEN05 1
#else
#define HAS_TCGEN05 0
#endif

// ------------------------- device scratch (chunked tile layouts) -----------
__device__ float g_ksq[NB * SK];
__device__ __align__(128) char g_Qs[(size_t)NB * 16 * 8 * CHUNK_B];     // 33.5MB bf16 hi/lo
__device__ __align__(128) char g_Ks[(size_t)NB * 16 * 8 * CHUNK_B];     // 33.5MB bf16 hi/lo
__device__ __align__(128) char g_Vs[(size_t)NB * 4 * 32 * HCHUNK_B];    // 16.8MB fp16
__device__ __align__(128) char g_Ws[(size_t)NB * 16 * 32 * HCHUNK_B];   // 67MB fp16

// ------------------------- ptx helpers -------------------------
__device__ __forceinline__ uint32_t smem_u32(const void* p) {
    uint32_t a;
    asm("{ .reg .u64 t; cvta.to.shared.u64 t, %1; cvt.u32.u64 %0, t; }" : "=r"(a) : "l"(p));
    return a;
}
__device__ __forceinline__ uint32_t elect1() {
    uint32_t p;
    asm volatile("{\n\t.reg .pred p;\n\telect.sync _|p, 0xFFFFFFFF;\n\tselp.b32 %0,1,0,p;\n\t}" : "=r"(p));
    return p;
}
__device__ __forceinline__ uint32_t ctarank() {
    uint32_t r;
    asm("mov.u32 %0, %%cluster_ctarank;" : "=r"(r));
    return r;
}
__device__ __forceinline__ void cluster_sync_all() {
    asm volatile("barrier.cluster.arrive.aligned;" ::: "memory");
    asm volatile("barrier.cluster.wait.aligned;" ::: "memory");
}
__device__ __forceinline__ void mbar_init(uint32_t addr, uint32_t cnt) {
    asm volatile("mbarrier.init.shared.b64 [%0], %1;" :: "r"(addr), "r"(cnt) : "memory");
}
__device__ __forceinline__ void mbar_wait(uint32_t mbar, uint32_t parity) {
    asm volatile(
        "{\n\t.reg .pred P;\n\t"
        "W_%=:\n\t"
        "mbarrier.try_wait.parity.acquire.cta.shared::cta.b64 P, [%0], %1, 0x989680;\n\t"
        "@P bra.uni D_%=;\n\t"
        "bra.uni W_%=;\n\t"
        "D_%=:\n\t}"
        :: "r"(mbar), "r"(parity) : "memory");
}
__device__ __forceinline__ void mbar_arrive(uint32_t mbar) {
    asm volatile("mbarrier.arrive.shared.b64 _, [%0];" :: "r"(mbar) : "memory");
}
__device__ __forceinline__ void mbar_arrive_cluster(uint32_t mbar, uint32_t target_rank) {
    asm volatile(
        "{\n\t.reg .b32 r;\n\t"
        "mapa.shared::cluster.u32 r, %0, %1;\n\t"
        "mbarrier.arrive.shared::cluster.b64 _, [r];\n\t}"
        :: "r"(mbar), "r"(target_rank) : "memory");
}
__device__ __forceinline__ void mbar_expect_tx(uint32_t mbar, uint32_t bytes) {
    asm volatile("mbarrier.arrive.expect_tx.shared.b64 _, [%0], %1;"
                 :: "r"(mbar), "r"(bytes) : "memory");
}
__device__ __forceinline__ void bulk_g2s(uint32_t dst, const void* src, uint32_t bytes,
                                         uint32_t mbar) {
    asm volatile(
        "cp.async.bulk.shared::cluster.global.mbarrier::complete_tx::bytes [%0], [%1], %2, [%3];"
        :: "r"(dst), "l"(src), "r"(bytes), "r"(mbar) : "memory");
}

#if HAS_TCGEN05
__device__ __forceinline__ void tmem_alloc_cg2(uint32_t smem_addr, uint32_t ncols) {
    asm volatile("tcgen05.alloc.cta_group::2.sync.aligned.shared::cta.b32 [%0], %1;"
                 :: "r"(smem_addr), "r"(ncols) : "memory");
}
__device__ __forceinline__ void tmem_dealloc_cg2(uint32_t tmem, uint32_t ncols) {
    asm volatile("tcgen05.dealloc.cta_group::2.sync.aligned.b32 %0, %1;" :: "r"(tmem), "r"(ncols));
}
__device__ __forceinline__ void tmem_relinquish_cg2() {
    asm volatile("tcgen05.relinquish_alloc_permit.cta_group::2.sync.aligned;");
}
__device__ __forceinline__ void mma_commit_mc_cg2(uint32_t mbar, uint16_t mask) {
    asm volatile(
        "tcgen05.commit.cta_group::2.mbarrier::arrive::one.shared::cluster.multicast::cluster.b64 "
        "[%0], %1;"
        :: "r"(mbar), "h"(mask) : "memory");
}
__device__ __forceinline__ void tc_fence_after() {
    asm volatile("tcgen05.fence::after_thread_sync;" ::: "memory");
}
__device__ __forceinline__ void tc_wait_ld() {
    asm volatile("tcgen05.wait::ld.sync.aligned;" ::: "memory");
}
__device__ __forceinline__ uint64_t mk_desc(uint32_t addr) {
    // SW128, version=1, SBO=64, LBO=1 (K-major, 128B rows)
    return (2ULL << 61) | (1ULL << 46) | (64ULL << 32) | (1ULL << 16) |
           ((uint64_t)(addr >> 4) & 0x3FFF);
}
__device__ __forceinline__ void mma_f16_ss_cg2(uint32_t d, uint64_t da, uint64_t db,
                                               uint32_t idesc, uint32_t acc) {
    asm volatile(
        "{\n\t.reg .pred p;\n\t"
        "setp.ne.u32 p, %4, 0;\n\t"
        "tcgen05.mma.cta_group::2.kind::f16 [%0], %1, %2, %3, "
        "{%5, %5, %5, %5, %5, %5, %5, %5}, p;\n\t}"
        :: "r"(d), "l"(da), "l"(db), "r"(idesc), "r"(acc), "r"(0u) : "memory");
}
__device__ __forceinline__ void ldtm32(uint32_t* r, uint32_t a) {
    asm volatile(
        "tcgen05.ld.sync.aligned.32x32b.x32.b32 "
        "{%0,%1,%2,%3,%4,%5,%6,%7,%8,%9,%10,%11,%12,%13,%14,%15,"
        "%16,%17,%18,%19,%20,%21,%22,%23,%24,%25,%26,%27,%28,%29,%30,%31}, [%32];"
        : "=r"(r[0]), "=r"(r[1]), "=r"(r[2]), "=r"(r[3]), "=r"(r[4]), "=r"(r[5]), "=r"(r[6]), "=r"(r[7]),
          "=r"(r[8]), "=r"(r[9]), "=r"(r[10]), "=r"(r[11]), "=r"(r[12]), "=r"(r[13]), "=r"(r[14]), "=r"(r[15]),
          "=r"(r[16]), "=r"(r[17]), "=r"(r[18]), "=r"(r[19]), "=r"(r[20]), "=r"(r[21]), "=r"(r[22]), "=r"(r[23]),
          "=r"(r[24]), "=r"(r[25]), "=r"(r[26]), "=r"(r[27]), "=r"(r[28]), "=r"(r[29]), "=r"(r[30]), "=r"(r[31])
        : "r"(a));
}
#endif // HAS_TCGEN05

// idesc cg2 (M=256, N=128, F32 accum): bf16 a/b (QK) and fp16 a/b (PV)
#define IDESC_QK ((1u << 4) | (1u << 7) | (1u << 10) | (16u << 17) | (16u << 24))
#define IDESC_PV ((1u << 4) | (16u << 17) | (16u << 24))

// ---------------------------------------------------------------------------
__device__ __forceinline__ void split8_bf(const float* v, uint32_t* hi, uint32_t* lo) {
    #pragma unroll
    for (int p = 0; p < 4; p++) {
        __nv_bfloat162 h(__float2bfloat16(v[2 * p]), __float2bfloat16(v[2 * p + 1]));
        __nv_bfloat162 l(__float2bfloat16(v[2 * p] - __bfloat162float(h.x)),
                         __float2bfloat16(v[2 * p + 1] - __bfloat162float(h.y)));
        hi[p] = *(uint32_t*)&h;
        lo[p] = *(uint32_t*)&l;
    }
}

// ---------------------------------------------------------------------------
// Fused prep kernel (task-switched by blockIdx.x):
//   [0,4096)      split Q  -> g_Qs (bf16 hi/lo chunks)
//   [4096,8192)   split K  -> g_Ks
//   [8192,16384)  V transpose -> g_Vs (fp16 single chunks)
//   [16384,18432) ksq
// ---------------------------------------------------------------------------
__global__ __launch_bounds__(256) void prep_kernel(const float* __restrict__ Q,
                                                   const float* __restrict__ K,
                                                   const float* __restrict__ V) {
    __shared__ float t[32][33];
    const int bid = blockIdx.x;
    const int tid = threadIdx.x;

    if (bid < 8192) {
        const float* X = (bid < 4096) ? Q : K;
        char* dst = (bid < 4096) ? g_Qs : g_Ks;
        int idx = (bid & 4095) * 256 + tid;
        int mg = idx >> 6;
        int k0 = (idx & 63) * 8;
        int b = mg >> 11, m = mg & 2047;
        int mtile = m >> 7, row = m & 127;
        int kstage = k0 >> 6, colc = k0 & 63;

        float v[8];
        const float* src = X + (size_t)mg * DH + k0;
        *(float4*)(v) = *(const float4*)(src);
        *(float4*)(v + 4) = *(const float4*)(src + 4);
        uint32_t hi[4], lo[4];
        split8_bf(v, hi, lo);

        size_t base = (size_t)((b * 16 + mtile) * 8 + kstage) * CHUNK_B;
        uint32_t off = row * 128 + colc * 2;
        off ^= (off >> 3) & 0x70;
        *(uint4*)(dst + base + off) = make_uint4(hi[0], hi[1], hi[2], hi[3]);
        *(uint4*)(dst + base + 16384 + off) = make_uint4(lo[0], lo[1], lo[2], lo[3]);
    } else if (bid < 16384) {
        // ------- V transpose + fp16 -------
        int r = bid - 8192;
        int b = r >> 10, rem = r & 1023;
        int k0 = (rem >> 4) * 32, d0 = (rem & 15) * 32;
        const float* Vb = V + (size_t)b * SK * DH;
        #pragma unroll
        for (int i = 0; i < 4; i++) {
            int kk = (tid >> 5) + i * 8, dd = tid & 31;
            t[kk][dd] = Vb[(size_t)(k0 + kk) * DH + d0 + dd];
        }
        __syncthreads();
        int d_local = tid >> 3, k_local = (tid & 7) * 4;
        float v[4];
        #pragma unroll
        for (int i = 0; i < 4; i++) v[i] = t[k_local + i][d_local];
        uint32_t hi[2];
        #pragma unroll
        for (int p = 0; p < 2; p++) {
            __half2 hh = __halves2half2(__float2half_rn(v[2 * p]),
                                        __float2half_rn(v[2 * p + 1]));
            hi[p] = *(uint32_t*)&hh;
        }
        int d = d0 + d_local, k = k0 + k_local;
        int ntile = d >> 7, row = d & 127, kstage = k >> 6, colc = k & 63;
        size_t base = (size_t)((b * 4 + ntile) * 32 + kstage) * HCHUNK_B;
        uint32_t off = row * 128 + colc * 2;
        off ^= (off >> 3) & 0x70;
        *(uint2*)(g_Vs + base + off) = make_uint2(hi[0], hi[1]);
    } else {
        int gw = (bid - 16384) * 8 + (tid >> 5);
        int lane = tid & 31;
        const float* row = K + (size_t)gw * DH;
        float s = 0.f;
        #pragma unroll
        for (int i = lane * 4; i < DH; i += 128) {
            float4 v = *(const float4*)(row + i);
            s = fmaf(v.x, v.x, s); s = fmaf(v.y, v.y, s);
            s = fmaf(v.z, v.z, s); s = fmaf(v.w, v.w, s);
        }
        #pragma unroll
        for (int o = 16; o > 0; o >>= 1) s += __shfl_xor_sync(0xffffffffu, s, o);
        if (lane == 0) g_ksq[gw] = s;
    }
}

// ---------------------------------------------------------------------------
// Persistent cg2 GEMM, 256x256 macro tiles, strided tile loop over 74 clusters.
//  QK: A = Q bf16 hi/lo (32KB), B = K bf16 hi/lo (rank-half 16KB), 3 MMAs/K16/half.
//  PV: A = W fp16 (16KB),       B = V fp16 (rank-half 8KB),        1 MMA /K16/half.
// ---------------------------------------------------------------------------
template <int MT, int NXT2, int KST, int NBUF_, bool IS_QK>
__global__ __launch_bounds__(256, 1) __cluster_dims__(2, 1, 1)
void gemm5_kernel(const char* __restrict__ Achunks, const char* __restrict__ Bchunks,
                  float* __restrict__ Out, const float* __restrict__ temp) {
    extern __shared__ __align__(1024) char smem[];
    constexpr int LDOUT = NXT2 * 256;
    constexpr int TPB = (MT / 2) * NXT2;     // macro tiles per batch
    constexpr int TOTAL = NB * TPB;
    constexpr int ACH = IS_QK ? 32768 : 16384;
    constexpr int BCH = IS_QK ? 32768 : 16384;   // full 128-row chunk size in gmem
    constexpr int BSL = BCH / 4;                 // one hi-or-lo rank-half slice (8K/4K)
    constexpr int STAGE = ACH + BCH;             // per-CTA stage bytes

    const int tid = threadIdx.x;
    const int wid = tid >> 5, lid = tid & 31;

#if HAS_TCGEN05
    const uint32_t rank = ctarank();
    const int cluster = blockIdx.x >> 1;
    const int NCLUST = gridDim.x >> 1;
    const int nt = (cluster < TOTAL) ? (TOTAL - cluster + NCLUST - 1) / NCLUST : 0;

    const uint32_t sbase = smem_u32(smem);
    // mbars: full[i]@+8+8i  empty[i]@+64+8i  peerfull[i]@+120+8i (i<6)
    //        done[2]@+176,184  efree[2]@+192,200
    if (wid == 0) {
        tmem_alloc_cg2(sbase, 512);
        tmem_relinquish_cg2();
    }
    if (tid == 0) {
        #pragma unroll
        for (int i = 0; i < NBUF_; i++) {
            mbar_init(sbase + 8 + i * 8, 1);
            mbar_init(sbase + 64 + i * 8, 1);
            mbar_init(sbase + 120 + i * 8, 1);
        }
        mbar_init(sbase + 176, 1);
        mbar_init(sbase + 184, 1);
        mbar_init(sbase + 192, 8);
        mbar_init(sbase + 200, 8);
    }
    __syncthreads();
    cluster_sync_all();
    uint32_t tmem;
    asm volatile("ld.shared.b32 %0, [%1];" : "=r"(tmem) : "r"(sbase));

    if (wid == 1 && elect1()) {
        // ---------------- producer ----------------
        for (int gs = 0; gs < nt * KST; gs++) {
            const int it = gs / KST, s = gs % KST;
            const int T = cluster + it * NCLUST;
            const int b = T / TPB, rem = T % TPB;
            const int mypair = rem / NXT2, nx2 = rem % NXT2;
            const int my = mypair * 2 + (int)rank;
            const int buf = gs % NBUF_;
            if (gs >= NBUF_) mbar_wait(sbase + 64 + buf * 8, ((gs - NBUF_) / NBUF_) & 1);
            uint32_t fm = sbase + 8 + buf * 8;
            uint32_t dst = sbase + SMEM_TILES + buf * STAGE;
            mbar_expect_tx(fm, STAGE);
            bulk_g2s(dst, Achunks + (size_t)((b * MT + my) * KST + s) * ACH, ACH, fm);
            const char* c0 = Bchunks + (size_t)((b * NXT2 * 2 + nx2 * 2) * KST + s) * BCH;
            const char* c1 = c0 + (size_t)KST * BCH;
            if (IS_QK) {
                bulk_g2s(dst + ACH,           c0 + rank * BSL, BSL, fm);
                bulk_g2s(dst + ACH + BSL,     c0 + 2 * BSL + rank * BSL, BSL, fm);
                bulk_g2s(dst + ACH + 2 * BSL, c1 + rank * BSL, BSL, fm);
                bulk_g2s(dst + ACH + 3 * BSL, c1 + 2 * BSL + rank * BSL, BSL, fm);
            } else {
                // fp16 single: rank half = 8KB of each N-chunk
                bulk_g2s(dst + ACH,            c0 + rank * 8192, 8192, fm);
                bulk_g2s(dst + ACH + 8192,     c1 + rank * 8192, 8192, fm);
            }
        }
    } else if (wid == 0 && elect1()) {
        if (rank == 1) {
            // ---------------- full-barrier forwarder ----------------
            for (int gs = 0; gs < nt * KST; gs++) {
                const int buf = gs % NBUF_;
                mbar_wait(sbase + 8 + buf * 8, (gs / NBUF_) & 1);
                mbar_arrive_cluster(sbase + 120 + buf * 8, 0);
            }
        } else {
            // ---------------- cg2 MMA issuer (rank 0) ----------------
            for (int it = 0; it < nt; it++) {
                const uint32_t dbuf = tmem + (it & 1) * 256;
                if (it >= 2) {
                    mbar_wait(sbase + 192 + (it & 1) * 8, ((it >> 1) - 1) & 1);
                    tc_fence_after();
                }
                for (int s = 0; s < KST; s++) {
                    const int gs = it * KST + s;
                    const int buf = gs % NBUF_;
                    const uint32_t par = (gs / NBUF_) & 1;
                    mbar_wait(sbase + 8 + buf * 8, par);
                    mbar_wait(sbase + 120 + buf * 8, par);
                    uint32_t tb = sbase + SMEM_TILES + buf * STAGE;
                    #pragma unroll
                    for (int h = 0; h < 2; h++) {
                        const uint32_t dh = dbuf + h * 128;
                        if (IS_QK) {
                            uint64_t dAh = mk_desc(tb);
                            uint64_t dAl = mk_desc(tb + 16384);
                            uint64_t dBh = mk_desc(tb + ACH + 2 * h * BSL);
                            uint64_t dBl = mk_desc(tb + ACH + (2 * h + 1) * BSL);
                            #pragma unroll
                            for (int ks = 0; ks < 4; ks++) {
                                uint32_t acc0 = (s == 0 && ks == 0) ? 0u : 1u;
                                mma_f16_ss_cg2(dh, dAh + ks * 2, dBh + ks * 2, IDESC_QK, acc0);
                                mma_f16_ss_cg2(dh, dAh + ks * 2, dBl + ks * 2, IDESC_QK, 1u);
                                mma_f16_ss_cg2(dh, dAl + ks * 2, dBh + ks * 2, IDESC_QK, 1u);
                            }
                        } else {
                            uint64_t dA = mk_desc(tb);
                            uint64_t dB = mk_desc(tb + ACH + h * 8192);
                            #pragma unroll
                            for (int ks = 0; ks < 4; ks++) {
                                uint32_t acc0 = (s == 0 && ks == 0) ? 0u : 1u;
                                mma_f16_ss_cg2(dh, dA + ks * 2, dB + ks * 2, IDESC_PV, acc0);
                            }
                        }
                    }
                    mma_commit_mc_cg2(sbase + 64 + buf * 8, 0x3);
                }
                mma_commit_mc_cg2(sbase + 176 + (it & 1) * 8, 0x3);
            }
        }
    } else if (wid >= 4) {
        // ---------------- epilogue warps (4..7, both CTAs) ----------------
        const int wsub = wid - 4;
        const float invT = IS_QK ? 1.0f / temp[0] : 1.0f;
        for (int it = 0; it < nt; it++) {
            const int T = cluster + it * NCLUST;
            const int b = T / TPB, rem = T % TPB;
            const int mypair = rem / NXT2, nx2 = rem % NXT2;
            const int n0 = nx2 * 256;
            const int m = mypair * 256 + (int)rank * 128 + wsub * 32 + lid;
            mbar_wait(sbase + 176 + (it & 1) * 8, (it >> 1) & 1);
            tc_fence_after();
            const uint32_t dbuf = tmem + (it & 1) * 256;
            #pragma unroll
            for (int cb = 0; cb < 256; cb += 32) {
                uint32_t r[32];
                ldtm32(r, dbuf + cb);
                tc_wait_ld();
                float* op = Out + (size_t)b * SQ * LDOUT + (size_t)m * LDOUT + n0 + cb;
                if (IS_QK) {
                    const float* kq = g_ksq + b * SK + n0 + cb;
                    #pragma unroll
                    for (int cc = 0; cc < 32; cc += 4) {
                        float4 o;
                        o.x = (2.f * __uint_as_float(r[cc + 0]) - kq[cc + 0]) * invT;
                        o.y = (2.f * __uint_as_float(r[cc + 1]) - kq[cc + 1]) * invT;
                        o.z = (2.f * __uint_as_float(r[cc + 2]) - kq[cc + 2]) * invT;
                        o.w = (2.f * __uint_as_float(r[cc + 3]) - kq[cc + 3]) * invT;
                        *(float4*)(op + cc) = o;
                    }
                } else {
                    #pragma unroll
                    for (int cc = 0; cc < 32; cc += 4) {
                        float4 o;
                        o.x = __uint_as_float(r[cc + 0]);
                        o.y = __uint_as_float(r[cc + 1]);
                        o.z = __uint_as_float(r[cc + 2]);
                        o.w = __uint_as_float(r[cc + 3]);
                        *(float4*)(op + cc) = o;
                    }
                }
            }
            if (elect1()) {
                if (rank == 0) mbar_arrive(sbase + 192 + (it & 1) * 8);
                else           mbar_arrive_cluster(sbase + 192 + (it & 1) * 8, 0);
            }
        }
    }

    __syncthreads();
    if (wid == 0) tmem_dealloc_cg2(tmem, 512);
    cluster_sync_all();

#else  // ---------------- naive correct fallback (plain sm_103 pass; unused) ----
    const int cluster = blockIdx.x >> 1;
    const int rank = blockIdx.x & 1;
    const int NCLUST = gridDim.x >> 1;
    const int nt = (cluster < TOTAL) ? (TOTAL - cluster + NCLUST - 1) / NCLUST : 0;
    const float invT = IS_QK ? 1.f / temp[0] : 1.f;
    for (int it = 0; it < nt; it++) {
        const int T = cluster + it * NCLUST;
        const int b = T / TPB, rem = T % TPB;
        const int mypair = rem / NXT2, nx2 = rem % NXT2;
        const int my = mypair * 2 + rank;
        const int m0 = my * 128, n0 = nx2 * 256;
        const char* ca0 = Achunks + (size_t)(b * MT + my) * KST * ACH;
        for (int e = tid; e < 128 * 256; e += 256) {
            int i = e >> 8, j = e & 255;
            const char* cb0 =
                Bchunks + (size_t)(b * NXT2 * 2 + nx2 * 2 + (j >> 7)) * KST * BCH;
            int jj = j & 127;
            float acc = 0.f;
            for (int s = 0; s < KST; s++) {
                const char* ca = ca0 + (size_t)s * ACH;
                const char* cb = cb0 + (size_t)s * BCH;
                for (int k = 0; k < 64; k++) {
                    uint32_t oa = i * 128 + k * 2; oa ^= (oa >> 3) & 0x70;
                    uint32_t ob = jj * 128 + k * 2; ob ^= (ob >> 3) & 0x70;
                    float a, bb;
                    if (IS_QK) {
                        a = __bfloat162float(*(const __nv_bfloat16*)(ca + oa)) +
                            __bfloat162float(*(const __nv_bfloat16*)(ca + 16384 + oa));
                        bb = __bfloat162float(*(const __nv_bfloat16*)(cb + ob)) +
                             __bfloat162float(*(const __nv_bfloat16*)(cb + 16384 + ob));
                    } else {
                        a = __half2float(*(const __half*)(ca + oa));
                        bb = __half2float(*(const __half*)(cb + ob));
                    }
                    acc = fmaf(a, bb, acc);
                }
            }
            float* op = Out + (size_t)b * SQ * LDOUT + (size_t)(m0 + i) * LDOUT + n0 + j;
            *op = IS_QK ? (2.f * acc - g_ksq[b * SK + n0 + j]) * invT : acc;
        }
        __syncthreads();
    }
#endif
}

// ---------------------------------------------------------------------------
// softmax (in-place fp32) + write fp16 chunked W tiles for PV
// ---------------------------------------------------------------------------
__global__ __launch_bounds__(256) void softmax_kernel(float* __restrict__ W) {
    const int rowg = blockIdx.x;
    float* r = W + (size_t)rowg * SK;
    const int tid = threadIdx.x;

    float vals[8];
    *(float4*)(vals) = *(const float4*)(r + tid * 8);
    *(float4*)(vals + 4) = *(const float4*)(r + tid * 8 + 4);
    float m = vals[0];
    #pragma unroll
    for (int i = 1; i < 8; i++) m = fmaxf(m, vals[i]);

    __shared__ float red[8];
    #pragma unroll
    for (int o = 16; o > 0; o >>= 1) m = fmaxf(m, __shfl_xor_sync(0xffffffffu, m, o));
    if ((tid & 31) == 0) red[tid >> 5] = m;
    __syncthreads();
    m = red[0];
    #pragma unroll
    for (int w = 1; w < 8; w++) m = fmaxf(m, red[w]);
    __syncthreads();

    float s = 0.f;
    #pragma unroll
    for (int i = 0; i < 8; i++) {
        vals[i] = __expf(vals[i] - m);
        s += vals[i];
    }
    #pragma unroll
    for (int o = 16; o > 0; o >>= 1) s += __shfl_xor_sync(0xffffffffu, s, o);
    if ((tid & 31) == 0) red[tid >> 5] = s;
    __syncthreads();
    s = red[0];
    #pragma unroll
    for (int w = 1; w < 8; w++) s += red[w];

    const float inv = 1.0f / s;
    #pragma unroll
    for (int i = 0; i < 8; i++) vals[i] *= inv;
    *(float4*)(r + tid * 8) = *(float4*)(vals);
    *(float4*)(r + tid * 8 + 4) = *(float4*)(vals + 4);

    uint32_t w4[4];
    #pragma unroll
    for (int p = 0; p < 4; p++) {
        __half2 hh = __halves2half2(__float2half_rn(vals[2 * p]),
                                    __float2half_rn(vals[2 * p + 1]));
        w4[p] = *(uint32_t*)&hh;
    }
    const int b = rowg >> 11, q = rowg & 2047;
    const int mtile = q >> 7, row = q & 127;
    const int kstage = tid >> 3, colc = (tid * 8) & 63;
    size_t base = (size_t)((b * 16 + mtile) * 32 + kstage) * HCHUNK_B;
    uint32_t off = row * 128 + colc * 2;
    off ^= (off >> 3) & 0x70;
    *(uint4*)(g_Ws + base + off) = make_uint4(w4[0], w4[1], w4[2], w4[3]);
}

// ---------------------------------------------------------------------------
extern "C" void kernel_launch(void* const* d_in, const int* in_sizes, int n_in,
                              void* d_out, int out_size) {
    const float* Q = (const float*)d_in[0];
    const float* K = (const float*)d_in[1];
    const float* V = (const float*)d_in[2];
    const float* T = (const float*)d_in[3];

    float* attended = (float*)d_out;                        // [B,SQ,DH]
    float* weights  = (float*)d_out + (size_t)NB * SQ * DH; // [B,SQ,SK]

    void *qs, *ks, *vs, *ws;
    cudaGetSymbolAddress(&qs, g_Qs);
    cudaGetSymbolAddress(&ks, g_Ks);
    cudaGetSymbolAddress(&vs, g_Vs);
    cudaGetSymbolAddress(&ws, g_Ws);

    cudaFuncSetAttribute((const void*)gemm5_kernel<16, 8, 8, 3, true>,
                         cudaFuncAttributeMaxDynamicSharedMemorySize, SMEM_TOTAL);
    cudaFuncSetAttribute((const void*)gemm5_kernel<16, 2, 32, 6, false>,
                         cudaFuncAttributeMaxDynamicSharedMemorySize, SMEM_TOTAL);

    // 1) fused prep (splits + vsplit + ksq)
    prep_kernel<<<18432, 256>>>(Q, K, V);

    // 2) logits = (2 q.k - ksq)/T  — 512 macro tiles over 74 clusters (148 CTAs)
    gemm5_kernel<16, 8, 8, 3, true><<<148, 256, SMEM_TOTAL>>>(
        (const char*)qs, (const char*)ks, weights, T);

    // 3) softmax in-place + fp16 chunked W
    softmax_kernel<<<NB * SQ, 256>>>(weights);

    // 4) attended = W @ V — 128 macro tiles over 74 clusters
    gemm5_kernel<16, 2, 32, 6, false><<<148, 256, SMEM_TOTAL>>>(
        (const char*)ws, (const char*)vs, attended, nullptr);
}